// round 1
// baseline (speedup 1.0000x reference)
#include <cuda_runtime.h>
#include <cuda_bf16.h>
#include <math.h>

#define N_NODES 100000
#define N_EDGES 20000
#define NNZ     1600000

// ---------------- scratch (static device globals; no allocation) ----------------
__device__ float g_xw[(size_t)N_NODES * 256];   // GEMM output per layer
__device__ float g_e [(size_t)N_EDGES * 256];   // per-edge aggregate
__device__ float g_hA[(size_t)N_NODES * 256];   // layer outputs (ping)
__device__ float g_hB[(size_t)N_NODES * 256];   // layer outputs (pong)

__device__ int   g_deg_e[N_EDGES];
__device__ int   g_deg_n[N_NODES];
__device__ float g_binv[N_EDGES];
__device__ float g_dinv[N_NODES];
__device__ int   g_off_e[N_EDGES + 1];
__device__ int   g_off_n[N_NODES + 1];
__device__ int   g_cur_e[N_EDGES];
__device__ int   g_cur_n[N_NODES];
__device__ int   g_csr_e[NNZ];   // node ids grouped by edge
__device__ int   g_csr_n[NNZ];   // edge ids grouped by node

__device__ float        g_logits[N_NODES];
__device__ unsigned int g_maxbits;
__device__ float        g_sumexp;

// ---------------- helpers ----------------
__device__ __forceinline__ unsigned int enc_f(float f) {
    unsigned int u = __float_as_uint(f);
    return (u & 0x80000000u) ? ~u : (u | 0x80000000u);
}
__device__ __forceinline__ float dec_f(unsigned int u) {
    u = (u & 0x80000000u) ? (u ^ 0x80000000u) : ~u;
    return __uint_as_float(u);
}

// ---------------- setup kernels ----------------
__global__ void k_zero_meta(int* deg_e, int* deg_n, int* cur_e, int* cur_n,
                            unsigned int* maxbits, float* sumexp, float* out) {
    int i = blockIdx.x * blockDim.x + threadIdx.x;
    int stride = gridDim.x * blockDim.x;
    for (int j = i; j < N_NODES; j += stride) {
        deg_n[j] = 0; cur_n[j] = 0;
        if (j < N_EDGES) { deg_e[j] = 0; cur_e[j] = 0; }
        if (j < 128) out[j] = 0.0f;
        if (j == 0) { *maxbits = 0u; *sumexp = 0.0f; }
    }
}

__global__ void k_count(const int* __restrict__ nidx, const int* __restrict__ eidx,
                        int* deg_n, int* deg_e) {
    int i = blockIdx.x * blockDim.x + threadIdx.x;
    if (i < NNZ) {
        atomicAdd(&deg_e[eidx[i]], 1);
        atomicAdd(&deg_n[nidx[i]], 1);
    }
}

// single-block exclusive scan over n ints; also writes inv[i] = 1/deg (0 if deg==0)
__global__ void k_scan(const int* __restrict__ deg, int* __restrict__ off,
                       float* __restrict__ inv, int n) {
    __shared__ int sh[1024];
    __shared__ int carry;
    if (threadIdx.x == 0) carry = 0;
    __syncthreads();
    for (int base = 0; base < n; base += 1024) {
        int c = carry;
        int i = base + (int)threadIdx.x;
        int v = (i < n) ? deg[i] : 0;
        sh[threadIdx.x] = v;
        __syncthreads();
        #pragma unroll
        for (int s = 1; s < 1024; s <<= 1) {
            int t = (threadIdx.x >= (unsigned)s) ? sh[threadIdx.x - s] : 0;
            __syncthreads();
            sh[threadIdx.x] += t;
            __syncthreads();
        }
        if (i < n) {
            off[i] = c + sh[threadIdx.x] - v;
            inv[i] = (v > 0) ? (1.0f / (float)v) : 0.0f;
        }
        __syncthreads();
        if (threadIdx.x == 0) carry = c + sh[1023];
        __syncthreads();
    }
    if (threadIdx.x == 0) off[n] = carry;
}

__global__ void k_fill(const int* __restrict__ nidx, const int* __restrict__ eidx,
                       const int* __restrict__ off_e, const int* __restrict__ off_n,
                       int* cur_e, int* cur_n, int* csr_e, int* csr_n) {
    int i = blockIdx.x * blockDim.x + threadIdx.x;
    if (i < NNZ) {
        int e = eidx[i], n = nidx[i];
        int p = atomicAdd(&cur_e[e], 1);
        csr_e[off_e[e] + p] = n;
        int q = atomicAdd(&cur_n[n], 1);
        csr_n[off_n[n] + q] = e;
    }
}

// ---------------- SGEMM: C[M,N] = A[M,K] @ B[K,N], row-major, fp32 ----------------
#define BM 128
#define BN 128
#define BK 8
#define TM 8
#define TN 8

__global__ __launch_bounds__(256) void k_sgemm(
    const float* __restrict__ A, const float* __restrict__ B, float* __restrict__ C,
    int M, int N, int K) {
    __shared__ float As[BK][BM];
    __shared__ float Bs[BK][BN];
    int tid = threadIdx.x;
    int tx = tid % (BN / TN);   // 0..15
    int ty = tid / (BN / TN);   // 0..15
    int mBase = blockIdx.y * BM;
    int nBase = blockIdx.x * BN;

    int arow = tid >> 1;          // 0..127
    int acol = (tid & 1) * 4;     // 0 or 4
    int brow = tid >> 5;          // 0..7
    int bcol = (tid & 31) * 4;    // 0..124

    float acc[TM][TN];
    #pragma unroll
    for (int i = 0; i < TM; i++)
        #pragma unroll
        for (int j = 0; j < TN; j++) acc[i][j] = 0.0f;

    for (int k0 = 0; k0 < K; k0 += BK) {
        // load A tile (BM x BK), store transposed
        float4 av = make_float4(0.f, 0.f, 0.f, 0.f);
        int gr = mBase + arow;
        int gc = k0 + acol;
        if (gr < M) {
            if (gc + 4 <= K) {
                av = *(const float4*)(A + (size_t)gr * K + gc);
            } else {
                float t[4] = {0.f, 0.f, 0.f, 0.f};
                #pragma unroll
                for (int i = 0; i < 4; i++)
                    if (gc + i < K) t[i] = A[(size_t)gr * K + gc + i];
                av = make_float4(t[0], t[1], t[2], t[3]);
            }
        }
        As[acol + 0][arow] = av.x;
        As[acol + 1][arow] = av.y;
        As[acol + 2][arow] = av.z;
        As[acol + 3][arow] = av.w;
        // load B tile (BK x BN); N is a multiple of BN here
        float4 bv = make_float4(0.f, 0.f, 0.f, 0.f);
        int gk = k0 + brow;
        if (gk < K) bv = *(const float4*)(B + (size_t)gk * N + nBase + bcol);
        *(float4*)&Bs[brow][bcol] = bv;
        __syncthreads();

        #pragma unroll
        for (int k = 0; k < BK; k++) {
            float a[TM], b[TN];
            #pragma unroll
            for (int i = 0; i < TM; i++) a[i] = As[k][ty * TM + i];
            #pragma unroll
            for (int j = 0; j < TN; j++) b[j] = Bs[k][tx * TN + j];
            #pragma unroll
            for (int i = 0; i < TM; i++)
                #pragma unroll
                for (int j = 0; j < TN; j++) acc[i][j] += a[i] * b[j];
        }
        __syncthreads();
    }

    #pragma unroll
    for (int i = 0; i < TM; i++) {
        int r = mBase + ty * TM + i;
        if (r >= M) continue;
        #pragma unroll
        for (int j = 0; j < TN; j += 4) {
            *(float4*)(C + (size_t)r * N + nBase + tx * TN + j) =
                make_float4(acc[i][j], acc[i][j + 1], acc[i][j + 2], acc[i][j + 3]);
        }
    }
}

// ---------------- aggregation (atomic-free, warp-per-segment) ----------------
template <int F>
__global__ void k_edge_agg(const float* __restrict__ src,
                           const int* __restrict__ off_e, const int* __restrict__ csr_e,
                           const float* __restrict__ binv, float* __restrict__ eagg) {
    int w = (blockIdx.x * blockDim.x + threadIdx.x) >> 5;
    if (w >= N_EDGES) return;
    int lane = threadIdx.x & 31;
    constexpr int V = F / 128;
    float4 acc[V];
    #pragma unroll
    for (int v = 0; v < V; v++) acc[v] = make_float4(0.f, 0.f, 0.f, 0.f);
    int beg = off_e[w], end = off_e[w + 1];
    for (int m = beg; m < end; m++) {
        int n = csr_e[m];
        const float4* row = (const float4*)(src + (size_t)n * F);
        #pragma unroll
        for (int v = 0; v < V; v++) {
            float4 t = row[lane + 32 * v];
            acc[v].x += t.x; acc[v].y += t.y; acc[v].z += t.z; acc[v].w += t.w;
        }
    }
    float bi = binv[w];
    float4* dst = (float4*)(eagg + (size_t)w * F);
    #pragma unroll
    for (int v = 0; v < V; v++) {
        acc[v].x *= bi; acc[v].y *= bi; acc[v].z *= bi; acc[v].w *= bi;
        dst[lane + 32 * v] = acc[v];
    }
}

template <int F, bool ACT>
__global__ void k_node_agg(const float* __restrict__ eagg,
                           const int* __restrict__ off_n, const int* __restrict__ csr_n,
                           const float* __restrict__ dinv, const float* __restrict__ bias,
                           float* __restrict__ dst) {
    int w = (blockIdx.x * blockDim.x + threadIdx.x) >> 5;
    if (w >= N_NODES) return;
    int lane = threadIdx.x & 31;
    constexpr int V = F / 128;
    float4 acc[V];
    #pragma unroll
    for (int v = 0; v < V; v++) acc[v] = make_float4(0.f, 0.f, 0.f, 0.f);
    int beg = off_n[w], end = off_n[w + 1];
    for (int m = beg; m < end; m++) {
        int e = csr_n[m];
        const float4* row = (const float4*)(eagg + (size_t)e * F);
        #pragma unroll
        for (int v = 0; v < V; v++) {
            float4 t = row[lane + 32 * v];
            acc[v].x += t.x; acc[v].y += t.y; acc[v].z += t.z; acc[v].w += t.w;
        }
    }
    float di = dinv[w];
    float4* dst4 = (float4*)(dst + (size_t)w * F);
    #pragma unroll
    for (int v = 0; v < V; v++) {
        float4 bb = ((const float4*)bias)[lane + 32 * v];
        float4 r;
        r.x = acc[v].x * di + bb.x;
        r.y = acc[v].y * di + bb.y;
        r.z = acc[v].z * di + bb.z;
        r.w = acc[v].w * di + bb.w;
        if (ACT) {
            r.x = r.x > 0.f ? r.x : 0.01f * r.x;
            r.y = r.y > 0.f ? r.y : 0.01f * r.y;
            r.z = r.z > 0.f ? r.z : 0.01f * r.z;
            r.w = r.w > 0.f ? r.w : 0.01f * r.w;
        }
        dst4[lane + 32 * v] = r;
    }
}

// ---------------- attention pooling ----------------
__global__ void k_logits(const float* __restrict__ h, const float* __restrict__ aw,
                         const float* __restrict__ ab, float* __restrict__ logits,
                         unsigned int* maxbits) {
    int w = (blockIdx.x * blockDim.x + threadIdx.x) >> 5;
    int lane = threadIdx.x & 31;
    float s = -3.4e38f;
    if (w < N_NODES) {
        float4 hv = ((const float4*)(h + (size_t)w * 128))[lane];
        float4 wv = ((const float4*)aw)[lane];
        float d = hv.x * wv.x + hv.y * wv.y + hv.z * wv.z + hv.w * wv.w;
        #pragma unroll
        for (int o = 16; o; o >>= 1) d += __shfl_xor_sync(0xffffffffu, d, o);
        d += ab[0];
        if (lane == 0) logits[w] = d;
        s = d;
    }
    __shared__ float smax[8];
    if (lane == 0) smax[threadIdx.x >> 5] = s;
    __syncthreads();
    if (threadIdx.x < 8) {
        float m = smax[threadIdx.x];
        #pragma unroll
        for (int o = 4; o; o >>= 1) m = fmaxf(m, __shfl_xor_sync(0xffu, m, o));
        if (threadIdx.x == 0) atomicMax(maxbits, enc_f(m));
    }
}

__global__ void k_sumexp(const float* __restrict__ logits, const unsigned int* __restrict__ maxbits,
                         float* sumexp) {
    float mx = dec_f(*maxbits);
    int i = blockIdx.x * blockDim.x + threadIdx.x;
    int stride = gridDim.x * blockDim.x;
    float s = 0.f;
    for (int j = i; j < N_NODES; j += stride) s += expf(logits[j] - mx);
    #pragma unroll
    for (int o = 16; o; o >>= 1) s += __shfl_xor_sync(0xffffffffu, s, o);
    __shared__ float sm[8];
    if ((threadIdx.x & 31) == 0) sm[threadIdx.x >> 5] = s;
    __syncthreads();
    if (threadIdx.x < 8) {
        float t = sm[threadIdx.x];
        #pragma unroll
        for (int o = 4; o; o >>= 1) t += __shfl_xor_sync(0xffu, t, o);
        if (threadIdx.x == 0) atomicAdd(sumexp, t);
    }
}

#define POOL_CH 256
__global__ void k_pool(const float* __restrict__ h, const float* __restrict__ logits,
                       const unsigned int* __restrict__ maxbits, const float* __restrict__ sumexp,
                       float* __restrict__ out) {
    __shared__ float wts[POOL_CH];
    float mx = dec_f(*maxbits);
    float inv = 1.0f / (*sumexp);
    int base = blockIdx.x * POOL_CH;
    for (int i = threadIdx.x; i < POOL_CH; i += 128) {
        int n = base + i;
        wts[i] = (n < N_NODES) ? expf(logits[n] - mx) : 0.0f;
    }
    __syncthreads();
    int f = threadIdx.x;
    int lim = min(POOL_CH, N_NODES - base);
    float acc = 0.f;
    for (int i = 0; i < lim; i++) acc += wts[i] * h[(size_t)(base + i) * 128 + f];
    atomicAdd(&out[f], acc * inv);
}

// ---------------- launch ----------------
extern "C" void kernel_launch(void* const* d_in, const int* in_sizes, int n_in,
                              void* d_out, int out_size) {
    const float* x   = (const float*)d_in[0];
    const int*   hei = (const int*)d_in[1];
    const int*   nidx = hei;
    const int*   eidx = hei + NNZ;
    const float* W1 = (const float*)d_in[2];
    const float* b1 = (const float*)d_in[3];
    const float* W2 = (const float*)d_in[4];
    const float* b2 = (const float*)d_in[5];
    const float* W3 = (const float*)d_in[6];
    const float* b3 = (const float*)d_in[7];
    const float* aw = (const float*)d_in[8];
    const float* ab = (const float*)d_in[9];
    float* out = (float*)d_out;

    // symbol addresses (host API, not a stream op — safe under capture)
    static float *p_xw = nullptr, *p_e, *p_hA, *p_hB, *p_binv, *p_dinv, *p_logits, *p_sumexp;
    static int *p_deg_e, *p_deg_n, *p_off_e, *p_off_n, *p_cur_e, *p_cur_n, *p_csr_e, *p_csr_n;
    static unsigned int* p_maxbits;
    if (!p_xw) {
        cudaGetSymbolAddress((void**)&p_xw, g_xw);
        cudaGetSymbolAddress((void**)&p_e, g_e);
        cudaGetSymbolAddress((void**)&p_hA, g_hA);
        cudaGetSymbolAddress((void**)&p_hB, g_hB);
        cudaGetSymbolAddress((void**)&p_binv, g_binv);
        cudaGetSymbolAddress((void**)&p_dinv, g_dinv);
        cudaGetSymbolAddress((void**)&p_logits, g_logits);
        cudaGetSymbolAddress((void**)&p_sumexp, g_sumexp);
        cudaGetSymbolAddress((void**)&p_deg_e, g_deg_e);
        cudaGetSymbolAddress((void**)&p_deg_n, g_deg_n);
        cudaGetSymbolAddress((void**)&p_off_e, g_off_e);
        cudaGetSymbolAddress((void**)&p_off_n, g_off_n);
        cudaGetSymbolAddress((void**)&p_cur_e, g_cur_e);
        cudaGetSymbolAddress((void**)&p_cur_n, g_cur_n);
        cudaGetSymbolAddress((void**)&p_csr_e, g_csr_e);
        cudaGetSymbolAddress((void**)&p_csr_n, g_csr_n);
        cudaGetSymbolAddress((void**)&p_maxbits, g_maxbits);
    }

    // ---- graph build (per launch, deterministic) ----
    k_zero_meta<<<400, 256>>>(p_deg_e, p_deg_n, p_cur_e, p_cur_n, p_maxbits, p_sumexp, out);
    k_count<<<(NNZ + 255) / 256, 256>>>(nidx, eidx, p_deg_n, p_deg_e);
    k_scan<<<1, 1024>>>(p_deg_e, p_off_e, p_binv, N_EDGES);
    k_scan<<<1, 1024>>>(p_deg_n, p_off_n, p_dinv, N_NODES);
    k_fill<<<(NNZ + 255) / 256, 256>>>(nidx, eidx, p_off_e, p_off_n, p_cur_e, p_cur_n, p_csr_e, p_csr_n);

    const int AGG_E_BLOCKS = (N_EDGES * 32 + 255) / 256;
    const int AGG_N_BLOCKS = (N_NODES * 32 + 255) / 256;

    // ---- layer 1: x[100000,300] @ W1[300,256] ----
    {
        dim3 grid((256 + BN - 1) / BN, (N_NODES + BM - 1) / BM);
        k_sgemm<<<grid, 256>>>(x, W1, p_xw, N_NODES, 256, 300);
        k_edge_agg<256><<<AGG_E_BLOCKS, 256>>>(p_xw, p_off_e, p_csr_e, p_binv, p_e);
        k_node_agg<256, true><<<AGG_N_BLOCKS, 256>>>(p_e, p_off_n, p_csr_n, p_dinv, b1, p_hA);
    }
    // ---- layer 2: hA @ W2[256,256] ----
    {
        dim3 grid((256 + BN - 1) / BN, (N_NODES + BM - 1) / BM);
        k_sgemm<<<grid, 256>>>(p_hA, W2, p_xw, N_NODES, 256, 256);
        k_edge_agg<256><<<AGG_E_BLOCKS, 256>>>(p_xw, p_off_e, p_csr_e, p_binv, p_e);
        k_node_agg<256, true><<<AGG_N_BLOCKS, 256>>>(p_e, p_off_n, p_csr_n, p_dinv, b2, p_hB);
    }
    // ---- layer 3: hB @ W3[256,128], no activation ----
    {
        dim3 grid((128 + BN - 1) / BN, (N_NODES + BM - 1) / BM);
        k_sgemm<<<grid, 256>>>(p_hB, W3, p_xw, N_NODES, 128, 256);
        k_edge_agg<128><<<AGG_E_BLOCKS, 256>>>(p_xw, p_off_e, p_csr_e, p_binv, p_e);
        k_node_agg<128, false><<<AGG_N_BLOCKS, 256>>>(p_e, p_off_n, p_csr_n, p_dinv, b3, p_hA);
    }

    // ---- attention pooling ----
    k_logits<<<(N_NODES * 32 + 255) / 256, 256>>>(p_hA, aw, ab, p_logits, p_maxbits);
    k_sumexp<<<512, 256>>>(p_logits, p_maxbits, p_sumexp);
    k_pool<<<(N_NODES + POOL_CH - 1) / POOL_CH, 128>>>(p_hA, p_logits, p_maxbits, p_sumexp, out);
}

// round 3
// speedup vs baseline: 1.7331x; 1.7331x over previous
#include <cuda_runtime.h>
#include <cuda.h>
#include <cuda_bf16.h>
#include <math.h>
#include <stdint.h>

#define N_NODES 100000
#define N_EDGES 20000
#define NNZ     1600000
#define NCHUNK  10          // 10 chunks of 32 k => KPAD 320

// ---------------- scratch (static device globals; no allocation) ----------------
__device__ __align__(128) float g_xw[(size_t)N_NODES * 256];   // GEMM output
__device__ __align__(128) float g_e [(size_t)N_EDGES * 128];   // per-edge aggregate (one F-pass)
__device__ __align__(128) float g_hA[(size_t)N_NODES * 128];   // final layer output
// packed bf16 tiles, chunk-major: [chunk][row][hi 32 bf16 | lo 32 bf16] = 128B rows
__device__ __align__(1024) __nv_bfloat16 g_Apk[(size_t)NCHUNK * N_NODES * 64];
__device__ __align__(1024) __nv_bfloat16 g_Wpk[(size_t)NCHUNK * 256 * 64];

__device__ int   g_deg_e[N_EDGES];
__device__ int   g_deg_n[N_NODES];
__device__ float g_binv[N_EDGES];
__device__ float g_dinv[N_NODES];
__device__ int   g_off_e[N_EDGES + 1];
__device__ int   g_off_n[N_NODES + 1];
__device__ int   g_cur_e[N_EDGES];
__device__ int   g_cur_n[N_NODES];
__device__ int   g_csr_e[NNZ];
__device__ int   g_csr_n[NNZ];
__device__ int   g_bsum_e[64];
__device__ int   g_bsum_n[128];

__device__ float        g_logits[N_NODES];
__device__ unsigned int g_maxbits;
__device__ float        g_sumexp;

// ---------------- PTX helpers (plain sm_103-safe: no tcgen05) ----------------
__device__ __forceinline__ uint32_t smem_u32(const void* p) {
    uint32_t a;
    asm("{ .reg .u64 t; cvta.to.shared.u64 t, %1; cvt.u32.u64 %0, t; }" : "=r"(a) : "l"(p));
    return a;
}
#define MBAR_INIT(a, cnt) asm volatile("mbarrier.init.shared.b64 [%0], %1;" :: "r"(a), "r"(cnt) : "memory")
#define MBAR_EXPECT_TX(a, b) asm volatile("mbarrier.arrive.expect_tx.shared.b64 _, [%0], %1;" :: "r"(a), "r"(b) : "memory")
#define MBAR_WAIT(a, par) do {                                             \
    uint32_t _m = (a); uint32_t _p = (par); uint32_t _d;                   \
    asm volatile("{\n .reg .pred p;\n"                                     \
        " mbarrier.try_wait.parity.acquire.cta.shared::cta.b64 p, [%1], %2;\n" \
        " selp.b32 %0,1,0,p;\n}" : "=r"(_d) : "r"(_m), "r"(_p) : "memory");\
    if (!_d) {                                                             \
        asm volatile("{\n .reg .pred P1;\n"                                \
        "W_%=:\n mbarrier.try_wait.parity.acquire.cta.shared::cta.b64 P1, [%0], %1, 0x989680;\n" \
        " @P1 bra.uni D_%=;\n bra.uni W_%=;\nD_%=:\n}"                     \
        :: "r"(_m), "r"(_p) : "memory");                                   \
    } } while (0)

__device__ __forceinline__ void tma3d(uint32_t dst, const void* tmap, int x, int y, int z, uint32_t mbar) {
    asm volatile(
        "cp.async.bulk.tensor.3d.shared::cta.global.tile.mbarrier::complete_tx::bytes "
        "[%0], [%1, {%2, %3, %4}], [%5];"
        :: "r"(dst), "l"(tmap), "r"(x), "r"(y), "r"(z), "r"(mbar) : "memory");
}
__device__ __forceinline__ void ldsm4(uint32_t* r, uint32_t addr) {
    asm volatile("ldmatrix.sync.aligned.m8n8.x4.shared.b16 {%0,%1,%2,%3}, [%4];"
        : "=r"(r[0]), "=r"(r[1]), "=r"(r[2]), "=r"(r[3]) : "r"(addr));
}
__device__ __forceinline__ void mma16816(float* d, const uint32_t* a, const uint32_t* b) {
    asm volatile("mma.sync.aligned.m16n8k16.row.col.f32.bf16.bf16.f32 "
        "{%0,%1,%2,%3}, {%4,%5,%6,%7}, {%8,%9}, {%0,%1,%2,%3};"
        : "+f"(d[0]), "+f"(d[1]), "+f"(d[2]), "+f"(d[3])
        : "r"(a[0]), "r"(a[1]), "r"(a[2]), "r"(a[3]), "r"(b[0]), "r"(b[1]));
}
// SW128 swizzled smem address within a 128B-pitch tile (byteCol multiple of 16)
__device__ __forceinline__ uint32_t swz(uint32_t base, int row, int byteCol) {
    return base + row * 128 + (byteCol ^ ((row & 7) << 4));
}

// ---------------- misc helpers ----------------
__device__ __forceinline__ unsigned int enc_f(float f) {
    unsigned int u = __float_as_uint(f);
    return (u & 0x80000000u) ? ~u : (u | 0x80000000u);
}
__device__ __forceinline__ float dec_f(unsigned int u) {
    u = (u & 0x80000000u) ? (u ^ 0x80000000u) : ~u;
    return __uint_as_float(u);
}

// ---------------- setup kernels ----------------
__global__ void k_zero_meta(int* deg_e, int* deg_n, int* cur_e, int* cur_n,
                            unsigned int* maxbits, float* sumexp, float* out) {
    int i = blockIdx.x * blockDim.x + threadIdx.x;
    int stride = gridDim.x * blockDim.x;
    for (int j = i; j < N_NODES; j += stride) {
        deg_n[j] = 0; cur_n[j] = 0;
        if (j < N_EDGES) { deg_e[j] = 0; cur_e[j] = 0; }
        if (j < 128) out[j] = 0.0f;
        if (j == 0) { *maxbits = 0u; *sumexp = 0.0f; }
    }
}

__global__ void k_count(const int* __restrict__ nidx, const int* __restrict__ eidx,
                        int* deg_n, int* deg_e) {
    int i = blockIdx.x * blockDim.x + threadIdx.x;
    if (i < NNZ) {
        atomicAdd(&deg_e[eidx[i]], 1);
        atomicAdd(&deg_n[nidx[i]], 1);
    }
}

__global__ void k_scan_local(const int* __restrict__ deg, int* __restrict__ off,
                             int* __restrict__ bsum, int n) {
    __shared__ int sh[1024];
    int i = blockIdx.x * 1024 + threadIdx.x;
    int v = (i < n) ? deg[i] : 0;
    sh[threadIdx.x] = v;
    __syncthreads();
    #pragma unroll
    for (int s = 1; s < 1024; s <<= 1) {
        int t = (threadIdx.x >= (unsigned)s) ? sh[threadIdx.x - s] : 0;
        __syncthreads();
        sh[threadIdx.x] += t;
        __syncthreads();
    }
    if (i < n) off[i] = sh[threadIdx.x] - v;
    if (threadIdx.x == 1023) bsum[blockIdx.x] = sh[1023];
}

__global__ void k_scan_carry(int* bsum_e, int nbe, int* tot_e,
                             int* bsum_n, int nbn, int* tot_n) {
    if (threadIdx.x == 0) {
        int s = 0;
        for (int i = 0; i < nbe; i++) { int v = bsum_e[i]; bsum_e[i] = s; s += v; }
        *tot_e = s;
    }
    if (threadIdx.x == 1) {
        int s = 0;
        for (int i = 0; i < nbn; i++) { int v = bsum_n[i]; bsum_n[i] = s; s += v; }
        *tot_n = s;
    }
}

__global__ void k_scan_add(int* __restrict__ off, const int* __restrict__ bsum,
                           const int* __restrict__ deg, float* __restrict__ inv, int n) {
    int i = blockIdx.x * blockDim.x + threadIdx.x;
    if (i < n) {
        off[i] += bsum[i >> 10];
        int d = deg[i];
        inv[i] = (d > 0) ? (1.0f / (float)d) : 0.0f;
    }
}

__global__ void k_fill(const int* __restrict__ nidx, const int* __restrict__ eidx,
                       const int* __restrict__ off_e, const int* __restrict__ off_n,
                       int* cur_e, int* cur_n, int* csr_e, int* csr_n) {
    int i = blockIdx.x * blockDim.x + threadIdx.x;
    if (i < NNZ) {
        int e = eidx[i], n = nidx[i];
        int p = atomicAdd(&cur_e[e], 1);
        csr_e[off_e[e] + p] = n;
        int q = atomicAdd(&cur_n[n], 1);
        csr_n[off_n[n] + q] = e;
    }
}

// ---------------- bf16 split + chunk-major repack ----------------
// x [M][K] fp32 -> Apk [chunk][m][hi32|lo32]
__global__ void k_packA(const float* __restrict__ src, int K, __nv_bfloat16* __restrict__ apk) {
    int m = blockIdx.x;
    int k = threadIdx.x;   // 320 threads
    float a = (k < K) ? src[(size_t)m * K + k] : 0.0f;
    __nv_bfloat16 h = __float2bfloat16(a);
    float r = a - __bfloat162float(h);
    size_t idx = ((size_t)(k >> 5) * N_NODES + m) * 64 + (k & 31);
    apk[idx] = h;
    apk[idx + 32] = __float2bfloat16(r);
}

// W [K][N] fp32 -> Wpk [chunk][n][hi32|lo32] (transposed)
__global__ void k_packW(const float* __restrict__ W, int K, int N, __nv_bfloat16* __restrict__ wpk) {
    int n = blockIdx.x;
    int k = threadIdx.x;   // 320 threads
    float a = (k < K) ? W[(size_t)k * N + n] : 0.0f;
    __nv_bfloat16 h = __float2bfloat16(a);
    float r = a - __bfloat162float(h);
    size_t idx = ((size_t)(k >> 5) * 256 + n) * 64 + (k & 31);
    wpk[idx] = h;
    wpk[idx + 32] = __float2bfloat16(r);
}

// ---------------- TMA + mma.sync bf16x3 GEMM ----------------
// C[M x Ncols] = A @ W, tiles 128x128, k-chunks of 32 bf16 (hi|lo in 128B rows)
#define STAGE_B 32768
#define N_STAGE 4
#define MB_OFF  (N_STAGE * STAGE_B)
#define SMEM_GEMM (MB_OFF + 64)

__global__ __launch_bounds__(256, 1) void k_mma_gemm(
    const __grid_constant__ CUtensorMap tmA,
    const __grid_constant__ CUtensorMap tmB,
    float* __restrict__ C, int M, int Ncols, int chunks) {
    extern __shared__ char smem[];
    uint32_t sb = smem_u32(smem);
    int tid = threadIdx.x;
    int lane = tid & 31;
    int wid = tid >> 5;
    int wm = wid >> 2;       // 0..1
    int wn = wid & 3;        // 0..3
    int mBase = blockIdx.y * 128;
    int nBase = blockIdx.x * 128;

    if (tid == 0) {
        #pragma unroll
        for (int s = 0; s < N_STAGE; s++) MBAR_INIT(sb + MB_OFF + s * 8, 1);
    }
    __syncthreads();
    if (tid == 0) {
        #pragma unroll
        for (int s = 0; s < N_STAGE; s++) {
            MBAR_EXPECT_TX(sb + MB_OFF + s * 8, STAGE_B);
            tma3d(sb + s * STAGE_B, &tmA, 0, mBase, s, sb + MB_OFF + s * 8);
            tma3d(sb + s * STAGE_B + 16384, &tmB, 0, nBase, s, sb + MB_OFF + s * 8);
        }
    }

    // fragment lane addressing
    int a_row = lane & 15;
    int a_byte = (lane >> 4) << 4;
    int b_row = ((lane & 16) >> 1) + (lane & 7);
    int b_byte = (lane & 8) * 2;

    float acc[4][4][4];
    #pragma unroll
    for (int i = 0; i < 4; i++)
        #pragma unroll
        for (int j = 0; j < 4; j++)
            #pragma unroll
            for (int q = 0; q < 4; q++) acc[i][j][q] = 0.0f;

    for (int c = 0; c < chunks; c++) {
        int st = c & (N_STAGE - 1);
        MBAR_WAIT(sb + MB_OFF + st * 8, (c >> 2) & 1);
        uint32_t sA = sb + st * STAGE_B;
        uint32_t sB = sA + 16384;
        #pragma unroll
        for (int ks = 0; ks < 2; ks++) {
            int kbh = ks * 32;
            int kbl = 64 + ks * 32;
            uint32_t ah[4][4], al[4][4], bh[2][4], bl[2][4];
            #pragma unroll
            for (int i = 0; i < 4; i++) {
                int r = wm * 64 + i * 16 + a_row;
                ldsm4(ah[i], swz(sA, r, kbh + a_byte));
                ldsm4(al[i], swz(sA, r, kbl + a_byte));
            }
            #pragma unroll
            for (int jj = 0; jj < 2; jj++) {
                int r = wn * 32 + jj * 16 + b_row;
                ldsm4(bh[jj], swz(sB, r, kbh + b_byte));
                ldsm4(bl[jj], swz(sB, r, kbl + b_byte));
            }
            #pragma unroll
            for (int i = 0; i < 4; i++)
                #pragma unroll
                for (int j = 0; j < 4; j++) {
                    const uint32_t* bH = &bh[j >> 1][(j & 1) * 2];
                    const uint32_t* bL = &bl[j >> 1][(j & 1) * 2];
                    mma16816(acc[i][j], ah[i], bH);
                    mma16816(acc[i][j], al[i], bH);
                    mma16816(acc[i][j], ah[i], bL);
                }
        }
        __syncthreads();
        if (tid == 0 && c + N_STAGE < chunks) {
            MBAR_EXPECT_TX(sb + MB_OFF + st * 8, STAGE_B);
            tma3d(sb + st * STAGE_B, &tmA, 0, mBase, c + N_STAGE, sb + MB_OFF + st * 8);
            tma3d(sb + st * STAGE_B + 16384, &tmB, 0, nBase, c + N_STAGE, sb + MB_OFF + st * 8);
        }
    }

    // epilogue
    #pragma unroll
    for (int i = 0; i < 4; i++) {
        int r0 = mBase + wm * 64 + i * 16 + (lane >> 2);
        #pragma unroll
        for (int j = 0; j < 4; j++) {
            int cc = nBase + wn * 32 + j * 8 + (lane & 3) * 2;
            if (r0 < M) *(float2*)&C[(size_t)r0 * Ncols + cc] = make_float2(acc[i][j][0], acc[i][j][1]);
            if (r0 + 8 < M) *(float2*)&C[(size_t)(r0 + 8) * Ncols + cc] = make_float2(acc[i][j][2], acc[i][j][3]);
        }
    }
}

// ---------------- aggregation: warp-per-segment, 128-feature pass ----------------
__global__ void k_edge_agg2(const float* __restrict__ src, int Ncols, int foff,
                            const int* __restrict__ off_e, const int* __restrict__ csr_e,
                            const float* __restrict__ binv, float* __restrict__ eagg) {
    int w = (blockIdx.x * blockDim.x + threadIdx.x) >> 5;
    if (w >= N_EDGES) return;
    int lane = threadIdx.x & 31;
    float4 acc = make_float4(0.f, 0.f, 0.f, 0.f);
    int beg = off_e[w], end = off_e[w + 1];
    for (int m = beg; m < end; m++) {
        int n = csr_e[m];
        float4 t = ((const float4*)(src + (size_t)n * Ncols + foff))[lane];
        acc.x += t.x; acc.y += t.y; acc.z += t.z; acc.w += t.w;
    }
    float bi = binv[w];
    acc.x *= bi; acc.y *= bi; acc.z *= bi; acc.w *= bi;
    ((float4*)(eagg + (size_t)w * 128))[lane] = acc;
}

template <bool ACT, bool PACK>
__global__ void k_node_agg2(const float* __restrict__ eagg,
                            const int* __restrict__ off_n, const int* __restrict__ csr_n,
                            const float* __restrict__ dinv, const float* __restrict__ bias, int foff,
                            float* __restrict__ dstF, __nv_bfloat16* __restrict__ apk) {
    int w = (blockIdx.x * blockDim.x + threadIdx.x) >> 5;
    if (w >= N_NODES) return;
    int lane = threadIdx.x & 31;
    float4 acc = make_float4(0.f, 0.f, 0.f, 0.f);
    int beg = off_n[w], end = off_n[w + 1];
    for (int m = beg; m < end; m++) {
        int e = csr_n[m];
        float4 t = ((const float4*)(eagg + (size_t)e * 128))[lane];
        acc.x += t.x; acc.y += t.y; acc.z += t.z; acc.w += t.w;
    }
    float di = dinv[w];
    float4 bb = ((const float4*)(bias + foff))[lane];
    float4 r;
    r.x = acc.x * di + bb.x;
    r.y = acc.y * di + bb.y;
    r.z = acc.z * di + bb.z;
    r.w = acc.w * di + bb.w;
    if (ACT) {
        r.x = r.x > 0.f ? r.x : 0.01f * r.x;
        r.y = r.y > 0.f ? r.y : 0.01f * r.y;
        r.z = r.z > 0.f ? r.z : 0.01f * r.z;
        r.w = r.w > 0.f ? r.w : 0.01f * r.w;
    }
    if (PACK) {
        __nv_bfloat16 h0 = __float2bfloat16(r.x), h1 = __float2bfloat16(r.y);
        __nv_bfloat16 h2 = __float2bfloat16(r.z), h3 = __float2bfloat16(r.w);
        __nv_bfloat16 l0 = __float2bfloat16(r.x - __bfloat162float(h0));
        __nv_bfloat16 l1 = __float2bfloat16(r.y - __bfloat162float(h1));
        __nv_bfloat16 l2 = __float2bfloat16(r.z - __bfloat162float(h2));
        __nv_bfloat16 l3 = __float2bfloat16(r.w - __bfloat162float(h3));
        int chunk = (foff >> 5) + (lane >> 3);
        int pos = (lane & 7) * 4;
        size_t base = ((size_t)chunk * N_NODES + w) * 64;
        __nv_bfloat162* ph = (__nv_bfloat162*)(apk + base + pos);
        ph[0] = __halves2bfloat162(h0, h1);
        ph[1] = __halves2bfloat162(h2, h3);
        __nv_bfloat162* pl = (__nv_bfloat162*)(apk + base + 32 + pos);
        pl[0] = __halves2bfloat162(l0, l1);
        pl[1] = __halves2bfloat162(l2, l3);
    } else {
        ((float4*)(dstF + (size_t)w * 128))[lane] = r;
    }
}

// ---------------- attention pooling ----------------
__global__ void k_logits(const float* __restrict__ h, const float* __restrict__ aw,
                         const float* __restrict__ ab, float* __restrict__ logits,
                         unsigned int* maxbits) {
    int w = (blockIdx.x * blockDim.x + threadIdx.x) >> 5;
    int lane = threadIdx.x & 31;
    float s = -3.4e38f;
    if (w < N_NODES) {
        float4 hv = ((const float4*)(h + (size_t)w * 128))[lane];
        float4 wv = ((const float4*)aw)[lane];
        float d = hv.x * wv.x + hv.y * wv.y + hv.z * wv.z + hv.w * wv.w;
        #pragma unroll
        for (int o = 16; o; o >>= 1) d += __shfl_xor_sync(0xffffffffu, d, o);
        d += ab[0];
        if (lane == 0) logits[w] = d;
        s = d;
    }
    __shared__ float smax[8];
    if (lane == 0) smax[threadIdx.x >> 5] = s;
    __syncthreads();
    if (threadIdx.x < 8) {
        float m = smax[threadIdx.x];
        #pragma unroll
        for (int o = 4; o; o >>= 1) m = fmaxf(m, __shfl_xor_sync(0xffu, m, o));
        if (threadIdx.x == 0) atomicMax(maxbits, enc_f(m));
    }
}

__global__ void k_sumexp(const float* __restrict__ logits, const unsigned int* __restrict__ maxbits,
                         float* sumexp) {
    float mx = dec_f(*maxbits);
    int i = blockIdx.x * blockDim.x + threadIdx.x;
    int stride = gridDim.x * blockDim.x;
    float s = 0.f;
    for (int j = i; j < N_NODES; j += stride) s += expf(logits[j] - mx);
    #pragma unroll
    for (int o = 16; o; o >>= 1) s += __shfl_xor_sync(0xffffffffu, s, o);
    __shared__ float sm[8];
    if ((threadIdx.x & 31) == 0) sm[threadIdx.x >> 5] = s;
    __syncthreads();
    if (threadIdx.x < 8) {
        float t = sm[threadIdx.x];
        #pragma unroll
        for (int o = 4; o; o >>= 1) t += __shfl_xor_sync(0xffu, t, o);
        if (threadIdx.x == 0) atomicAdd(sumexp, t);
    }
}

#define POOL_CH 256
__global__ void k_pool(const float* __restrict__ h, const float* __restrict__ logits,
                       const unsigned int* __restrict__ maxbits, const float* __restrict__ sumexp,
                       float* __restrict__ out) {
    __shared__ float wts[POOL_CH];
    float mx = dec_f(*maxbits);
    float inv = 1.0f / (*sumexp);
    int base = blockIdx.x * POOL_CH;
    for (int i = threadIdx.x; i < POOL_CH; i += 128) {
        int n = base + i;
        wts[i] = (n < N_NODES) ? expf(logits[n] - mx) : 0.0f;
    }
    __syncthreads();
    int f = threadIdx.x;
    int lim = min(POOL_CH, N_NODES - base);
    float acc = 0.f;
    for (int i = 0; i < lim; i++) acc += wts[i] * h[(size_t)(base + i) * 128 + f];
    atomicAdd(&out[f], acc * inv);
}

// ---------------- host-side tensormap plumbing ----------------
typedef CUresult (*PFN_encodeTmap)(
    CUtensorMap*, CUtensorMapDataType, unsigned int, void*,
    const unsigned long long*, const unsigned long long*,
    const unsigned int*, const unsigned int*,
    CUtensorMapInterleave, CUtensorMapSwizzle, CUtensorMapL2promotion, CUtensorMapFloatOOBfill);

// ---------------- launch ----------------
extern "C" void kernel_launch(void* const* d_in, const int* in_sizes, int n_in,
                              void* d_out, int out_size) {
    const float* x   = (const float*)d_in[0];
    const int*   hei = (const int*)d_in[1];
    const int*   nidx = hei;
    const int*   eidx = hei + NNZ;
    const float* W1 = (const float*)d_in[2];
    const float* b1 = (const float*)d_in[3];
    const float* W2 = (const float*)d_in[4];
    const float* b2 = (const float*)d_in[5];
    const float* W3 = (const float*)d_in[6];
    const float* b3 = (const float*)d_in[7];
    const float* aw = (const float*)d_in[8];
    const float* ab = (const float*)d_in[9];
    float* out = (float*)d_out;

    static float *p_xw = nullptr, *p_e, *p_hA, *p_binv, *p_dinv, *p_logits, *p_sumexp;
    static int *p_deg_e, *p_deg_n, *p_off_e, *p_off_n, *p_cur_e, *p_cur_n, *p_csr_e, *p_csr_n;
    static int *p_bsum_e, *p_bsum_n;
    static unsigned int* p_maxbits;
    static __nv_bfloat16 *p_Apk, *p_Wpk;
    static CUtensorMap tmA, tmB;
    if (!p_xw) {
        cudaGetSymbolAddress((void**)&p_xw, g_xw);
        cudaGetSymbolAddress((void**)&p_e, g_e);
        cudaGetSymbolAddress((void**)&p_hA, g_hA);
        cudaGetSymbolAddress((void**)&p_binv, g_binv);
        cudaGetSymbolAddress((void**)&p_dinv, g_dinv);
        cudaGetSymbolAddress((void**)&p_logits, g_logits);
        cudaGetSymbolAddress((void**)&p_sumexp, g_sumexp);
        cudaGetSymbolAddress((void**)&p_deg_e, g_deg_e);
        cudaGetSymbolAddress((void**)&p_deg_n, g_deg_n);
        cudaGetSymbolAddress((void**)&p_off_e, g_off_e);
        cudaGetSymbolAddress((void**)&p_off_n, g_off_n);
        cudaGetSymbolAddress((void**)&p_cur_e, g_cur_e);
        cudaGetSymbolAddress((void**)&p_cur_n, g_cur_n);
        cudaGetSymbolAddress((void**)&p_csr_e, g_csr_e);
        cudaGetSymbolAddress((void**)&p_csr_n, g_csr_n);
        cudaGetSymbolAddress((void**)&p_bsum_e, g_bsum_e);
        cudaGetSymbolAddress((void**)&p_bsum_n, g_bsum_n);
        cudaGetSymbolAddress((void**)&p_maxbits, g_maxbits);
        cudaGetSymbolAddress((void**)&p_Apk, g_Apk);
        cudaGetSymbolAddress((void**)&p_Wpk, g_Wpk);
        cudaFuncSetAttribute(k_mma_gemm, cudaFuncAttributeMaxDynamicSharedMemorySize, SMEM_GEMM);

        // tensormaps via driver entry point (no -lcuda link dependency)
        void* fp = nullptr;
        cudaDriverEntryPointQueryResult qr;
        cudaGetDriverEntryPoint("cuTensorMapEncodeTiled", &fp, cudaEnableDefault, &qr);
        PFN_encodeTmap enc = (PFN_encodeTmap)fp;
        unsigned long long dimsA[3] = {128ull, (unsigned long long)N_NODES, (unsigned long long)NCHUNK};
        unsigned long long strA[2]  = {128ull, 128ull * N_NODES};
        unsigned long long dimsB[3] = {128ull, 256ull, (unsigned long long)NCHUNK};
        unsigned long long strB[2]  = {128ull, 128ull * 256ull};
        unsigned int box[3] = {128u, 128u, 1u};
        unsigned int est[3] = {1u, 1u, 1u};
        enc(&tmA, CU_TENSOR_MAP_DATA_TYPE_UINT8, 3, (void*)p_Apk, dimsA, strA, box, est,
            CU_TENSOR_MAP_INTERLEAVE_NONE, CU_TENSOR_MAP_SWIZZLE_128B,
            CU_TENSOR_MAP_L2_PROMOTION_L2_128B, CU_TENSOR_MAP_FLOAT_OOB_FILL_NONE);
        enc(&tmB, CU_TENSOR_MAP_DATA_TYPE_UINT8, 3, (void*)p_Wpk, dimsB, strB, box, est,
            CU_TENSOR_MAP_INTERLEAVE_NONE, CU_TENSOR_MAP_SWIZZLE_128B,
            CU_TENSOR_MAP_L2_PROMOTION_L2_128B, CU_TENSOR_MAP_FLOAT_OOB_FILL_NONE);
    }

    // ---- CSR build ----
    k_zero_meta<<<400, 256>>>(p_deg_e, p_deg_n, p_cur_e, p_cur_n, p_maxbits, p_sumexp, out);
    k_count<<<(NNZ + 255) / 256, 256>>>(nidx, eidx, p_deg_n, p_deg_e);
    const int NBE = (N_EDGES + 1023) / 1024;
    const int NBN = (N_NODES + 1023) / 1024;
    k_scan_local<<<NBE, 1024>>>(p_deg_e, p_off_e, p_bsum_e, N_EDGES);
    k_scan_local<<<NBN, 1024>>>(p_deg_n, p_off_n, p_bsum_n, N_NODES);
    k_scan_carry<<<1, 32>>>(p_bsum_e, NBE, p_off_e + N_EDGES, p_bsum_n, NBN, p_off_n + N_NODES);
    k_scan_add<<<(N_EDGES + 255) / 256, 256>>>(p_off_e, p_bsum_e, p_deg_e, p_binv, N_EDGES);
    k_scan_add<<<(N_NODES + 255) / 256, 256>>>(p_off_n, p_bsum_n, p_deg_n, p_dinv, N_NODES);
    k_fill<<<(NNZ + 255) / 256, 256>>>(nidx, eidx, p_off_e, p_off_n, p_cur_e, p_cur_n, p_csr_e, p_csr_n);

    const int EB = (N_EDGES * 32) / 256;    // 2500
    const int NB = (N_NODES * 32) / 256;    // 12500
    const int GM = (N_NODES + 127) / 128;   // 782

    // ---- layer 1: x @ W1 [300->256] ----
    k_packA<<<N_NODES, 320>>>(x, 300, p_Apk);
    k_packW<<<256, 320>>>(W1, 300, 256, p_Wpk);
    k_mma_gemm<<<dim3(2, GM), 256, SMEM_GEMM>>>(tmA, tmB, p_xw, N_NODES, 256, 10);
    k_edge_agg2<<<EB, 256>>>(p_xw, 256, 0, p_off_e, p_csr_e, p_binv, p_e);
    k_node_agg2<true, true><<<NB, 256>>>(p_e, p_off_n, p_csr_n, p_dinv, b1, 0, nullptr, p_Apk);
    k_edge_agg2<<<EB, 256>>>(p_xw, 256, 128, p_off_e, p_csr_e, p_binv, p_e);
    k_node_agg2<true, true><<<NB, 256>>>(p_e, p_off_n, p_csr_n, p_dinv, b1, 128, nullptr, p_Apk);

    // ---- layer 2: h1 @ W2 [256->256] ----
    k_packW<<<256, 320>>>(W2, 256, 256, p_Wpk);
    k_mma_gemm<<<dim3(2, GM), 256, SMEM_GEMM>>>(tmA, tmB, p_xw, N_NODES, 256, 8);
    k_edge_agg2<<<EB, 256>>>(p_xw, 256, 0, p_off_e, p_csr_e, p_binv, p_e);
    k_node_agg2<true, true><<<NB, 256>>>(p_e, p_off_n, p_csr_n, p_dinv, b2, 0, nullptr, p_Apk);
    k_edge_agg2<<<EB, 256>>>(p_xw, 256, 128, p_off_e, p_csr_e, p_binv, p_e);
    k_node_agg2<true, true><<<NB, 256>>>(p_e, p_off_n, p_csr_n, p_dinv, b2, 128, nullptr, p_Apk);

    // ---- layer 3: h2 @ W3 [256->128] ----
    k_packW<<<128, 320>>>(W3, 256, 128, p_Wpk);
    k_mma_gemm<<<dim3(1, GM), 256, SMEM_GEMM>>>(tmA, tmB, p_xw, N_NODES, 128, 8);
    k_edge_agg2<<<EB, 256>>>(p_xw, 128, 0, p_off_e, p_csr_e, p_binv, p_e);
    k_node_agg2<false, false><<<NB, 256>>>(p_e, p_off_n, p_csr_n, p_dinv, b3, 0, p_hA, nullptr);

    // ---- attention pooling ----
    k_logits<<<NB, 256>>>(p_hA, aw, ab, p_logits, p_maxbits);
    k_sumexp<<<512, 256>>>(p_logits, p_maxbits, p_sumexp);
    k_pool<<<(N_NODES + POOL_CH - 1) / POOL_CH, 128>>>(p_hA, p_logits, p_maxbits, p_sumexp, out);
}

// round 4
// speedup vs baseline: 2.0725x; 1.1958x over previous
#include <cuda_runtime.h>
#include <cuda.h>
#include <cuda_bf16.h>
#include <math.h>
#include <stdint.h>

#define N_NODES 100000
#define N_EDGES 20000
#define NNZ     1600000
#define NCHUNK  10          // 10 chunks of 32 k => KPAD 320

// ---------------- scratch (static device globals; no allocation) ----------------
__device__ __align__(128) float g_xwE[(size_t)N_EDGES * 256];  // edge GEMM output
__device__ __align__(128) float g_hA[(size_t)N_NODES * 256];   // layer outputs (ping)
__device__ __align__(128) float g_hB[(size_t)N_NODES * 256];   // layer outputs (pong)
// packed bf16 tiles, chunk-major: [chunk][row][hi 32 bf16 | lo 32 bf16] = 128B rows
__device__ __align__(1024) __nv_bfloat16 g_Apk[(size_t)NCHUNK * N_EDGES * 64];
__device__ __align__(1024) __nv_bfloat16 g_Wpk[(size_t)NCHUNK * 256 * 64];

__device__ int   g_deg_e[N_EDGES];
__device__ int   g_deg_n[N_NODES];
__device__ float g_binv[N_EDGES];
__device__ float g_dinv[N_NODES];
__device__ int   g_off_e[N_EDGES + 1];
__device__ int   g_off_n[N_NODES + 1];
__device__ int   g_cur_e[N_EDGES];
__device__ int   g_cur_n[N_NODES];
__device__ int   g_csr_e[NNZ];
__device__ int   g_csr_n[NNZ];
__device__ int   g_bsum_e[64];
__device__ int   g_bsum_n[128];

__device__ float        g_logits[N_NODES];
__device__ unsigned int g_maxbits;
__device__ float        g_sumexp;

// ---------------- PTX helpers (plain sm_103-safe: no tcgen05) ----------------
__device__ __forceinline__ uint32_t smem_u32(const void* p) {
    uint32_t a;
    asm("{ .reg .u64 t; cvta.to.shared.u64 t, %1; cvt.u32.u64 %0, t; }" : "=r"(a) : "l"(p));
    return a;
}
#define MBAR_INIT(a, cnt) asm volatile("mbarrier.init.shared.b64 [%0], %1;" :: "r"(a), "r"(cnt) : "memory")
#define MBAR_EXPECT_TX(a, b) asm volatile("mbarrier.arrive.expect_tx.shared.b64 _, [%0], %1;" :: "r"(a), "r"(b) : "memory")
#define MBAR_WAIT(a, par) do {                                             \
    uint32_t _m = (a); uint32_t _p = (par); uint32_t _d;                   \
    asm volatile("{\n .reg .pred p;\n"                                     \
        " mbarrier.try_wait.parity.acquire.cta.shared::cta.b64 p, [%1], %2;\n" \
        " selp.b32 %0,1,0,p;\n}" : "=r"(_d) : "r"(_m), "r"(_p) : "memory");\
    if (!_d) {                                                             \
        asm volatile("{\n .reg .pred P1;\n"                                \
        "W_%=:\n mbarrier.try_wait.parity.acquire.cta.shared::cta.b64 P1, [%0], %1, 0x989680;\n" \
        " @P1 bra.uni D_%=;\n bra.uni W_%=;\nD_%=:\n}"                     \
        :: "r"(_m), "r"(_p) : "memory");                                   \
    } } while (0)

__device__ __forceinline__ void tma3d(uint32_t dst, const void* tmap, int x, int y, int z, uint32_t mbar) {
    asm volatile(
        "cp.async.bulk.tensor.3d.shared::cta.global.tile.mbarrier::complete_tx::bytes "
        "[%0], [%1, {%2, %3, %4}], [%5];"
        :: "r"(dst), "l"(tmap), "r"(x), "r"(y), "r"(z), "r"(mbar) : "memory");
}
__device__ __forceinline__ void ldsm4(uint32_t* r, uint32_t addr) {
    asm volatile("ldmatrix.sync.aligned.m8n8.x4.shared.b16 {%0,%1,%2,%3}, [%4];"
        : "=r"(r[0]), "=r"(r[1]), "=r"(r[2]), "=r"(r[3]) : "r"(addr));
}
__device__ __forceinline__ void mma16816(float* d, const uint32_t* a, const uint32_t* b) {
    asm volatile("mma.sync.aligned.m16n8k16.row.col.f32.bf16.bf16.f32 "
        "{%0,%1,%2,%3}, {%4,%5,%6,%7}, {%8,%9}, {%0,%1,%2,%3};"
        : "+f"(d[0]), "+f"(d[1]), "+f"(d[2]), "+f"(d[3])
        : "r"(a[0]), "r"(a[1]), "r"(a[2]), "r"(a[3]), "r"(b[0]), "r"(b[1]));
}
__device__ __forceinline__ uint32_t swz(uint32_t base, int row, int byteCol) {
    return base + row * 128 + (byteCol ^ ((row & 7) << 4));
}

// ---------------- misc helpers ----------------
__device__ __forceinline__ unsigned int enc_f(float f) {
    unsigned int u = __float_as_uint(f);
    return (u & 0x80000000u) ? ~u : (u | 0x80000000u);
}
__device__ __forceinline__ float dec_f(unsigned int u) {
    u = (u & 0x80000000u) ? (u ^ 0x80000000u) : ~u;
    return __uint_as_float(u);
}
__device__ __forceinline__ void add4(float4& a, float4 t) {
    a.x += t.x; a.y += t.y; a.z += t.z; a.w += t.w;
}
// pack one float4 (features 4v..4v+3) of edge-row e into chunk-major hi/lo layout
__device__ __forceinline__ void pack_write(__nv_bfloat16* __restrict__ apk, int v, int e, float4 r) {
    int chunk = v >> 3;
    int pos = (v & 7) * 4;
    size_t base = ((size_t)chunk * N_EDGES + e) * 64 + pos;
    __nv_bfloat16 h0 = __float2bfloat16(r.x), h1 = __float2bfloat16(r.y);
    __nv_bfloat16 h2 = __float2bfloat16(r.z), h3 = __float2bfloat16(r.w);
    *(__nv_bfloat162*)(apk + base)     = __halves2bfloat162(h0, h1);
    *(__nv_bfloat162*)(apk + base + 2) = __halves2bfloat162(h2, h3);
    __nv_bfloat16 l0 = __float2bfloat16(r.x - __bfloat162float(h0));
    __nv_bfloat16 l1 = __float2bfloat16(r.y - __bfloat162float(h1));
    __nv_bfloat16 l2 = __float2bfloat16(r.z - __bfloat162float(h2));
    __nv_bfloat16 l3 = __float2bfloat16(r.w - __bfloat162float(h3));
    *(__nv_bfloat162*)(apk + base + 32) = __halves2bfloat162(l0, l1);
    *(__nv_bfloat162*)(apk + base + 34) = __halves2bfloat162(l2, l3);
}

// ---------------- setup kernels ----------------
__global__ void k_zero_meta(int* deg_e, int* deg_n, int* cur_e, int* cur_n,
                            unsigned int* maxbits, float* sumexp, float* out) {
    int i = blockIdx.x * blockDim.x + threadIdx.x;
    int stride = gridDim.x * blockDim.x;
    for (int j = i; j < N_NODES; j += stride) {
        deg_n[j] = 0; cur_n[j] = 0;
        if (j < N_EDGES) { deg_e[j] = 0; cur_e[j] = 0; }
        if (j < 128) out[j] = 0.0f;
        if (j == 0) { *maxbits = 0u; *sumexp = 0.0f; }
    }
}

__global__ void k_count(const int* __restrict__ nidx, const int* __restrict__ eidx,
                        int* deg_n, int* deg_e) {
    int i = blockIdx.x * blockDim.x + threadIdx.x;
    if (i < NNZ) {
        atomicAdd(&deg_e[eidx[i]], 1);
        atomicAdd(&deg_n[nidx[i]], 1);
    }
}

__global__ void k_scan_local(const int* __restrict__ deg, int* __restrict__ off,
                             int* __restrict__ bsum, int n) {
    __shared__ int sh[1024];
    int i = blockIdx.x * 1024 + threadIdx.x;
    int v = (i < n) ? deg[i] : 0;
    sh[threadIdx.x] = v;
    __syncthreads();
    #pragma unroll
    for (int s = 1; s < 1024; s <<= 1) {
        int t = (threadIdx.x >= (unsigned)s) ? sh[threadIdx.x - s] : 0;
        __syncthreads();
        sh[threadIdx.x] += t;
        __syncthreads();
    }
    if (i < n) off[i] = sh[threadIdx.x] - v;
    if (threadIdx.x == 1023) bsum[blockIdx.x] = sh[1023];
}

__global__ void k_scan_carry(int* bsum_e, int nbe, int* tot_e,
                             int* bsum_n, int nbn, int* tot_n) {
    if (threadIdx.x == 0) {
        int s = 0;
        for (int i = 0; i < nbe; i++) { int v = bsum_e[i]; bsum_e[i] = s; s += v; }
        *tot_e = s;
    }
    if (threadIdx.x == 1) {
        int s = 0;
        for (int i = 0; i < nbn; i++) { int v = bsum_n[i]; bsum_n[i] = s; s += v; }
        *tot_n = s;
    }
}

__global__ void k_scan_add(int* __restrict__ off, const int* __restrict__ bsum,
                           const int* __restrict__ deg, float* __restrict__ inv, int n) {
    int i = blockIdx.x * blockDim.x + threadIdx.x;
    if (i < n) {
        off[i] += bsum[i >> 10];
        int d = deg[i];
        inv[i] = (d > 0) ? (1.0f / (float)d) : 0.0f;
    }
}

__global__ void k_fill(const int* __restrict__ nidx, const int* __restrict__ eidx,
                       const int* __restrict__ off_e, const int* __restrict__ off_n,
                       int* cur_e, int* cur_n, int* csr_e, int* csr_n) {
    int i = blockIdx.x * blockDim.x + threadIdx.x;
    if (i < NNZ) {
        int e = eidx[i], n = nidx[i];
        int p = atomicAdd(&cur_e[e], 1);
        csr_e[off_e[e] + p] = n;
        int q = atomicAdd(&cur_n[n], 1);
        csr_n[off_n[n] + q] = e;
    }
}

// W [K][N] fp32 -> Wpk [chunk][n][hi32|lo32] (transposed, fixed 256-row stride)
__global__ void k_packW(const float* __restrict__ W, int K, int N, __nv_bfloat16* __restrict__ wpk) {
    int n = blockIdx.x;
    int k = threadIdx.x;   // 320 threads
    float a = (k < K) ? W[(size_t)k * N + n] : 0.0f;
    __nv_bfloat16 h = __float2bfloat16(a);
    float r = a - __bfloat162float(h);
    size_t idx = ((size_t)(k >> 5) * 256 + n) * 64 + (k & 31);
    wpk[idx] = h;
    wpk[idx + 32] = __float2bfloat16(r);
}

// ---------------- edge gather + fused bf16x3 pack ----------------
// L1: gather x [N_NODES,300] over csr_e, scale binv, pack 10 chunks (pad to 320)
__global__ void k_edge_pack300(const float* __restrict__ x,
                               const int* __restrict__ off_e, const int* __restrict__ csr_e,
                               const float* __restrict__ binv, __nv_bfloat16* __restrict__ apk) {
    int w = (blockIdx.x * blockDim.x + threadIdx.x) >> 5;
    if (w >= N_EDGES) return;
    int lane = threadIdx.x & 31;
    float4 a0 = make_float4(0, 0, 0, 0), a1 = a0, a2 = a0;
    bool p2 = lane < 11;   // v=lane+64 real for v<=74 (features < 300)
    int beg = off_e[w], end = off_e[w + 1];
    int m = beg;
    for (; m + 3 < end; m += 4) {
        int n0 = csr_e[m], n1 = csr_e[m + 1], n2 = csr_e[m + 2], n3 = csr_e[m + 3];
        const float4* r0 = (const float4*)(x + (size_t)n0 * 300);
        const float4* r1 = (const float4*)(x + (size_t)n1 * 300);
        const float4* r2 = (const float4*)(x + (size_t)n2 * 300);
        const float4* r3 = (const float4*)(x + (size_t)n3 * 300);
        add4(a0, r0[lane]); add4(a0, r1[lane]); add4(a0, r2[lane]); add4(a0, r3[lane]);
        add4(a1, r0[lane + 32]); add4(a1, r1[lane + 32]); add4(a1, r2[lane + 32]); add4(a1, r3[lane + 32]);
        if (p2) {
            add4(a2, r0[lane + 64]); add4(a2, r1[lane + 64]);
            add4(a2, r2[lane + 64]); add4(a2, r3[lane + 64]);
        }
    }
    for (; m < end; m++) {
        const float4* r0 = (const float4*)(x + (size_t)csr_e[m] * 300);
        add4(a0, r0[lane]); add4(a1, r0[lane + 32]);
        if (p2) add4(a2, r0[lane + 64]);
    }
    float bi = binv[w];
    a0.x *= bi; a0.y *= bi; a0.z *= bi; a0.w *= bi;
    a1.x *= bi; a1.y *= bi; a1.z *= bi; a1.w *= bi;
    a2.x *= bi; a2.y *= bi; a2.z *= bi; a2.w *= bi;
    pack_write(apk, lane, w, a0);
    pack_write(apk, lane + 32, w, a1);
    if (lane < 16) pack_write(apk, lane + 64, w, p2 ? a2 : make_float4(0, 0, 0, 0));
}

// L2/L3: gather h [N_NODES,256] over csr_e, scale binv, pack 8 chunks
__global__ void k_edge_pack256(const float* __restrict__ h,
                               const int* __restrict__ off_e, const int* __restrict__ csr_e,
                               const float* __restrict__ binv, __nv_bfloat16* __restrict__ apk) {
    int w = (blockIdx.x * blockDim.x + threadIdx.x) >> 5;
    if (w >= N_EDGES) return;
    int lane = threadIdx.x & 31;
    float4 a0 = make_float4(0, 0, 0, 0), a1 = a0;
    int beg = off_e[w], end = off_e[w + 1];
    int m = beg;
    for (; m + 3 < end; m += 4) {
        int n0 = csr_e[m], n1 = csr_e[m + 1], n2 = csr_e[m + 2], n3 = csr_e[m + 3];
        const float4* r0 = (const float4*)(h + (size_t)n0 * 256);
        const float4* r1 = (const float4*)(h + (size_t)n1 * 256);
        const float4* r2 = (const float4*)(h + (size_t)n2 * 256);
        const float4* r3 = (const float4*)(h + (size_t)n3 * 256);
        add4(a0, r0[lane]); add4(a0, r1[lane]); add4(a0, r2[lane]); add4(a0, r3[lane]);
        add4(a1, r0[lane + 32]); add4(a1, r1[lane + 32]); add4(a1, r2[lane + 32]); add4(a1, r3[lane + 32]);
    }
    for (; m < end; m++) {
        const float4* r0 = (const float4*)(h + (size_t)csr_e[m] * 256);
        add4(a0, r0[lane]); add4(a1, r0[lane + 32]);
    }
    float bi = binv[w];
    a0.x *= bi; a0.y *= bi; a0.z *= bi; a0.w *= bi;
    a1.x *= bi; a1.y *= bi; a1.z *= bi; a1.w *= bi;
    pack_write(apk, lane, w, a0);
    pack_write(apk, lane + 32, w, a1);
}

// ---------------- TMA + mma.sync bf16x3 GEMM (M = N_EDGES rows) ----------------
#define STAGE_B 32768
#define N_STAGE 4
#define MB_OFF  (N_STAGE * STAGE_B)
#define SMEM_GEMM (MB_OFF + 64)

__global__ __launch_bounds__(256, 1) void k_mma_gemm(
    const __grid_constant__ CUtensorMap tmA,
    const __grid_constant__ CUtensorMap tmB,
    float* __restrict__ C, int M, int Ncols, int chunks) {
    extern __shared__ char smem[];
    uint32_t sb = smem_u32(smem);
    int tid = threadIdx.x;
    int lane = tid & 31;
    int wid = tid >> 5;
    int wm = wid >> 2;
    int wn = wid & 3;
    int mBase = blockIdx.y * 128;
    int nBase = blockIdx.x * 128;

    if (tid == 0) {
        #pragma unroll
        for (int s = 0; s < N_STAGE; s++) MBAR_INIT(sb + MB_OFF + s * 8, 1);
    }
    __syncthreads();
    if (tid == 0) {
        #pragma unroll
        for (int s = 0; s < N_STAGE; s++) {
            MBAR_EXPECT_TX(sb + MB_OFF + s * 8, STAGE_B);
            tma3d(sb + s * STAGE_B, &tmA, 0, mBase, s, sb + MB_OFF + s * 8);
            tma3d(sb + s * STAGE_B + 16384, &tmB, 0, nBase, s, sb + MB_OFF + s * 8);
        }
    }

    int a_row = lane & 15;
    int a_byte = (lane >> 4) << 4;
    int b_row = ((lane & 16) >> 1) + (lane & 7);
    int b_byte = (lane & 8) * 2;

    float acc[4][4][4];
    #pragma unroll
    for (int i = 0; i < 4; i++)
        #pragma unroll
        for (int j = 0; j < 4; j++)
            #pragma unroll
            for (int q = 0; q < 4; q++) acc[i][j][q] = 0.0f;

    for (int c = 0; c < chunks; c++) {
        int st = c & (N_STAGE - 1);
        MBAR_WAIT(sb + MB_OFF + st * 8, (c >> 2) & 1);
        uint32_t sA = sb + st * STAGE_B;
        uint32_t sB = sA + 16384;
        #pragma unroll
        for (int ks = 0; ks < 2; ks++) {
            int kbh = ks * 32;
            int kbl = 64 + ks * 32;
            uint32_t ah[4][4], al[4][4], bh[2][4], bl[2][4];
            #pragma unroll
            for (int i = 0; i < 4; i++) {
                int r = wm * 64 + i * 16 + a_row;
                ldsm4(ah[i], swz(sA, r, kbh + a_byte));
                ldsm4(al[i], swz(sA, r, kbl + a_byte));
            }
            #pragma unroll
            for (int jj = 0; jj < 2; jj++) {
                int r = wn * 32 + jj * 16 + b_row;
                ldsm4(bh[jj], swz(sB, r, kbh + b_byte));
                ldsm4(bl[jj], swz(sB, r, kbl + b_byte));
            }
            #pragma unroll
            for (int i = 0; i < 4; i++)
                #pragma unroll
                for (int j = 0; j < 4; j++) {
                    const uint32_t* bH = &bh[j >> 1][(j & 1) * 2];
                    const uint32_t* bL = &bl[j >> 1][(j & 1) * 2];
                    mma16816(acc[i][j], ah[i], bH);
                    mma16816(acc[i][j], al[i], bH);
                    mma16816(acc[i][j], ah[i], bL);
                }
        }
        __syncthreads();
        if (tid == 0 && c + N_STAGE < chunks) {
            MBAR_EXPECT_TX(sb + MB_OFF + st * 8, STAGE_B);
            tma3d(sb + st * STAGE_B, &tmA, 0, mBase, c + N_STAGE, sb + MB_OFF + st * 8);
            tma3d(sb + st * STAGE_B + 16384, &tmB, 0, nBase, c + N_STAGE, sb + MB_OFF + st * 8);
        }
    }

    #pragma unroll
    for (int i = 0; i < 4; i++) {
        int r0 = mBase + wm * 64 + i * 16 + (lane >> 2);
        #pragma unroll
        for (int j = 0; j < 4; j++) {
            int cc = nBase + wn * 32 + j * 8 + (lane & 3) * 2;
            if (r0 < M) *(float2*)&C[(size_t)r0 * Ncols + cc] = make_float2(acc[i][j][0], acc[i][j][1]);
            if (r0 + 8 < M) *(float2*)&C[(size_t)(r0 + 8) * Ncols + cc] = make_float2(acc[i][j][2], acc[i][j][3]);
        }
    }
}

// ---------------- node gather (from edge GEMM output) ----------------
template <bool ACT>
__global__ void k_node_agg256(const float* __restrict__ xwE,
                              const int* __restrict__ off_n, const int* __restrict__ csr_n,
                              const float* __restrict__ dinv, const float* __restrict__ bias,
                              float* __restrict__ dst) {
    int w = (blockIdx.x * blockDim.x + threadIdx.x) >> 5;
    if (w >= N_NODES) return;
    int lane = threadIdx.x & 31;
    float4 a0 = make_float4(0, 0, 0, 0), a1 = a0;
    int beg = off_n[w], end = off_n[w + 1];
    int m = beg;
    for (; m + 3 < end; m += 4) {
        int e0 = csr_n[m], e1 = csr_n[m + 1], e2 = csr_n[m + 2], e3 = csr_n[m + 3];
        const float4* r0 = (const float4*)(xwE + (size_t)e0 * 256);
        const float4* r1 = (const float4*)(xwE + (size_t)e1 * 256);
        const float4* r2 = (const float4*)(xwE + (size_t)e2 * 256);
        const float4* r3 = (const float4*)(xwE + (size_t)e3 * 256);
        add4(a0, r0[lane]); add4(a0, r1[lane]); add4(a0, r2[lane]); add4(a0, r3[lane]);
        add4(a1, r0[lane + 32]); add4(a1, r1[lane + 32]); add4(a1, r2[lane + 32]); add4(a1, r3[lane + 32]);
    }
    for (; m < end; m++) {
        const float4* r0 = (const float4*)(xwE + (size_t)csr_n[m] * 256);
        add4(a0, r0[lane]); add4(a1, r0[lane + 32]);
    }
    float di = dinv[w];
    float4 b0 = ((const float4*)bias)[lane];
    float4 b1 = ((const float4*)bias)[lane + 32];
    float4 r0v, r1v;
    r0v.x = a0.x * di + b0.x; r0v.y = a0.y * di + b0.y;
    r0v.z = a0.z * di + b0.z; r0v.w = a0.w * di + b0.w;
    r1v.x = a1.x * di + b1.x; r1v.y = a1.y * di + b1.y;
    r1v.z = a1.z * di + b1.z; r1v.w = a1.w * di + b1.w;
    if (ACT) {
        r0v.x = r0v.x > 0.f ? r0v.x : 0.01f * r0v.x;
        r0v.y = r0v.y > 0.f ? r0v.y : 0.01f * r0v.y;
        r0v.z = r0v.z > 0.f ? r0v.z : 0.01f * r0v.z;
        r0v.w = r0v.w > 0.f ? r0v.w : 0.01f * r0v.w;
        r1v.x = r1v.x > 0.f ? r1v.x : 0.01f * r1v.x;
        r1v.y = r1v.y > 0.f ? r1v.y : 0.01f * r1v.y;
        r1v.z = r1v.z > 0.f ? r1v.z : 0.01f * r1v.z;
        r1v.w = r1v.w > 0.f ? r1v.w : 0.01f * r1v.w;
    }
    float4* d4 = (float4*)(dst + (size_t)w * 256);
    d4[lane] = r0v;
    d4[lane + 32] = r1v;
}

// Final layer: F=128 node gather + fused attention logit + global max
__global__ void k_node_agg_final(const float* __restrict__ xwE,
                                 const int* __restrict__ off_n, const int* __restrict__ csr_n,
                                 const float* __restrict__ dinv, const float* __restrict__ bias,
                                 const float* __restrict__ aw, const float* __restrict__ ab,
                                 float* __restrict__ dst, float* __restrict__ logits,
                                 unsigned int* maxbits) {
    int w = (blockIdx.x * blockDim.x + threadIdx.x) >> 5;
    int lane = threadIdx.x & 31;
    float d = -3.4e38f;
    if (w < N_NODES) {
        float4 a0 = make_float4(0, 0, 0, 0);
        int beg = off_n[w], end = off_n[w + 1];
        int m = beg;
        for (; m + 3 < end; m += 4) {
            int e0 = csr_n[m], e1 = csr_n[m + 1], e2 = csr_n[m + 2], e3 = csr_n[m + 3];
            add4(a0, ((const float4*)(xwE + (size_t)e0 * 128))[lane]);
            add4(a0, ((const float4*)(xwE + (size_t)e1 * 128))[lane]);
            add4(a0, ((const float4*)(xwE + (size_t)e2 * 128))[lane]);
            add4(a0, ((const float4*)(xwE + (size_t)e3 * 128))[lane]);
        }
        for (; m < end; m++)
            add4(a0, ((const float4*)(xwE + (size_t)csr_n[m] * 128))[lane]);
        float di = dinv[w];
        float4 bb = ((const float4*)bias)[lane];
        float4 r;
        r.x = a0.x * di + bb.x; r.y = a0.y * di + bb.y;
        r.z = a0.z * di + bb.z; r.w = a0.w * di + bb.w;
        ((float4*)(dst + (size_t)w * 128))[lane] = r;
        float4 wv = ((const float4*)aw)[lane];
        float dd = r.x * wv.x + r.y * wv.y + r.z * wv.z + r.w * wv.w;
        #pragma unroll
        for (int o = 16; o; o >>= 1) dd += __shfl_xor_sync(0xffffffffu, dd, o);
        dd += ab[0];
        if (lane == 0) logits[w] = dd;
        d = dd;
    }
    __shared__ float smax[8];
    if (lane == 0) smax[threadIdx.x >> 5] = d;
    __syncthreads();
    if (threadIdx.x < 8) {
        float mv = smax[threadIdx.x];
        #pragma unroll
        for (int o = 4; o; o >>= 1) mv = fmaxf(mv, __shfl_xor_sync(0xffu, mv, o));
        if (threadIdx.x == 0) atomicMax(maxbits, enc_f(mv));
    }
}

// ---------------- softmax pooling ----------------
__global__ void k_sumexp(const float* __restrict__ logits, const unsigned int* __restrict__ maxbits,
                         float* sumexp) {
    float mx = dec_f(*maxbits);
    int i = blockIdx.x * blockDim.x + threadIdx.x;
    int stride = gridDim.x * blockDim.x;
    float s = 0.f;
    for (int j = i; j < N_NODES; j += stride) s += expf(logits[j] - mx);
    #pragma unroll
    for (int o = 16; o; o >>= 1) s += __shfl_xor_sync(0xffffffffu, s, o);
    __shared__ float sm[8];
    if ((threadIdx.x & 31) == 0) sm[threadIdx.x >> 5] = s;
    __syncthreads();
    if (threadIdx.x < 8) {
        float t = sm[threadIdx.x];
        #pragma unroll
        for (int o = 4; o; o >>= 1) t += __shfl_xor_sync(0xffu, t, o);
        if (threadIdx.x == 0) atomicAdd(sumexp, t);
    }
}

#define POOL_CH 256
__global__ void k_pool(const float* __restrict__ h, const float* __restrict__ logits,
                       const unsigned int* __restrict__ maxbits, const float* __restrict__ sumexp,
                       float* __restrict__ out) {
    __shared__ float wts[POOL_CH];
    float mx = dec_f(*maxbits);
    float inv = 1.0f / (*sumexp);
    int base = blockIdx.x * POOL_CH;
    for (int i = threadIdx.x; i < POOL_CH; i += 128) {
        int n = base + i;
        wts[i] = (n < N_NODES) ? expf(logits[n] - mx) : 0.0f;
    }
    __syncthreads();
    int f = threadIdx.x;
    int lim = min(POOL_CH, N_NODES - base);
    float acc = 0.f;
    for (int i = 0; i < lim; i++) acc += wts[i] * h[(size_t)(base + i) * 128 + f];
    atomicAdd(&out[f], acc * inv);
}

// ---------------- host-side tensormap plumbing ----------------
typedef CUresult (*PFN_encodeTmap)(
    CUtensorMap*, CUtensorMapDataType, unsigned int, void*,
    const unsigned long long*, const unsigned long long*,
    const unsigned int*, const unsigned int*,
    CUtensorMapInterleave, CUtensorMapSwizzle, CUtensorMapL2promotion, CUtensorMapFloatOOBfill);

// ---------------- launch ----------------
extern "C" void kernel_launch(void* const* d_in, const int* in_sizes, int n_in,
                              void* d_out, int out_size) {
    const float* x   = (const float*)d_in[0];
    const int*   hei = (const int*)d_in[1];
    const int*   nidx = hei;
    const int*   eidx = hei + NNZ;
    const float* W1 = (const float*)d_in[2];
    const float* b1 = (const float*)d_in[3];
    const float* W2 = (const float*)d_in[4];
    const float* b2 = (const float*)d_in[5];
    const float* W3 = (const float*)d_in[6];
    const float* b3 = (const float*)d_in[7];
    const float* aw = (const float*)d_in[8];
    const float* ab = (const float*)d_in[9];
    float* out = (float*)d_out;

    static float *p_xwE = nullptr, *p_hA, *p_hB, *p_binv, *p_dinv, *p_logits, *p_sumexp;
    static int *p_deg_e, *p_deg_n, *p_off_e, *p_off_n, *p_cur_e, *p_cur_n, *p_csr_e, *p_csr_n;
    static int *p_bsum_e, *p_bsum_n;
    static unsigned int* p_maxbits;
    static __nv_bfloat16 *p_Apk, *p_Wpk;
    static CUtensorMap tmA, tmB;
    if (!p_xwE) {
        cudaGetSymbolAddress((void**)&p_xwE, g_xwE);
        cudaGetSymbolAddress((void**)&p_hA, g_hA);
        cudaGetSymbolAddress((void**)&p_hB, g_hB);
        cudaGetSymbolAddress((void**)&p_binv, g_binv);
        cudaGetSymbolAddress((void**)&p_dinv, g_dinv);
        cudaGetSymbolAddress((void**)&p_logits, g_logits);
        cudaGetSymbolAddress((void**)&p_sumexp, g_sumexp);
        cudaGetSymbolAddress((void**)&p_deg_e, g_deg_e);
        cudaGetSymbolAddress((void**)&p_deg_n, g_deg_n);
        cudaGetSymbolAddress((void**)&p_off_e, g_off_e);
        cudaGetSymbolAddress((void**)&p_off_n, g_off_n);
        cudaGetSymbolAddress((void**)&p_cur_e, g_cur_e);
        cudaGetSymbolAddress((void**)&p_cur_n, g_cur_n);
        cudaGetSymbolAddress((void**)&p_csr_e, g_csr_e);
        cudaGetSymbolAddress((void**)&p_csr_n, g_csr_n);
        cudaGetSymbolAddress((void**)&p_bsum_e, g_bsum_e);
        cudaGetSymbolAddress((void**)&p_bsum_n, g_bsum_n);
        cudaGetSymbolAddress((void**)&p_maxbits, g_maxbits);
        cudaGetSymbolAddress((void**)&p_Apk, g_Apk);
        cudaGetSymbolAddress((void**)&p_Wpk, g_Wpk);
        cudaFuncSetAttribute(k_mma_gemm, cudaFuncAttributeMaxDynamicSharedMemorySize, SMEM_GEMM);

        void* fp = nullptr;
        cudaDriverEntryPointQueryResult qr;
        cudaGetDriverEntryPoint("cuTensorMapEncodeTiled", &fp, cudaEnableDefault, &qr);
        PFN_encodeTmap enc = (PFN_encodeTmap)fp;
        unsigned long long dimsA[3] = {128ull, (unsigned long long)N_EDGES, (unsigned long long)NCHUNK};
        unsigned long long strA[2]  = {128ull, 128ull * N_EDGES};
        unsigned long long dimsB[3] = {128ull, 256ull, (unsigned long long)NCHUNK};
        unsigned long long strB[2]  = {128ull, 128ull * 256ull};
        unsigned int box[3] = {128u, 128u, 1u};
        unsigned int est[3] = {1u, 1u, 1u};
        enc(&tmA, CU_TENSOR_MAP_DATA_TYPE_UINT8, 3, (void*)p_Apk, dimsA, strA, box, est,
            CU_TENSOR_MAP_INTERLEAVE_NONE, CU_TENSOR_MAP_SWIZZLE_128B,
            CU_TENSOR_MAP_L2_PROMOTION_L2_128B, CU_TENSOR_MAP_FLOAT_OOB_FILL_NONE);
        enc(&tmB, CU_TENSOR_MAP_DATA_TYPE_UINT8, 3, (void*)p_Wpk, dimsB, strB, box, est,
            CU_TENSOR_MAP_INTERLEAVE_NONE, CU_TENSOR_MAP_SWIZZLE_128B,
            CU_TENSOR_MAP_L2_PROMOTION_L2_128B, CU_TENSOR_MAP_FLOAT_OOB_FILL_NONE);
    }

    // ---- CSR build ----
    k_zero_meta<<<400, 256>>>(p_deg_e, p_deg_n, p_cur_e, p_cur_n, p_maxbits, p_sumexp, out);
    k_count<<<(NNZ + 255) / 256, 256>>>(nidx, eidx, p_deg_n, p_deg_e);
    const int NBE = (N_EDGES + 1023) / 1024;
    const int NBN = (N_NODES + 1023) / 1024;
    k_scan_local<<<NBE, 1024>>>(p_deg_e, p_off_e, p_bsum_e, N_EDGES);
    k_scan_local<<<NBN, 1024>>>(p_deg_n, p_off_n, p_bsum_n, N_NODES);
    k_scan_carry<<<1, 32>>>(p_bsum_e, NBE, p_off_e + N_EDGES, p_bsum_n, NBN, p_off_n + N_NODES);
    k_scan_add<<<(N_EDGES + 255) / 256, 256>>>(p_off_e, p_bsum_e, p_deg_e, p_binv, N_EDGES);
    k_scan_add<<<(N_NODES + 255) / 256, 256>>>(p_off_n, p_bsum_n, p_deg_n, p_dinv, N_NODES);
    k_fill<<<(NNZ + 255) / 256, 256>>>(nidx, eidx, p_off_e, p_off_n, p_cur_e, p_cur_n, p_csr_e, p_csr_n);

    const int EB = (N_EDGES * 32) / 256;    // 2500
    const int NB = (N_NODES * 32) / 256;    // 12500
    const int GM = (N_EDGES + 127) / 128;   // 157

    // ---- layer 1: e = B^-1 H^T x ; eW = e @ W1 ; h1 = leaky(D^-1 H eW + b1) ----
    k_packW<<<256, 320>>>(W1, 300, 256, p_Wpk);
    k_edge_pack300<<<EB, 256>>>(x, p_off_e, p_csr_e, p_binv, p_Apk);
    k_mma_gemm<<<dim3(2, GM), 256, SMEM_GEMM>>>(tmA, tmB, p_xwE, N_EDGES, 256, 10);
    k_node_agg256<true><<<NB, 256>>>(p_xwE, p_off_n, p_csr_n, p_dinv, b1, p_hA);

    // ---- layer 2 ----
    k_packW<<<256, 320>>>(W2, 256, 256, p_Wpk);
    k_edge_pack256<<<EB, 256>>>(p_hA, p_off_e, p_csr_e, p_binv, p_Apk);
    k_mma_gemm<<<dim3(2, GM), 256, SMEM_GEMM>>>(tmA, tmB, p_xwE, N_EDGES, 256, 8);
    k_node_agg256<true><<<NB, 256>>>(p_xwE, p_off_n, p_csr_n, p_dinv, b2, p_hB);

    // ---- layer 3 (Fout=128) + fused logits ----
    k_packW<<<128, 320>>>(W3, 256, 128, p_Wpk);
    k_edge_pack256<<<EB, 256>>>(p_hB, p_off_e, p_csr_e, p_binv, p_Apk);
    k_mma_gemm<<<dim3(1, GM), 256, SMEM_GEMM>>>(tmA, tmB, p_xwE, N_EDGES, 128, 8);
    k_node_agg_final<<<NB, 256>>>(p_xwE, p_off_n, p_csr_n, p_dinv, b3, aw, ab,
                                  p_hA, p_logits, p_maxbits);

    // ---- softmax pooling ----
    k_sumexp<<<512, 256>>>(p_logits, p_maxbits, p_sumexp);
    k_pool<<<(N_NODES + POOL_CH - 1) / POOL_CH, 128>>>(p_hA, p_logits, p_maxbits, p_sumexp, out);
}

// round 5
// speedup vs baseline: 2.5685x; 1.2394x over previous
#include <cuda_runtime.h>
#include <cuda.h>
#include <cuda_bf16.h>
#include <cuda_fp16.h>
#include <math.h>
#include <stdint.h>

#define N_NODES 100000
#define N_EDGES 20000
#define NNZ     1600000
#define NCHUNK  10          // 10 chunks of 32 k => KPAD 320

// ---------------- scratch (static device globals; no allocation) ----------------
__device__ __align__(128) __half g_xh[(size_t)N_NODES * 320];    // x in fp16, padded
__device__ __align__(128) __half g_xwE[(size_t)N_EDGES * 256];   // edge GEMM output (fp16)
__device__ __align__(128) __half g_h16[(size_t)N_NODES * 256];   // layer output fp16 (ping)
__device__ __align__(128) __half g_h16b[(size_t)N_NODES * 256];  // layer output fp16 (pong)
__device__ __align__(128) float  g_hA[(size_t)N_NODES * 128];    // final layer output fp32
// packed bf16 tiles, chunk-major: [chunk][row][hi 32 bf16 | lo 32 bf16] = 128B rows
__device__ __align__(1024) __nv_bfloat16 g_Apk[(size_t)NCHUNK * N_EDGES * 64];
__device__ __align__(1024) __nv_bfloat16 g_Wpk[(size_t)NCHUNK * 256 * 64];

__device__ int   g_deg_e[N_EDGES];
__device__ int   g_deg_n[N_NODES];
__device__ float g_binv[N_EDGES];
__device__ float g_dinv[N_NODES];
__device__ int   g_off_e[N_EDGES + 1];
__device__ int   g_off_n[N_NODES + 1];
__device__ int   g_cur_e[N_EDGES];
__device__ int   g_cur_n[N_NODES];
__device__ int   g_csr_e[NNZ];
__device__ int   g_csr_n[NNZ];
__device__ int   g_bsum_e[64];
__device__ int   g_bsum_n[128];

__device__ float        g_logits[N_NODES];
__device__ unsigned int g_maxbits;
__device__ float        g_sumexp;

// ---------------- PTX helpers (plain sm_103-safe: no tcgen05) ----------------
__device__ __forceinline__ uint32_t smem_u32(const void* p) {
    uint32_t a;
    asm("{ .reg .u64 t; cvta.to.shared.u64 t, %1; cvt.u32.u64 %0, t; }" : "=r"(a) : "l"(p));
    return a;
}
#define MBAR_INIT(a, cnt) asm volatile("mbarrier.init.shared.b64 [%0], %1;" :: "r"(a), "r"(cnt) : "memory")
#define MBAR_EXPECT_TX(a, b) asm volatile("mbarrier.arrive.expect_tx.shared.b64 _, [%0], %1;" :: "r"(a), "r"(b) : "memory")
#define MBAR_WAIT(a, par) do {                                             \
    uint32_t _m = (a); uint32_t _p = (par); uint32_t _d;                   \
    asm volatile("{\n .reg .pred p;\n"                                     \
        " mbarrier.try_wait.parity.acquire.cta.shared::cta.b64 p, [%1], %2;\n" \
        " selp.b32 %0,1,0,p;\n}" : "=r"(_d) : "r"(_m), "r"(_p) : "memory");\
    if (!_d) {                                                             \
        asm volatile("{\n .reg .pred P1;\n"                                \
        "W_%=:\n mbarrier.try_wait.parity.acquire.cta.shared::cta.b64 P1, [%0], %1, 0x989680;\n" \
        " @P1 bra.uni D_%=;\n bra.uni W_%=;\nD_%=:\n}"                     \
        :: "r"(_m), "r"(_p) : "memory");                                   \
    } } while (0)

__device__ __forceinline__ void tma3d(uint32_t dst, const void* tmap, int x, int y, int z, uint32_t mbar) {
    asm volatile(
        "cp.async.bulk.tensor.3d.shared::cta.global.tile.mbarrier::complete_tx::bytes "
        "[%0], [%1, {%2, %3, %4}], [%5];"
        :: "r"(dst), "l"(tmap), "r"(x), "r"(y), "r"(z), "r"(mbar) : "memory");
}
__device__ __forceinline__ void ldsm4(uint32_t* r, uint32_t addr) {
    asm volatile("ldmatrix.sync.aligned.m8n8.x4.shared.b16 {%0,%1,%2,%3}, [%4];"
        : "=r"(r[0]), "=r"(r[1]), "=r"(r[2]), "=r"(r[3]) : "r"(addr));
}
__device__ __forceinline__ void mma16816(float* d, const uint32_t* a, const uint32_t* b) {
    asm volatile("mma.sync.aligned.m16n8k16.row.col.f32.bf16.bf16.f32 "
        "{%0,%1,%2,%3}, {%4,%5,%6,%7}, {%8,%9}, {%0,%1,%2,%3};"
        : "+f"(d[0]), "+f"(d[1]), "+f"(d[2]), "+f"(d[3])
        : "r"(a[0]), "r"(a[1]), "r"(a[2]), "r"(a[3]), "r"(b[0]), "r"(b[1]));
}
__device__ __forceinline__ uint32_t swz(uint32_t base, int row, int byteCol) {
    return base + row * 128 + (byteCol ^ ((row & 7) << 4));
}

// ---------------- misc helpers ----------------
__device__ __forceinline__ unsigned int enc_f(float f) {
    unsigned int u = __float_as_uint(f);
    return (u & 0x80000000u) ? ~u : (u | 0x80000000u);
}
__device__ __forceinline__ float dec_f(unsigned int u) {
    u = (u & 0x80000000u) ? (u ^ 0x80000000u) : ~u;
    return __uint_as_float(u);
}
// accumulate 8 fp16 values (one uint4) into 8 fp32 accumulators
__device__ __forceinline__ void addh8(float* a, uint4 v) {
    const __half2* h = (const __half2*)&v;
    #pragma unroll
    for (int i = 0; i < 4; i++) {
        float2 f = __half22float2(h[i]);
        a[2 * i] += f.x;
        a[2 * i + 1] += f.y;
    }
}
// pack 4 floats (features 4v..4v+3) of edge-row e into chunk-major bf16 hi/lo layout
__device__ __forceinline__ void pack_write(__nv_bfloat16* __restrict__ apk, int v, int e,
                                           float r0, float r1, float r2, float r3) {
    int chunk = v >> 3;
    int pos = (v & 7) * 4;
    size_t base = ((size_t)chunk * N_EDGES + e) * 64 + pos;
    __nv_bfloat16 h0 = __float2bfloat16(r0), h1 = __float2bfloat16(r1);
    __nv_bfloat16 h2 = __float2bfloat16(r2), h3 = __float2bfloat16(r3);
    *(__nv_bfloat162*)(apk + base)     = __halves2bfloat162(h0, h1);
    *(__nv_bfloat162*)(apk + base + 2) = __halves2bfloat162(h2, h3);
    __nv_bfloat16 l0 = __float2bfloat16(r0 - __bfloat162float(h0));
    __nv_bfloat16 l1 = __float2bfloat16(r1 - __bfloat162float(h1));
    __nv_bfloat16 l2 = __float2bfloat16(r2 - __bfloat162float(h2));
    __nv_bfloat16 l3 = __float2bfloat16(r3 - __bfloat162float(h3));
    *(__nv_bfloat162*)(apk + base + 32) = __halves2bfloat162(l0, l1);
    *(__nv_bfloat162*)(apk + base + 34) = __halves2bfloat162(l2, l3);
}

// ---------------- setup kernels ----------------
__global__ void k_zero_meta(int* deg_e, int* deg_n, int* cur_e, int* cur_n,
                            unsigned int* maxbits, float* sumexp, float* out) {
    int i = blockIdx.x * blockDim.x + threadIdx.x;
    int stride = gridDim.x * blockDim.x;
    for (int j = i; j < N_NODES; j += stride) {
        deg_n[j] = 0; cur_n[j] = 0;
        if (j < N_EDGES) { deg_e[j] = 0; cur_e[j] = 0; }
        if (j < 128) out[j] = 0.0f;
        if (j == 0) { *maxbits = 0u; *sumexp = 0.0f; }
    }
}

__global__ void k_count(const int* __restrict__ nidx, const int* __restrict__ eidx,
                        int* deg_n, int* deg_e) {
    int i = blockIdx.x * blockDim.x + threadIdx.x;
    if (i < NNZ) {
        atomicAdd(&deg_e[eidx[i]], 1);
        atomicAdd(&deg_n[nidx[i]], 1);
    }
}

__global__ void k_scan_local(const int* __restrict__ deg, int* __restrict__ off,
                             int* __restrict__ bsum, int n) {
    __shared__ int sh[1024];
    int i = blockIdx.x * 1024 + threadIdx.x;
    int v = (i < n) ? deg[i] : 0;
    sh[threadIdx.x] = v;
    __syncthreads();
    #pragma unroll
    for (int s = 1; s < 1024; s <<= 1) {
        int t = (threadIdx.x >= (unsigned)s) ? sh[threadIdx.x - s] : 0;
        __syncthreads();
        sh[threadIdx.x] += t;
        __syncthreads();
    }
    if (i < n) off[i] = sh[threadIdx.x] - v;
    if (threadIdx.x == 1023) bsum[blockIdx.x] = sh[1023];
}

__global__ void k_scan_carry(int* bsum_e, int nbe, int* tot_e,
                             int* bsum_n, int nbn, int* tot_n) {
    if (threadIdx.x == 0) {
        int s = 0;
        for (int i = 0; i < nbe; i++) { int v = bsum_e[i]; bsum_e[i] = s; s += v; }
        *tot_e = s;
    }
    if (threadIdx.x == 1) {
        int s = 0;
        for (int i = 0; i < nbn; i++) { int v = bsum_n[i]; bsum_n[i] = s; s += v; }
        *tot_n = s;
    }
}

__global__ void k_scan_add(int* __restrict__ off, const int* __restrict__ bsum,
                           const int* __restrict__ deg, float* __restrict__ inv, int n) {
    int i = blockIdx.x * blockDim.x + threadIdx.x;
    if (i < n) {
        off[i] += bsum[i >> 10];
        int d = deg[i];
        inv[i] = (d > 0) ? (1.0f / (float)d) : 0.0f;
    }
}

__global__ void k_fill(const int* __restrict__ nidx, const int* __restrict__ eidx,
                       const int* __restrict__ off_e, const int* __restrict__ off_n,
                       int* cur_e, int* cur_n, int* csr_e, int* csr_n) {
    int i = blockIdx.x * blockDim.x + threadIdx.x;
    if (i < NNZ) {
        int e = eidx[i], n = nidx[i];
        int p = atomicAdd(&cur_e[e], 1);
        csr_e[off_e[e] + p] = n;
        int q = atomicAdd(&cur_n[n], 1);
        csr_n[off_n[n] + q] = e;
    }
}

// x [N_NODES,300] fp32 -> g_xh [N_NODES,320] fp16 (zero padded)
__global__ void k_cvtX(const float* __restrict__ x, __half* __restrict__ xh) {
    int m = blockIdx.x;
    int k = threadIdx.x;   // 320
    float v = (k < 300) ? x[(size_t)m * 300 + k] : 0.0f;
    xh[(size_t)m * 320 + k] = __float2half_rn(v);
}

// W [K][N] fp32 -> Wpk [chunk][n][hi32|lo32] (transposed, fixed 256-row stride)
__global__ void k_packW(const float* __restrict__ W, int K, int N, __nv_bfloat16* __restrict__ wpk) {
    int n = blockIdx.x;
    int k = threadIdx.x;   // 320 threads
    float a = (k < K) ? W[(size_t)k * N + n] : 0.0f;
    __nv_bfloat16 h = __float2bfloat16(a);
    float r = a - __bfloat162float(h);
    size_t idx = ((size_t)(k >> 5) * 256 + n) * 64 + (k & 31);
    wpk[idx] = h;
    wpk[idx + 32] = __float2bfloat16(r);
}

// ---------------- edge gather (fp16 source) + fused bf16x3 pack ----------------
// L1: gather g_xh [N_NODES,320] fp16; pack 10 chunks
__global__ void k_edge_pack320(const __half* __restrict__ xh,
                               const int* __restrict__ off_e, const int* __restrict__ csr_e,
                               const float* __restrict__ binv, __nv_bfloat16* __restrict__ apk) {
    int w = (blockIdx.x * blockDim.x + threadIdx.x) >> 5;
    if (w >= N_EDGES) return;
    int lane = threadIdx.x & 31;
    float a[8] = {0, 0, 0, 0, 0, 0, 0, 0};
    float b[8] = {0, 0, 0, 0, 0, 0, 0, 0};
    bool hasB = lane < 8;
    int beg = off_e[w], end = off_e[w + 1];
    int m = beg;
    for (; m + 3 < end; m += 4) {
        int n0 = csr_e[m], n1 = csr_e[m + 1], n2 = csr_e[m + 2], n3 = csr_e[m + 3];
        const uint4* r0 = (const uint4*)(xh + (size_t)n0 * 320);
        const uint4* r1 = (const uint4*)(xh + (size_t)n1 * 320);
        const uint4* r2 = (const uint4*)(xh + (size_t)n2 * 320);
        const uint4* r3 = (const uint4*)(xh + (size_t)n3 * 320);
        addh8(a, r0[lane]); addh8(a, r1[lane]); addh8(a, r2[lane]); addh8(a, r3[lane]);
        if (hasB) {
            addh8(b, r0[lane + 32]); addh8(b, r1[lane + 32]);
            addh8(b, r2[lane + 32]); addh8(b, r3[lane + 32]);
        }
    }
    for (; m < end; m++) {
        const uint4* r0 = (const uint4*)(xh + (size_t)csr_e[m] * 320);
        addh8(a, r0[lane]);
        if (hasB) addh8(b, r0[lane + 32]);
    }
    float bi = binv[w];
    #pragma unroll
    for (int i = 0; i < 8; i++) { a[i] *= bi; b[i] *= bi; }
    pack_write(apk, 2 * lane, w, a[0], a[1], a[2], a[3]);
    pack_write(apk, 2 * lane + 1, w, a[4], a[5], a[6], a[7]);
    if (hasB) {
        pack_write(apk, 64 + 2 * lane, w, b[0], b[1], b[2], b[3]);
        pack_write(apk, 64 + 2 * lane + 1, w, b[4], b[5], b[6], b[7]);
    }
}

// L2/L3: gather h16 [N_NODES,256] fp16; pack 8 chunks
__global__ void k_edge_pack256(const __half* __restrict__ h,
                               const int* __restrict__ off_e, const int* __restrict__ csr_e,
                               const float* __restrict__ binv, __nv_bfloat16* __restrict__ apk) {
    int w = (blockIdx.x * blockDim.x + threadIdx.x) >> 5;
    if (w >= N_EDGES) return;
    int lane = threadIdx.x & 31;
    float a[8] = {0, 0, 0, 0, 0, 0, 0, 0};
    int beg = off_e[w], end = off_e[w + 1];
    int m = beg;
    for (; m + 3 < end; m += 4) {
        int n0 = csr_e[m], n1 = csr_e[m + 1], n2 = csr_e[m + 2], n3 = csr_e[m + 3];
        addh8(a, ((const uint4*)(h + (size_t)n0 * 256))[lane]);
        addh8(a, ((const uint4*)(h + (size_t)n1 * 256))[lane]);
        addh8(a, ((const uint4*)(h + (size_t)n2 * 256))[lane]);
        addh8(a, ((const uint4*)(h + (size_t)n3 * 256))[lane]);
    }
    for (; m < end; m++)
        addh8(a, ((const uint4*)(h + (size_t)csr_e[m] * 256))[lane]);
    float bi = binv[w];
    #pragma unroll
    for (int i = 0; i < 8; i++) a[i] *= bi;
    pack_write(apk, 2 * lane, w, a[0], a[1], a[2], a[3]);
    pack_write(apk, 2 * lane + 1, w, a[4], a[5], a[6], a[7]);
}

// ---------------- TMA + mma.sync bf16x3 GEMM, fp16 output ----------------
#define STAGE_B 32768
#define N_STAGE 4
#define MB_OFF  (N_STAGE * STAGE_B)
#define SMEM_GEMM (MB_OFF + 64)

__global__ __launch_bounds__(256, 1) void k_mma_gemm(
    const __grid_constant__ CUtensorMap tmA,
    const __grid_constant__ CUtensorMap tmB,
    __half* __restrict__ C, int M, int Ncols, int chunks) {
    extern __shared__ char smem[];
    uint32_t sb = smem_u32(smem);
    int tid = threadIdx.x;
    int lane = tid & 31;
    int wid = tid >> 5;
    int wm = wid >> 2;
    int wn = wid & 3;
    int mBase = blockIdx.y * 128;
    int nBase = blockIdx.x * 128;

    if (tid == 0) {
        #pragma unroll
        for (int s = 0; s < N_STAGE; s++) MBAR_INIT(sb + MB_OFF + s * 8, 1);
    }
    __syncthreads();
    if (tid == 0) {
        #pragma unroll
        for (int s = 0; s < N_STAGE; s++) {
            MBAR_EXPECT_TX(sb + MB_OFF + s * 8, STAGE_B);
            tma3d(sb + s * STAGE_B, &tmA, 0, mBase, s, sb + MB_OFF + s * 8);
            tma3d(sb + s * STAGE_B + 16384, &tmB, 0, nBase, s, sb + MB_OFF + s * 8);
        }
    }

    int a_row = lane & 15;
    int a_byte = (lane >> 4) << 4;
    int b_row = ((lane & 16) >> 1) + (lane & 7);
    int b_byte = (lane & 8) * 2;

    float acc[4][4][4];
    #pragma unroll
    for (int i = 0; i < 4; i++)
        #pragma unroll
        for (int j = 0; j < 4; j++)
            #pragma unroll
            for (int q = 0; q < 4; q++) acc[i][j][q] = 0.0f;

    for (int c = 0; c < chunks; c++) {
        int st = c & (N_STAGE - 1);
        MBAR_WAIT(sb + MB_OFF + st * 8, (c >> 2) & 1);
        uint32_t sA = sb + st * STAGE_B;
        uint32_t sB = sA + 16384;
        #pragma unroll
        for (int ks = 0; ks < 2; ks++) {
            int kbh = ks * 32;
            int kbl = 64 + ks * 32;
            uint32_t ah[4][4], al[4][4], bh[2][4], bl[2][4];
            #pragma unroll
            for (int i = 0; i < 4; i++) {
                int r = wm * 64 + i * 16 + a_row;
                ldsm4(ah[i], swz(sA, r, kbh + a_byte));
                ldsm4(al[i], swz(sA, r, kbl + a_byte));
            }
            #pragma unroll
            for (int jj = 0; jj < 2; jj++) {
                int r = wn * 32 + jj * 16 + b_row;
                ldsm4(bh[jj], swz(sB, r, kbh + b_byte));
                ldsm4(bl[jj], swz(sB, r, kbl + b_byte));
            }
            #pragma unroll
            for (int i = 0; i < 4; i++)
                #pragma unroll
                for (int j = 0; j < 4; j++) {
                    const uint32_t* bH = &bh[j >> 1][(j & 1) * 2];
                    const uint32_t* bL = &bl[j >> 1][(j & 1) * 2];
                    mma16816(acc[i][j], ah[i], bH);
                    mma16816(acc[i][j], al[i], bH);
                    mma16816(acc[i][j], ah[i], bL);
                }
        }
        __syncthreads();
        if (tid == 0 && c + N_STAGE < chunks) {
            MBAR_EXPECT_TX(sb + MB_OFF + st * 8, STAGE_B);
            tma3d(sb + st * STAGE_B, &tmA, 0, mBase, c + N_STAGE, sb + MB_OFF + st * 8);
            tma3d(sb + st * STAGE_B + 16384, &tmB, 0, nBase, c + N_STAGE, sb + MB_OFF + st * 8);
        }
    }

    #pragma unroll
    for (int i = 0; i < 4; i++) {
        int r0 = mBase + wm * 64 + i * 16 + (lane >> 2);
        #pragma unroll
        for (int j = 0; j < 4; j++) {
            int cc = nBase + wn * 32 + j * 8 + (lane & 3) * 2;
            if (r0 < M)
                *(__half2*)&C[(size_t)r0 * Ncols + cc] =
                    __floats2half2_rn(acc[i][j][0], acc[i][j][1]);
            if (r0 + 8 < M)
                *(__half2*)&C[(size_t)(r0 + 8) * Ncols + cc] =
                    __floats2half2_rn(acc[i][j][2], acc[i][j][3]);
        }
    }
}

// ---------------- node gather (fp16 edge GEMM output) ----------------
__global__ void k_node_agg256(const __half* __restrict__ xwE,
                              const int* __restrict__ off_n, const int* __restrict__ csr_n,
                              const float* __restrict__ dinv, const float* __restrict__ bias,
                              __half* __restrict__ dst) {
    int w = (blockIdx.x * blockDim.x + threadIdx.x) >> 5;
    if (w >= N_NODES) return;
    int lane = threadIdx.x & 31;
    float a[8] = {0, 0, 0, 0, 0, 0, 0, 0};
    int beg = off_n[w], end = off_n[w + 1];
    int m = beg;
    for (; m + 3 < end; m += 4) {
        int e0 = csr_n[m], e1 = csr_n[m + 1], e2 = csr_n[m + 2], e3 = csr_n[m + 3];
        addh8(a, ((const uint4*)(xwE + (size_t)e0 * 256))[lane]);
        addh8(a, ((const uint4*)(xwE + (size_t)e1 * 256))[lane]);
        addh8(a, ((const uint4*)(xwE + (size_t)e2 * 256))[lane]);
        addh8(a, ((const uint4*)(xwE + (size_t)e3 * 256))[lane]);
    }
    for (; m < end; m++)
        addh8(a, ((const uint4*)(xwE + (size_t)csr_n[m] * 256))[lane]);
    float di = dinv[w];
    float4 b0 = ((const float4*)bias)[2 * lane];
    float4 b1 = ((const float4*)bias)[2 * lane + 1];
    float r[8];
    r[0] = a[0] * di + b0.x; r[1] = a[1] * di + b0.y;
    r[2] = a[2] * di + b0.z; r[3] = a[3] * di + b0.w;
    r[4] = a[4] * di + b1.x; r[5] = a[5] * di + b1.y;
    r[6] = a[6] * di + b1.z; r[7] = a[7] * di + b1.w;
    #pragma unroll
    for (int i = 0; i < 8; i++) r[i] = r[i] > 0.f ? r[i] : 0.01f * r[i];
    __half2 o[4];
    #pragma unroll
    for (int i = 0; i < 4; i++) o[i] = __floats2half2_rn(r[2 * i], r[2 * i + 1]);
    ((uint4*)(dst + (size_t)w * 256))[lane] = *(const uint4*)o;
}

// Final layer: F=128 node gather + fused attention logit + global max
__global__ void k_node_agg_final(const __half* __restrict__ xwE,
                                 const int* __restrict__ off_n, const int* __restrict__ csr_n,
                                 const float* __restrict__ dinv, const float* __restrict__ bias,
                                 const float* __restrict__ aw, const float* __restrict__ ab,
                                 float* __restrict__ dst, float* __restrict__ logits,
                                 unsigned int* maxbits) {
    int w = (blockIdx.x * blockDim.x + threadIdx.x) >> 5;
    int lane = threadIdx.x & 31;
    float d = -3.4e38f;
    if (w < N_NODES) {
        float a[4] = {0, 0, 0, 0};
        int beg = off_n[w], end = off_n[w + 1];
        int m = beg;
        for (; m + 3 < end; m += 4) {
            int e0 = csr_n[m], e1 = csr_n[m + 1], e2 = csr_n[m + 2], e3 = csr_n[m + 3];
            uint2 v0 = ((const uint2*)(xwE + (size_t)e0 * 128))[lane];
            uint2 v1 = ((const uint2*)(xwE + (size_t)e1 * 128))[lane];
            uint2 v2 = ((const uint2*)(xwE + (size_t)e2 * 128))[lane];
            uint2 v3 = ((const uint2*)(xwE + (size_t)e3 * 128))[lane];
            const __half2* h0 = (const __half2*)&v0;
            const __half2* h1 = (const __half2*)&v1;
            const __half2* h2 = (const __half2*)&v2;
            const __half2* h3 = (const __half2*)&v3;
            #pragma unroll
            for (int i = 0; i < 2; i++) {
                float2 f0 = __half22float2(h0[i]);
                float2 f1 = __half22float2(h1[i]);
                float2 f2 = __half22float2(h2[i]);
                float2 f3 = __half22float2(h3[i]);
                a[2 * i] += f0.x + f1.x + f2.x + f3.x;
                a[2 * i + 1] += f0.y + f1.y + f2.y + f3.y;
            }
        }
        for (; m < end; m++) {
            uint2 v0 = ((const uint2*)(xwE + (size_t)csr_n[m] * 128))[lane];
            const __half2* h0 = (const __half2*)&v0;
            #pragma unroll
            for (int i = 0; i < 2; i++) {
                float2 f0 = __half22float2(h0[i]);
                a[2 * i] += f0.x;
                a[2 * i + 1] += f0.y;
            }
        }
        float di = dinv[w];
        float4 bb = ((const float4*)bias)[lane];
        float4 r;
        r.x = a[0] * di + bb.x; r.y = a[1] * di + bb.y;
        r.z = a[2] * di + bb.z; r.w = a[3] * di + bb.w;
        ((float4*)(dst + (size_t)w * 128))[lane] = r;
        float4 wv = ((const float4*)aw)[lane];
        float dd = r.x * wv.x + r.y * wv.y + r.z * wv.z + r.w * wv.w;
        #pragma unroll
        for (int o = 16; o; o >>= 1) dd += __shfl_xor_sync(0xffffffffu, dd, o);
        dd += ab[0];
        if (lane == 0) logits[w] = dd;
        d = dd;
    }
    __shared__ float smax[8];
    if (lane == 0) smax[threadIdx.x >> 5] = d;
    __syncthreads();
    if (threadIdx.x < 8) {
        float mv = smax[threadIdx.x];
        #pragma unroll
        for (int o = 4; o; o >>= 1) mv = fmaxf(mv, __shfl_xor_sync(0xffu, mv, o));
        if (threadIdx.x == 0) atomicMax(maxbits, enc_f(mv));
    }
}

// ---------------- softmax pooling ----------------
__global__ void k_sumexp(const float* __restrict__ logits, const unsigned int* __restrict__ maxbits,
                         float* sumexp) {
    float mx = dec_f(*maxbits);
    int i = blockIdx.x * blockDim.x + threadIdx.x;
    int stride = gridDim.x * blockDim.x;
    float s = 0.f;
    for (int j = i; j < N_NODES; j += stride) s += expf(logits[j] - mx);
    #pragma unroll
    for (int o = 16; o; o >>= 1) s += __shfl_xor_sync(0xffffffffu, s, o);
    __shared__ float sm[8];
    if ((threadIdx.x & 31) == 0) sm[threadIdx.x >> 5] = s;
    __syncthreads();
    if (threadIdx.x < 8) {
        float t = sm[threadIdx.x];
        #pragma unroll
        for (int o = 4; o; o >>= 1) t += __shfl_xor_sync(0xffu, t, o);
        if (threadIdx.x == 0) atomicAdd(sumexp, t);
    }
}

#define POOL_CH 256
__global__ void k_pool(const float* __restrict__ h, const float* __restrict__ logits,
                       const unsigned int* __restrict__ maxbits, const float* __restrict__ sumexp,
                       float* __restrict__ out) {
    __shared__ float wts[POOL_CH];
    float mx = dec_f(*maxbits);
    float inv = 1.0f / (*sumexp);
    int base = blockIdx.x * POOL_CH;
    for (int i = threadIdx.x; i < POOL_CH; i += 128) {
        int n = base + i;
        wts[i] = (n < N_NODES) ? expf(logits[n] - mx) : 0.0f;
    }
    __syncthreads();
    int f = threadIdx.x;
    int lim = min(POOL_CH, N_NODES - base);
    float acc = 0.f;
    for (int i = 0; i < lim; i++) acc += wts[i] * h[(size_t)(base + i) * 128 + f];
    atomicAdd(&out[f], acc * inv);
}

// ---------------- host-side tensormap plumbing ----------------
typedef CUresult (*PFN_encodeTmap)(
    CUtensorMap*, CUtensorMapDataType, unsigned int, void*,
    const unsigned long long*, const unsigned long long*,
    const unsigned int*, const unsigned int*,
    CUtensorMapInterleave, CUtensorMapSwizzle, CUtensorMapL2promotion, CUtensorMapFloatOOBfill);

// ---------------- launch ----------------
extern "C" void kernel_launch(void* const* d_in, const int* in_sizes, int n_in,
                              void* d_out, int out_size) {
    const float* x   = (const float*)d_in[0];
    const int*   hei = (const int*)d_in[1];
    const int*   nidx = hei;
    const int*   eidx = hei + NNZ;
    const float* W1 = (const float*)d_in[2];
    const float* b1 = (const float*)d_in[3];
    const float* W2 = (const float*)d_in[4];
    const float* b2 = (const float*)d_in[5];
    const float* W3 = (const float*)d_in[6];
    const float* b3 = (const float*)d_in[7];
    const float* aw = (const float*)d_in[8];
    const float* ab = (const float*)d_in[9];
    float* out = (float*)d_out;

    static __half *p_xh = nullptr, *p_xwE, *p_h16, *p_h16b;
    static float *p_hA, *p_binv, *p_dinv, *p_logits, *p_sumexp;
    static int *p_deg_e, *p_deg_n, *p_off_e, *p_off_n, *p_cur_e, *p_cur_n, *p_csr_e, *p_csr_n;
    static int *p_bsum_e, *p_bsum_n;
    static unsigned int* p_maxbits;
    static __nv_bfloat16 *p_Apk, *p_Wpk;
    static CUtensorMap tmA, tmB;
    if (!p_xh) {
        cudaGetSymbolAddress((void**)&p_xh, g_xh);
        cudaGetSymbolAddress((void**)&p_xwE, g_xwE);
        cudaGetSymbolAddress((void**)&p_h16, g_h16);
        cudaGetSymbolAddress((void**)&p_h16b, g_h16b);
        cudaGetSymbolAddress((void**)&p_hA, g_hA);
        cudaGetSymbolAddress((void**)&p_binv, g_binv);
        cudaGetSymbolAddress((void**)&p_dinv, g_dinv);
        cudaGetSymbolAddress((void**)&p_logits, g_logits);
        cudaGetSymbolAddress((void**)&p_sumexp, g_sumexp);
        cudaGetSymbolAddress((void**)&p_deg_e, g_deg_e);
        cudaGetSymbolAddress((void**)&p_deg_n, g_deg_n);
        cudaGetSymbolAddress((void**)&p_off_e, g_off_e);
        cudaGetSymbolAddress((void**)&p_off_n, g_off_n);
        cudaGetSymbolAddress((void**)&p_cur_e, g_cur_e);
        cudaGetSymbolAddress((void**)&p_cur_n, g_cur_n);
        cudaGetSymbolAddress((void**)&p_csr_e, g_csr_e);
        cudaGetSymbolAddress((void**)&p_csr_n, g_csr_n);
        cudaGetSymbolAddress((void**)&p_bsum_e, g_bsum_e);
        cudaGetSymbolAddress((void**)&p_bsum_n, g_bsum_n);
        cudaGetSymbolAddress((void**)&p_maxbits, g_maxbits);
        cudaGetSymbolAddress((void**)&p_Apk, g_Apk);
        cudaGetSymbolAddress((void**)&p_Wpk, g_Wpk);
        cudaFuncSetAttribute(k_mma_gemm, cudaFuncAttributeMaxDynamicSharedMemorySize, SMEM_GEMM);

        void* fp = nullptr;
        cudaDriverEntryPointQueryResult qr;
        cudaGetDriverEntryPoint("cuTensorMapEncodeTiled", &fp, cudaEnableDefault, &qr);
        PFN_encodeTmap enc = (PFN_encodeTmap)fp;
        unsigned long long dimsA[3] = {128ull, (unsigned long long)N_EDGES, (unsigned long long)NCHUNK};
        unsigned long long strA[2]  = {128ull, 128ull * N_EDGES};
        unsigned long long dimsB[3] = {128ull, 256ull, (unsigned long long)NCHUNK};
        unsigned long long strB[2]  = {128ull, 128ull * 256ull};
        unsigned int box[3] = {128u, 128u, 1u};
        unsigned int est[3] = {1u, 1u, 1u};
        enc(&tmA, CU_TENSOR_MAP_DATA_TYPE_UINT8, 3, (void*)p_Apk, dimsA, strA, box, est,
            CU_TENSOR_MAP_INTERLEAVE_NONE, CU_TENSOR_MAP_SWIZZLE_128B,
            CU_TENSOR_MAP_L2_PROMOTION_L2_128B, CU_TENSOR_MAP_FLOAT_OOB_FILL_NONE);
        enc(&tmB, CU_TENSOR_MAP_DATA_TYPE_UINT8, 3, (void*)p_Wpk, dimsB, strB, box, est,
            CU_TENSOR_MAP_INTERLEAVE_NONE, CU_TENSOR_MAP_SWIZZLE_128B,
            CU_TENSOR_MAP_L2_PROMOTION_L2_128B, CU_TENSOR_MAP_FLOAT_OOB_FILL_NONE);
    }

    // ---- CSR build + x conversion ----
    k_zero_meta<<<400, 256>>>(p_deg_e, p_deg_n, p_cur_e, p_cur_n, p_maxbits, p_sumexp, out);
    k_count<<<(NNZ + 255) / 256, 256>>>(nidx, eidx, p_deg_n, p_deg_e);
    k_cvtX<<<N_NODES, 320>>>(x, p_xh);
    const int NBE = (N_EDGES + 1023) / 1024;
    const int NBN = (N_NODES + 1023) / 1024;
    k_scan_local<<<NBE, 1024>>>(p_deg_e, p_off_e, p_bsum_e, N_EDGES);
    k_scan_local<<<NBN, 1024>>>(p_deg_n, p_off_n, p_bsum_n, N_NODES);
    k_scan_carry<<<1, 32>>>(p_bsum_e, NBE, p_off_e + N_EDGES, p_bsum_n, NBN, p_off_n + N_NODES);
    k_scan_add<<<(N_EDGES + 255) / 256, 256>>>(p_off_e, p_bsum_e, p_deg_e, p_binv, N_EDGES);
    k_scan_add<<<(N_NODES + 255) / 256, 256>>>(p_off_n, p_bsum_n, p_deg_n, p_dinv, N_NODES);
    k_fill<<<(NNZ + 255) / 256, 256>>>(nidx, eidx, p_off_e, p_off_n, p_cur_e, p_cur_n, p_csr_e, p_csr_n);

    const int EB = (N_EDGES * 32) / 256;    // 2500
    const int NB = (N_NODES * 32) / 256;    // 12500
    const int GM = (N_EDGES + 127) / 128;   // 157

    // ---- layer 1 ----
    k_packW<<<256, 320>>>(W1, 300, 256, p_Wpk);
    k_edge_pack320<<<EB, 256>>>(p_xh, p_off_e, p_csr_e, p_binv, p_Apk);
    k_mma_gemm<<<dim3(2, GM), 256, SMEM_GEMM>>>(tmA, tmB, p_xwE, N_EDGES, 256, 10);
    k_node_agg256<<<NB, 256>>>(p_xwE, p_off_n, p_csr_n, p_dinv, b1, p_h16);

    // ---- layer 2 ----
    k_packW<<<256, 320>>>(W2, 256, 256, p_Wpk);
    k_edge_pack256<<<EB, 256>>>(p_h16, p_off_e, p_csr_e, p_binv, p_Apk);
    k_mma_gemm<<<dim3(2, GM), 256, SMEM_GEMM>>>(tmA, tmB, p_xwE, N_EDGES, 256, 8);
    k_node_agg256<<<NB, 256>>>(p_xwE, p_off_n, p_csr_n, p_dinv, b2, p_h16b);

    // ---- layer 3 (Fout=128) + fused logits ----
    k_packW<<<128, 320>>>(W3, 256, 128, p_Wpk);
    k_edge_pack256<<<EB, 256>>>(p_h16b, p_off_e, p_csr_e, p_binv, p_Apk);
    k_mma_gemm<<<dim3(1, GM), 256, SMEM_GEMM>>>(tmA, tmB, p_xwE, N_EDGES, 128, 8);
    k_node_agg_final<<<NB, 256>>>(p_xwE, p_off_n, p_csr_n, p_dinv, b3, aw, ab,
                                  p_hA, p_logits, p_maxbits);

    // ---- softmax pooling ----
    k_sumexp<<<512, 256>>>(p_logits, p_maxbits, p_sumexp);
    k_pool<<<(N_NODES + POOL_CH - 1) / POOL_CH, 128>>>(p_hA, p_logits, p_maxbits, p_sumexp, out);
}

// round 9
// speedup vs baseline: 2.6487x; 1.0312x over previous
#include <cuda_runtime.h>
#include <cuda.h>
#include <cuda_bf16.h>
#include <cuda_fp16.h>
#include <math.h>
#include <stdint.h>

#define N_NODES 100000
#define N_EDGES 20000
#define NNZ     1600000
#define NCHUNK  10          // 10 chunks of 32 k => KPAD 320

// ---------------- scratch (static device globals; no allocation) ----------------
__device__ __align__(128) __half g_xh[(size_t)N_NODES * 320];    // x in fp16, padded
__device__ __align__(128) __half g_xwE[(size_t)N_EDGES * 256];   // edge GEMM output (fp16)
__device__ __align__(128) __half g_h16[(size_t)N_NODES * 256];   // layer output fp16 (ping)
__device__ __align__(128) __half g_h16b[(size_t)N_NODES * 256];  // layer output fp16 (pong)
__device__ float g_t[N_EDGES];       // per-edge logit contribution
__device__ float g_s[N_EDGES];       // per-edge softmax-coefficient sum
__device__ float g_c[N_NODES];       // per-node attn*dinv coefficient
__device__ float g_cdot;             // b3 . aw + ab
// packed bf16 tiles, chunk-major: [chunk][row][hi 32 bf16 | lo 32 bf16] = 128B rows
__device__ __align__(1024) __nv_bfloat16 g_Apk[(size_t)NCHUNK * N_EDGES * 64];
__device__ __align__(1024) __nv_bfloat16 g_Wpk[(size_t)NCHUNK * 256 * 64];

__device__ int   g_deg_e[N_EDGES];
__device__ int   g_deg_n[N_NODES];
__device__ float g_binv[N_EDGES];
__device__ float g_dinv[N_NODES];
__device__ int   g_off_e[N_EDGES + 1];
__device__ int   g_off_n[N_NODES + 1];
__device__ int   g_cur_e[N_EDGES];
__device__ int   g_cur_n[N_NODES];
__device__ int   g_csr_e[NNZ];
__device__ int   g_csr_n[NNZ];
__device__ int   g_bsum_e[64];
__device__ int   g_bsum_n[128];

__device__ float        g_logits[N_NODES];
__device__ unsigned int g_maxbits;
__device__ float        g_sumexp;

// ---------------- PTX helpers (plain sm_103-safe: no tcgen05) ----------------
__device__ __forceinline__ uint32_t smem_u32(const void* p) {
    uint32_t a;
    asm("{ .reg .u64 t; cvta.to.shared.u64 t, %1; cvt.u32.u64 %0, t; }" : "=r"(a) : "l"(p));
    return a;
}
#define MBAR_INIT(a, cnt) asm volatile("mbarrier.init.shared.b64 [%0], %1;" :: "r"(a), "r"(cnt) : "memory")
#define MBAR_EXPECT_TX(a, b) asm volatile("mbarrier.arrive.expect_tx.shared.b64 _, [%0], %1;" :: "r"(a), "r"(b) : "memory")
#define MBAR_WAIT(a, par) do {                                             \
    uint32_t _m = (a); uint32_t _p = (par); uint32_t _d;                   \
    asm volatile("{\n .reg .pred p;\n"                                     \
        " mbarrier.try_wait.parity.acquire.cta.shared::cta.b64 p, [%1], %2;\n" \
        " selp.b32 %0,1,0,p;\n}" : "=r"(_d) : "r"(_m), "r"(_p) : "memory");\
    if (!_d) {                                                             \
        asm volatile("{\n .reg .pred P1;\n"                                \
        "W_%=:\n mbarrier.try_wait.parity.acquire.cta.shared::cta.b64 P1, [%0], %1, 0x989680;\n" \
        " @P1 bra.uni D_%=;\n bra.uni W_%=;\nD_%=:\n}"                     \
        :: "r"(_m), "r"(_p) : "memory");                                   \
    } } while (0)

__device__ __forceinline__ void tma3d(uint32_t dst, const void* tmap, int x, int y, int z, uint32_t mbar) {
    asm volatile(
        "cp.async.bulk.tensor.3d.shared::cta.global.tile.mbarrier::complete_tx::bytes "
        "[%0], [%1, {%2, %3, %4}], [%5];"
        :: "r"(dst), "l"(tmap), "r"(x), "r"(y), "r"(z), "r"(mbar) : "memory");
}
__device__ __forceinline__ void ldsm4(uint32_t* r, uint32_t addr) {
    asm volatile("ldmatrix.sync.aligned.m8n8.x4.shared.b16 {%0,%1,%2,%3}, [%4];"
        : "=r"(r[0]), "=r"(r[1]), "=r"(r[2]), "=r"(r[3]) : "r"(addr));
}
__device__ __forceinline__ void mma16816(float* d, const uint32_t* a, const uint32_t* b) {
    asm volatile("mma.sync.aligned.m16n8k16.row.col.f32.bf16.bf16.f32 "
        "{%0,%1,%2,%3}, {%4,%5,%6,%7}, {%8,%9}, {%0,%1,%2,%3};"
        : "+f"(d[0]), "+f"(d[1]), "+f"(d[2]), "+f"(d[3])
        : "r"(a[0]), "r"(a[1]), "r"(a[2]), "r"(a[3]), "r"(b[0]), "r"(b[1]));
}
__device__ __forceinline__ uint32_t swz(uint32_t base, int row, int byteCol) {
    return base + row * 128 + (byteCol ^ ((row & 7) << 4));
}

// ---------------- misc helpers ----------------
__device__ __forceinline__ unsigned int enc_f(float f) {
    unsigned int u = __float_as_uint(f);
    return (u & 0x80000000u) ? ~u : (u | 0x80000000u);
}
__device__ __forceinline__ float dec_f(unsigned int u) {
    u = (u & 0x80000000u) ? (u ^ 0x80000000u) : ~u;
    return __uint_as_float(u);
}
// accumulate 8 fp16 values (one uint4) into 8 fp32 accumulators
__device__ __forceinline__ void addh8(float* a, uint4 v) {
    const __half2* h = (const __half2*)&v;
    #pragma unroll
    for (int i = 0; i < 4; i++) {
        float2 f = __half22float2(h[i]);
        a[2 * i] += f.x;
        a[2 * i + 1] += f.y;
    }
}
// pack 4 floats (features 4v..4v+3) of edge-row e into chunk-major bf16 hi/lo layout
__device__ __forceinline__ void pack_write(__nv_bfloat16* __restrict__ apk, int v, int e,
                                           float r0, float r1, float r2, float r3) {
    int chunk = v >> 3;
    int pos = (v & 7) * 4;
    size_t base = ((size_t)chunk * N_EDGES + e) * 64 + pos;
    __nv_bfloat16 h0 = __float2bfloat16(r0), h1 = __float2bfloat16(r1);
    __nv_bfloat16 h2 = __float2bfloat16(r2), h3 = __float2bfloat16(r3);
    *(__nv_bfloat162*)(apk + base)     = __halves2bfloat162(h0, h1);
    *(__nv_bfloat162*)(apk + base + 2) = __halves2bfloat162(h2, h3);
    __nv_bfloat16 l0 = __float2bfloat16(r0 - __bfloat162float(h0));
    __nv_bfloat16 l1 = __float2bfloat16(r1 - __bfloat162float(h1));
    __nv_bfloat16 l2 = __float2bfloat16(r2 - __bfloat162float(h2));
    __nv_bfloat16 l3 = __float2bfloat16(r3 - __bfloat162float(h3));
    *(__nv_bfloat162*)(apk + base + 32) = __halves2bfloat162(l0, l1);
    *(__nv_bfloat162*)(apk + base + 34) = __halves2bfloat162(l2, l3);
}

// ---------------- setup kernels ----------------
__global__ void k_zero_meta(int* deg_e, int* deg_n, int* cur_e, int* cur_n,
                            unsigned int* maxbits, float* sumexp, float* out) {
    int i = blockIdx.x * blockDim.x + threadIdx.x;
    int stride = gridDim.x * blockDim.x;
    for (int j = i; j < N_NODES; j += stride) {
        deg_n[j] = 0; cur_n[j] = 0;
        if (j < N_EDGES) { deg_e[j] = 0; cur_e[j] = 0; }
        if (j < 128) out[j] = 0.0f;
        if (j == 0) { *maxbits = 0u; *sumexp = 0.0f; }
    }
}

__global__ void k_count(const int* __restrict__ nidx, const int* __restrict__ eidx,
                        int* deg_n, int* deg_e) {
    int i = blockIdx.x * blockDim.x + threadIdx.x;
    if (i < NNZ) {
        atomicAdd(&deg_e[eidx[i]], 1);
        atomicAdd(&deg_n[nidx[i]], 1);
    }
}

__global__ void k_scan_local(const int* __restrict__ deg, int* __restrict__ off,
                             int* __restrict__ bsum, int n) {
    __shared__ int sh[1024];
    int i = blockIdx.x * 1024 + threadIdx.x;
    int v = (i < n) ? deg[i] : 0;
    sh[threadIdx.x] = v;
    __syncthreads();
    #pragma unroll
    for (int s = 1; s < 1024; s <<= 1) {
        int t = (threadIdx.x >= (unsigned)s) ? sh[threadIdx.x - s] : 0;
        __syncthreads();
        sh[threadIdx.x] += t;
        __syncthreads();
    }
    if (i < n) off[i] = sh[threadIdx.x] - v;
    if (threadIdx.x == 1023) bsum[blockIdx.x] = sh[1023];
}

__global__ void k_scan_carry(int* bsum_e, int nbe, int* tot_e,
                             int* bsum_n, int nbn, int* tot_n) {
    if (threadIdx.x == 0) {
        int s = 0;
        for (int i = 0; i < nbe; i++) { int v = bsum_e[i]; bsum_e[i] = s; s += v; }
        *tot_e = s;
    }
    if (threadIdx.x == 1) {
        int s = 0;
        for (int i = 0; i < nbn; i++) { int v = bsum_n[i]; bsum_n[i] = s; s += v; }
        *tot_n = s;
    }
}

__global__ void k_scan_add(int* __restrict__ off, const int* __restrict__ bsum,
                           const int* __restrict__ deg, float* __restrict__ inv, int n) {
    int i = blockIdx.x * blockDim.x + threadIdx.x;
    if (i < n) {
        off[i] += bsum[i >> 10];
        int d = deg[i];
        inv[i] = (d > 0) ? (1.0f / (float)d) : 0.0f;
    }
}

__global__ void k_fill(const int* __restrict__ nidx, const int* __restrict__ eidx,
                       const int* __restrict__ off_e, const int* __restrict__ off_n,
                       int* cur_e, int* cur_n, int* csr_e, int* csr_n) {
    int i = blockIdx.x * blockDim.x + threadIdx.x;
    if (i < NNZ) {
        int e = eidx[i], n = nidx[i];
        int p = atomicAdd(&cur_e[e], 1);
        csr_e[off_e[e] + p] = n;
        int q = atomicAdd(&cur_n[n], 1);
        csr_n[off_n[n] + q] = e;
    }
}

// x [N_NODES,300] fp32 -> g_xh [N_NODES,320] fp16 (zero padded)
__global__ void k_cvtX(const float* __restrict__ x, __half* __restrict__ xh) {
    int m = blockIdx.x;
    int k = threadIdx.x;   // 320
    float v = (k < 300) ? x[(size_t)m * 300 + k] : 0.0f;
    xh[(size_t)m * 320 + k] = __float2half_rn(v);
}

// W [K][N] fp32 -> Wpk [chunk][n][hi32|lo32] (transposed, fixed 256-row stride)
__global__ void k_packW(const float* __restrict__ W, int K, int N, __nv_bfloat16* __restrict__ wpk) {
    int n = blockIdx.x;
    int k = threadIdx.x;   // 320 threads
    float a = (k < K) ? W[(size_t)k * N + n] : 0.0f;
    __nv_bfloat16 h = __float2bfloat16(a);
    float r = a - __bfloat162float(h);
    size_t idx = ((size_t)(k >> 5) * 256 + n) * 64 + (k & 31);
    wpk[idx] = h;
    wpk[idx + 32] = __float2bfloat16(r);
}

// ---------------- edge gather (fp16 source) + fused bf16x3 pack ----------------
__global__ void k_edge_pack320(const __half* __restrict__ xh,
                               const int* __restrict__ off_e, const int* __restrict__ csr_e,
                               const float* __restrict__ binv, __nv_bfloat16* __restrict__ apk) {
    int w = (blockIdx.x * blockDim.x + threadIdx.x) >> 5;
    if (w >= N_EDGES) return;
    int lane = threadIdx.x & 31;
    float a[8] = {0, 0, 0, 0, 0, 0, 0, 0};
    float b[8] = {0, 0, 0, 0, 0, 0, 0, 0};
    bool hasB = lane < 8;
    int beg = off_e[w], end = off_e[w + 1];
    int m = beg;
    for (; m + 3 < end; m += 4) {
        int n0 = csr_e[m], n1 = csr_e[m + 1], n2 = csr_e[m + 2], n3 = csr_e[m + 3];
        const uint4* r0 = (const uint4*)(xh + (size_t)n0 * 320);
        const uint4* r1 = (const uint4*)(xh + (size_t)n1 * 320);
        const uint4* r2 = (const uint4*)(xh + (size_t)n2 * 320);
        const uint4* r3 = (const uint4*)(xh + (size_t)n3 * 320);
        addh8(a, r0[lane]); addh8(a, r1[lane]); addh8(a, r2[lane]); addh8(a, r3[lane]);
        if (hasB) {
            addh8(b, r0[lane + 32]); addh8(b, r1[lane + 32]);
            addh8(b, r2[lane + 32]); addh8(b, r3[lane + 32]);
        }
    }
    for (; m < end; m++) {
        const uint4* r0 = (const uint4*)(xh + (size_t)csr_e[m] * 320);
        addh8(a, r0[lane]);
        if (hasB) addh8(b, r0[lane + 32]);
    }
    float bi = binv[w];
    #pragma unroll
    for (int i = 0; i < 8; i++) { a[i] *= bi; b[i] *= bi; }
    pack_write(apk, 2 * lane, w, a[0], a[1], a[2], a[3]);
    pack_write(apk, 2 * lane + 1, w, a[4], a[5], a[6], a[7]);
    if (hasB) {
        pack_write(apk, 64 + 2 * lane, w, b[0], b[1], b[2], b[3]);
        pack_write(apk, 64 + 2 * lane + 1, w, b[4], b[5], b[6], b[7]);
    }
}

__global__ void k_edge_pack256(const __half* __restrict__ h,
                               const int* __restrict__ off_e, const int* __restrict__ csr_e,
                               const float* __restrict__ binv, __nv_bfloat16* __restrict__ apk) {
    int w = (blockIdx.x * blockDim.x + threadIdx.x) >> 5;
    if (w >= N_EDGES) return;
    int lane = threadIdx.x & 31;
    float a[8] = {0, 0, 0, 0, 0, 0, 0, 0};
    int beg = off_e[w], end = off_e[w + 1];
    int m = beg;
    for (; m + 3 < end; m += 4) {
        int n0 = csr_e[m], n1 = csr_e[m + 1], n2 = csr_e[m + 2], n3 = csr_e[m + 3];
        addh8(a, ((const uint4*)(h + (size_t)n0 * 256))[lane]);
        addh8(a, ((const uint4*)(h + (size_t)n1 * 256))[lane]);
        addh8(a, ((const uint4*)(h + (size_t)n2 * 256))[lane]);
        addh8(a, ((const uint4*)(h + (size_t)n3 * 256))[lane]);
    }
    for (; m < end; m++)
        addh8(a, ((const uint4*)(h + (size_t)csr_e[m] * 256))[lane]);
    float bi = binv[w];
    #pragma unroll
    for (int i = 0; i < 8; i++) a[i] *= bi;
    pack_write(apk, 2 * lane, w, a[0], a[1], a[2], a[3]);
    pack_write(apk, 2 * lane + 1, w, a[4], a[5], a[6], a[7]);
}

// ---------------- TMA + mma.sync bf16x3 GEMM, fp16 output (round-5 proven) ----------------
#define STAGE_B 32768
#define N_STAGE 4
#define MB_OFF  (N_STAGE * STAGE_B)
#define SMEM_GEMM (MB_OFF + 64)

__global__ __launch_bounds__(256, 1) void k_mma_gemm(
    const __grid_constant__ CUtensorMap tmA,
    const __grid_constant__ CUtensorMap tmB,
    __half* __restrict__ C, int M, int Ncols, int chunks) {
    extern __shared__ char smem[];
    uint32_t sb = smem_u32(smem);
    int tid = threadIdx.x;
    int lane = tid & 31;
    int wid = tid >> 5;
    int wm = wid >> 2;
    int wn = wid & 3;
    int mBase = blockIdx.y * 128;
    int nBase = blockIdx.x * 128;

    if (tid == 0) {
        #pragma unroll
        for (int s = 0; s < N_STAGE; s++) MBAR_INIT(sb + MB_OFF + s * 8, 1);
    }
    __syncthreads();
    if (tid == 0) {
        #pragma unroll
        for (int s = 0; s < N_STAGE; s++) {
            MBAR_EXPECT_TX(sb + MB_OFF + s * 8, STAGE_B);
            tma3d(sb + s * STAGE_B, &tmA, 0, mBase, s, sb + MB_OFF + s * 8);
            tma3d(sb + s * STAGE_B + 16384, &tmB, 0, nBase, s, sb + MB_OFF + s * 8);
        }
    }

    int a_row = lane & 15;
    int a_byte = (lane >> 4) << 4;
    int b_row = ((lane & 16) >> 1) + (lane & 7);
    int b_byte = (lane & 8) * 2;

    float acc[4][4][4];
    #pragma unroll
    for (int i = 0; i < 4; i++)
        #pragma unroll
        for (int j = 0; j < 4; j++)
            #pragma unroll
            for (int q = 0; q < 4; q++) acc[i][j][q] = 0.0f;

    for (int c = 0; c < chunks; c++) {
        int st = c & (N_STAGE - 1);
        MBAR_WAIT(sb + MB_OFF + st * 8, (c >> 2) & 1);
        uint32_t sA = sb + st * STAGE_B;
        uint32_t sB = sA + 16384;
        #pragma unroll
        for (int ks = 0; ks < 2; ks++) {
            int kbh = ks * 32;
            int kbl = 64 + ks * 32;
            uint32_t ah[4][4], al[4][4], bh[2][4], bl[2][4];
            #pragma unroll
            for (int i = 0; i < 4; i++) {
                int r = wm * 64 + i * 16 + a_row;
                ldsm4(ah[i], swz(sA, r, kbh + a_byte));
                ldsm4(al[i], swz(sA, r, kbl + a_byte));
            }
            #pragma unroll
            for (int jj = 0; jj < 2; jj++) {
                int r = wn * 32 + jj * 16 + b_row;
                ldsm4(bh[jj], swz(sB, r, kbh + b_byte));
                ldsm4(bl[jj], swz(sB, r, kbl + b_byte));
            }
            #pragma unroll
            for (int i = 0; i < 4; i++)
                #pragma unroll
                for (int j = 0; j < 4; j++) {
                    const uint32_t* bH = &bh[j >> 1][(j & 1) * 2];
                    const uint32_t* bL = &bl[j >> 1][(j & 1) * 2];
                    mma16816(acc[i][j], ah[i], bH);
                    mma16816(acc[i][j], al[i], bH);
                    mma16816(acc[i][j], ah[i], bL);
                }
        }
        __syncthreads();
        if (tid == 0 && c + N_STAGE < chunks) {
            MBAR_EXPECT_TX(sb + MB_OFF + st * 8, STAGE_B);
            tma3d(sb + st * STAGE_B, &tmA, 0, mBase, c + N_STAGE, sb + MB_OFF + st * 8);
            tma3d(sb + st * STAGE_B + 16384, &tmB, 0, nBase, c + N_STAGE, sb + MB_OFF + st * 8);
        }
    }

    #pragma unroll
    for (int i = 0; i < 4; i++) {
        int r0 = mBase + wm * 64 + i * 16 + (lane >> 2);
        #pragma unroll
        for (int j = 0; j < 4; j++) {
            int cc = nBase + wn * 32 + j * 8 + (lane & 3) * 2;
            if (r0 < M)
                *(__half2*)&C[(size_t)r0 * Ncols + cc] =
                    __floats2half2_rn(acc[i][j][0], acc[i][j][1]);
            if (r0 + 8 < M)
                *(__half2*)&C[(size_t)(r0 + 8) * Ncols + cc] =
                    __floats2half2_rn(acc[i][j][2], acc[i][j][3]);
        }
    }
}

// ---------------- node gather (fp16 edge GEMM output) -> fp16 h (round-5 proven) ----------------
__global__ void k_node_agg256(const __half* __restrict__ xwE,
                              const int* __restrict__ off_n, const int* __restrict__ csr_n,
                              const float* __restrict__ dinv, const float* __restrict__ bias,
                              __half* __restrict__ dst) {
    int w = (blockIdx.x * blockDim.x + threadIdx.x) >> 5;
    if (w >= N_NODES) return;
    int lane = threadIdx.x & 31;
    float a[8] = {0, 0, 0, 0, 0, 0, 0, 0};
    int beg = off_n[w], end = off_n[w + 1];
    int m = beg;
    for (; m + 3 < end; m += 4) {
        int e0 = csr_n[m], e1 = csr_n[m + 1], e2 = csr_n[m + 2], e3 = csr_n[m + 3];
        addh8(a, ((const uint4*)(xwE + (size_t)e0 * 256))[lane]);
        addh8(a, ((const uint4*)(xwE + (size_t)e1 * 256))[lane]);
        addh8(a, ((const uint4*)(xwE + (size_t)e2 * 256))[lane]);
        addh8(a, ((const uint4*)(xwE + (size_t)e3 * 256))[lane]);
    }
    for (; m < end; m++)
        addh8(a, ((const uint4*)(xwE + (size_t)csr_n[m] * 256))[lane]);
    float di = dinv[w];
    float4 b0 = ((const float4*)bias)[2 * lane];
    float4 b1 = ((const float4*)bias)[2 * lane + 1];
    float r[8];
    r[0] = a[0] * di + b0.x; r[1] = a[1] * di + b0.y;
    r[2] = a[2] * di + b0.z; r[3] = a[3] * di + b0.w;
    r[4] = a[4] * di + b1.x; r[5] = a[5] * di + b1.y;
    r[6] = a[6] * di + b1.z; r[7] = a[7] * di + b1.w;
    #pragma unroll
    for (int i = 0; i < 8; i++) r[i] = r[i] > 0.f ? r[i] : 0.01f * r[i];
    __half2 o[4];
    #pragma unroll
    for (int i = 0; i < 4; i++) o[i] = __floats2half2_rn(r[2 * i], r[2 * i + 1]);
    ((uint4*)(dst + (size_t)w * 256))[lane] = *(const uint4*)o;
}

// ---------------- final-layer algebraic tail ----------------
// cdot = b3 . aw + ab
__global__ void k_cdot(const float* __restrict__ b3, const float* __restrict__ aw,
                       const float* __restrict__ ab, float* __restrict__ cdot) {
    int f = threadIdx.x;   // 128
    float v = b3[f] * aw[f];
    #pragma unroll
    for (int o = 16; o; o >>= 1) v += __shfl_xor_sync(0xffffffffu, v, o);
    __shared__ float sm[4];
    if ((f & 31) == 0) sm[f >> 5] = v;
    __syncthreads();
    if (f == 0) *cdot = sm[0] + sm[1] + sm[2] + sm[3] + ab[0];
}

// t_e = xwE_e . aw  (warp per edge, 128 cols fp16)
__global__ void k_edge_dot(const __half* __restrict__ xwE, const float* __restrict__ aw,
                           float* __restrict__ t) {
    int e = (blockIdx.x * blockDim.x + threadIdx.x) >> 5;
    if (e >= N_EDGES) return;
    int lane = threadIdx.x & 31;
    uint2 v = ((const uint2*)(xwE + (size_t)e * 128))[lane];   // feats 4*lane..+3
    const __half2* h = (const __half2*)&v;
    float2 f0 = __half22float2(h[0]);
    float2 f1 = __half22float2(h[1]);
    float4 wv = ((const float4*)aw)[lane];
    float d = f0.x * wv.x + f0.y * wv.y + f1.x * wv.z + f1.y * wv.w;
    #pragma unroll
    for (int o = 16; o; o >>= 1) d += __shfl_xor_sync(0xffffffffu, d, o);
    if (lane == 0) t[e] = d;
}

// logits_n = dinv_n * sum_{e in n} t_e + cdot ; block max -> atomicMax
__global__ void k_logits_node(const float* __restrict__ t,
                              const int* __restrict__ off_n, const int* __restrict__ csr_n,
                              const float* __restrict__ dinv, const float* __restrict__ cdot,
                              float* __restrict__ logits, unsigned int* maxbits) {
    int n = blockIdx.x * blockDim.x + threadIdx.x;
    float lg = -3.4e38f;
    if (n < N_NODES) {
        float s = 0.f;
        int beg = off_n[n], end = off_n[n + 1];
        for (int m = beg; m < end; m++) s += t[csr_n[m]];
        lg = dinv[n] * s + *cdot;
        logits[n] = lg;
    }
    #pragma unroll
    for (int o = 16; o; o >>= 1) lg = fmaxf(lg, __shfl_xor_sync(0xffffffffu, lg, o));
    __shared__ float sm[8];
    if ((threadIdx.x & 31) == 0) sm[threadIdx.x >> 5] = lg;
    __syncthreads();
    if (threadIdx.x < 8) {
        float mv = sm[threadIdx.x];
        #pragma unroll
        for (int o = 4; o; o >>= 1) mv = fmaxf(mv, __shfl_xor_sync(0xffu, mv, o));
        if (threadIdx.x == 0) atomicMax(maxbits, enc_f(mv));
    }
}

__global__ void k_sumexp(const float* __restrict__ logits, const unsigned int* __restrict__ maxbits,
                         float* sumexp) {
    float mx = dec_f(*maxbits);
    int i = blockIdx.x * blockDim.x + threadIdx.x;
    int stride = gridDim.x * blockDim.x;
    float s = 0.f;
    for (int j = i; j < N_NODES; j += stride) s += expf(logits[j] - mx);
    #pragma unroll
    for (int o = 16; o; o >>= 1) s += __shfl_xor_sync(0xffffffffu, s, o);
    __shared__ float sm[8];
    if ((threadIdx.x & 31) == 0) sm[threadIdx.x >> 5] = s;
    __syncthreads();
    if (threadIdx.x < 8) {
        float tt = sm[threadIdx.x];
        #pragma unroll
        for (int o = 4; o; o >>= 1) tt += __shfl_xor_sync(0xffu, tt, o);
        if (threadIdx.x == 0) atomicAdd(sumexp, tt);
    }
}

// c_n = exp(logit_n - mx) * dinv_n   (division by sumexp deferred)
__global__ void k_coef(const float* __restrict__ logits, const unsigned int* __restrict__ maxbits,
                       const float* __restrict__ dinv, float* __restrict__ c) {
    int n = blockIdx.x * blockDim.x + threadIdx.x;
    if (n < N_NODES) {
        float mx = dec_f(*maxbits);
        c[n] = expf(logits[n] - mx) * dinv[n];
    }
}

// s_e = sum_{n in e} c_n  (warp per edge, lanes stride members)
__global__ void k_edge_coef(const float* __restrict__ c,
                            const int* __restrict__ off_e, const int* __restrict__ csr_e,
                            float* __restrict__ s) {
    int e = (blockIdx.x * blockDim.x + threadIdx.x) >> 5;
    if (e >= N_EDGES) return;
    int lane = threadIdx.x & 31;
    float acc = 0.f;
    int beg = off_e[e], end = off_e[e + 1];
    for (int m = beg + lane; m < end; m += 32) acc += c[csr_e[m]];
    #pragma unroll
    for (int o = 16; o; o >>= 1) acc += __shfl_xor_sync(0xffffffffu, acc, o);
    if (lane == 0) s[e] = acc;
}

// out[f] += sum_e s_e * xwE[e][f]   (block per 128 edges)
__global__ void k_final_sum(const __half* __restrict__ xwE, const float* __restrict__ s,
                            float* __restrict__ out) {
    int f = threadIdx.x;   // 128
    int e0 = blockIdx.x * 128;
    int e1 = min(e0 + 128, N_EDGES);
    float acc = 0.f;
    for (int e = e0; e < e1; e++)
        acc += s[e] * __half2float(xwE[(size_t)e * 128 + f]);
    atomicAdd(&out[f], acc);
}

// out[f] = out[f] / sumexp + b3[f]
__global__ void k_finalize(float* __restrict__ out, const float* __restrict__ sumexp,
                           const float* __restrict__ b3) {
    int f = threadIdx.x;
    out[f] = out[f] / (*sumexp) + b3[f];
}

// ---------------- host-side tensormap plumbing ----------------
typedef CUresult (*PFN_encodeTmap)(
    CUtensorMap*, CUtensorMapDataType, unsigned int, void*,
    const unsigned long long*, const unsigned long long*,
    const unsigned int*, const unsigned int*,
    CUtensorMapInterleave, CUtensorMapSwizzle, CUtensorMapL2promotion, CUtensorMapFloatOOBfill);

// ---------------- launch ----------------
extern "C" void kernel_launch(void* const* d_in, const int* in_sizes, int n_in,
                              void* d_out, int out_size) {
    const float* x   = (const float*)d_in[0];
    const int*   hei = (const int*)d_in[1];
    const int*   nidx = hei;
    const int*   eidx = hei + NNZ;
    const float* W1 = (const float*)d_in[2];
    const float* b1 = (const float*)d_in[3];
    const float* W2 = (const float*)d_in[4];
    const float* b2 = (const float*)d_in[5];
    const float* W3 = (const float*)d_in[6];
    const float* b3 = (const float*)d_in[7];
    const float* aw = (const float*)d_in[8];
    const float* ab = (const float*)d_in[9];
    float* out = (float*)d_out;

    static __half *p_xh = nullptr, *p_xwE, *p_h16, *p_h16b;
    static float *p_t, *p_s, *p_c, *p_cdot;
    static float *p_binv, *p_dinv, *p_logits, *p_sumexp;
    static int *p_deg_e, *p_deg_n, *p_off_e, *p_off_n, *p_cur_e, *p_cur_n, *p_csr_e, *p_csr_n;
    static int *p_bsum_e, *p_bsum_n;
    static unsigned int* p_maxbits;
    static __nv_bfloat16 *p_Apk, *p_Wpk;
    static CUtensorMap tmA, tmB;
    if (!p_xh) {
        cudaGetSymbolAddress((void**)&p_xh, g_xh);
        cudaGetSymbolAddress((void**)&p_xwE, g_xwE);
        cudaGetSymbolAddress((void**)&p_h16, g_h16);
        cudaGetSymbolAddress((void**)&p_h16b, g_h16b);
        cudaGetSymbolAddress((void**)&p_t, g_t);
        cudaGetSymbolAddress((void**)&p_s, g_s);
        cudaGetSymbolAddress((void**)&p_c, g_c);
        cudaGetSymbolAddress((void**)&p_cdot, g_cdot);
        cudaGetSymbolAddress((void**)&p_binv, g_binv);
        cudaGetSymbolAddress((void**)&p_dinv, g_dinv);
        cudaGetSymbolAddress((void**)&p_logits, g_logits);
        cudaGetSymbolAddress((void**)&p_sumexp, g_sumexp);
        cudaGetSymbolAddress((void**)&p_deg_e, g_deg_e);
        cudaGetSymbolAddress((void**)&p_deg_n, g_deg_n);
        cudaGetSymbolAddress((void**)&p_off_e, g_off_e);
        cudaGetSymbolAddress((void**)&p_off_n, g_off_n);
        cudaGetSymbolAddress((void**)&p_cur_e, g_cur_e);
        cudaGetSymbolAddress((void**)&p_cur_n, g_cur_n);
        cudaGetSymbolAddress((void**)&p_csr_e, g_csr_e);
        cudaGetSymbolAddress((void**)&p_csr_n, g_csr_n);
        cudaGetSymbolAddress((void**)&p_bsum_e, g_bsum_e);
        cudaGetSymbolAddress((void**)&p_bsum_n, g_bsum_n);
        cudaGetSymbolAddress((void**)&p_maxbits, g_maxbits);
        cudaGetSymbolAddress((void**)&p_Apk, g_Apk);
        cudaGetSymbolAddress((void**)&p_Wpk, g_Wpk);
        cudaFuncSetAttribute(k_mma_gemm, cudaFuncAttributeMaxDynamicSharedMemorySize, SMEM_GEMM);

        void* fp = nullptr;
        cudaDriverEntryPointQueryResult qr;
        cudaGetDriverEntryPoint("cuTensorMapEncodeTiled", &fp, cudaEnableDefault, &qr);
        PFN_encodeTmap enc = (PFN_encodeTmap)fp;
        unsigned long long dimsA[3] = {128ull, (unsigned long long)N_EDGES, (unsigned long long)NCHUNK};
        unsigned long long strA[2]  = {128ull, 128ull * N_EDGES};
        unsigned long long dimsB[3] = {128ull, 256ull, (unsigned long long)NCHUNK};
        unsigned long long strB[2]  = {128ull, 128ull * 256ull};
        unsigned int box[3] = {128u, 128u, 1u};
        unsigned int est[3] = {1u, 1u, 1u};
        enc(&tmA, CU_TENSOR_MAP_DATA_TYPE_UINT8, 3, (void*)p_Apk, dimsA, strA, box, est,
            CU_TENSOR_MAP_INTERLEAVE_NONE, CU_TENSOR_MAP_SWIZZLE_128B,
            CU_TENSOR_MAP_L2_PROMOTION_L2_128B, CU_TENSOR_MAP_FLOAT_OOB_FILL_NONE);
        enc(&tmB, CU_TENSOR_MAP_DATA_TYPE_UINT8, 3, (void*)p_Wpk, dimsB, strB, box, est,
            CU_TENSOR_MAP_INTERLEAVE_NONE, CU_TENSOR_MAP_SWIZZLE_128B,
            CU_TENSOR_MAP_L2_PROMOTION_L2_128B, CU_TENSOR_MAP_FLOAT_OOB_FILL_NONE);
    }

    // ---- CSR build + x conversion ----
    k_zero_meta<<<400, 256>>>(p_deg_e, p_deg_n, p_cur_e, p_cur_n, p_maxbits, p_sumexp, out);
    k_count<<<(NNZ + 255) / 256, 256>>>(nidx, eidx, p_deg_n, p_deg_e);
    k_cvtX<<<N_NODES, 320>>>(x, p_xh);
    const int NBE = (N_EDGES + 1023) / 1024;
    const int NBN = (N_NODES + 1023) / 1024;
    k_scan_local<<<NBE, 1024>>>(p_deg_e, p_off_e, p_bsum_e, N_EDGES);
    k_scan_local<<<NBN, 1024>>>(p_deg_n, p_off_n, p_bsum_n, N_NODES);
    k_scan_carry<<<1, 32>>>(p_bsum_e, NBE, p_off_e + N_EDGES, p_bsum_n, NBN, p_off_n + N_NODES);
    k_scan_add<<<(N_EDGES + 255) / 256, 256>>>(p_off_e, p_bsum_e, p_deg_e, p_binv, N_EDGES);
    k_scan_add<<<(N_NODES + 255) / 256, 256>>>(p_off_n, p_bsum_n, p_deg_n, p_dinv, N_NODES);
    k_fill<<<(NNZ + 255) / 256, 256>>>(nidx, eidx, p_off_e, p_off_n, p_cur_e, p_cur_n, p_csr_e, p_csr_n);
    k_cdot<<<1, 128>>>(b3, aw, ab, p_cdot);

    const int EB = (N_EDGES * 32) / 256;    // 2500
    const int NB = (N_NODES * 32) / 256;    // 12500
    const int GM = (N_EDGES + 127) / 128;   // 157

    // ---- layer 1 ----
    k_packW<<<256, 320>>>(W1, 300, 256, p_Wpk);
    k_edge_pack320<<<EB, 256>>>(p_xh, p_off_e, p_csr_e, p_binv, p_Apk);
    k_mma_gemm<<<dim3(2, GM), 256, SMEM_GEMM>>>(tmA, tmB, p_xwE, N_EDGES, 256, 10);
    k_node_agg256<<<NB, 256>>>(p_xwE, p_off_n, p_csr_n, p_dinv, b1, p_h16);

    // ---- layer 2 ----
    k_packW<<<256, 320>>>(W2, 256, 256, p_Wpk);
    k_edge_pack256<<<EB, 256>>>(p_h16, p_off_e, p_csr_e, p_binv, p_Apk);
    k_mma_gemm<<<dim3(2, GM), 256, SMEM_GEMM>>>(tmA, tmB, p_xwE, N_EDGES, 256, 8);
    k_node_agg256<<<NB, 256>>>(p_xwE, p_off_n, p_csr_n, p_dinv, b2, p_h16b);

    // ---- layer 3: edge GEMM then algebraic pooling tail (h3 never materialized) ----
    k_packW<<<128, 320>>>(W3, 256, 128, p_Wpk);
    k_edge_pack256<<<EB, 256>>>(p_h16b, p_off_e, p_csr_e, p_binv, p_Apk);
    k_mma_gemm<<<dim3(1, GM), 256, SMEM_GEMM>>>(tmA, tmB, p_xwE, N_EDGES, 128, 8);
    k_edge_dot<<<EB, 256>>>(p_xwE, aw, p_t);
    k_logits_node<<<(N_NODES + 255) / 256, 256>>>(p_t, p_off_n, p_csr_n, p_dinv, p_cdot,
                                                  p_logits, p_maxbits);
    k_sumexp<<<512, 256>>>(p_logits, p_maxbits, p_sumexp);
    k_coef<<<(N_NODES + 255) / 256, 256>>>(p_logits, p_maxbits, p_dinv, p_c);
    k_edge_coef<<<EB, 256>>>(p_c, p_off_e, p_csr_e, p_s);
    k_final_sum<<<GM, 128>>>(p_xwE, p_s, out);
    k_finalize<<<1, 128>>>(out, p_sumexp, b3);
}

// round 10
// speedup vs baseline: 2.8115x; 1.0615x over previous
#include <cuda_runtime.h>
#include <cuda.h>
#include <cuda_bf16.h>
#include <cuda_fp16.h>
#include <math.h>
#include <stdint.h>

#define N_NODES 100000
#define N_EDGES 20000
#define NNZ     1600000
#define NCHUNK  5           // 5 chunks of 64 k => KPAD 320

// ---------------- scratch (static device globals; no allocation) ----------------
__device__ __align__(128) __half g_xh[(size_t)N_NODES * 320];    // x in fp16, padded
__device__ __align__(128) __half g_xwE[(size_t)N_EDGES * 256];   // edge GEMM output (fp16)
__device__ __align__(128) __half g_h16[(size_t)N_NODES * 256];   // layer output fp16 (ping)
__device__ __align__(128) __half g_h16b[(size_t)N_NODES * 256];  // layer output fp16 (pong)
__device__ float g_t[N_EDGES];
__device__ float g_s[N_EDGES];
__device__ float g_c[N_NODES];
__device__ float g_cdot;
// A packed bf16 (hi only), chunk-major: [chunk][row][64 bf16] = 128B rows
__device__ __align__(1024) __nv_bfloat16 g_Apk[(size_t)NCHUNK * N_EDGES * 64];
// W packed: per layer slice [chunk][512][64]: rows 0-255 = hi(n), rows 256-511 = lo(n)
#define WPK_SLICE ((size_t)NCHUNK * 512 * 64)
__device__ __align__(1024) __nv_bfloat16 g_Wpk[3 * WPK_SLICE];

__device__ int   g_deg_e[N_EDGES];
__device__ int   g_deg_n[N_NODES];
__device__ float g_binv[N_EDGES];
__device__ float g_dinv[N_NODES];
__device__ int   g_off_e[N_EDGES + 1];
__device__ int   g_off_n[N_NODES + 1];
__device__ int   g_cur_e[N_EDGES];
__device__ int   g_cur_n[N_NODES];
__device__ int   g_csr_e[NNZ];
__device__ int   g_csr_n[NNZ];
__device__ int   g_bsum_e[64];
__device__ int   g_bsum_n[128];

__device__ float        g_logits[N_NODES];
__device__ unsigned int g_maxbits;
__device__ float        g_sumexp;

// ---------------- PTX helpers ----------------
__device__ __forceinline__ uint32_t smem_u32(const void* p) {
    uint32_t a;
    asm("{ .reg .u64 t; cvta.to.shared.u64 t, %1; cvt.u32.u64 %0, t; }" : "=r"(a) : "l"(p));
    return a;
}
#define MBAR_INIT(a, cnt) asm volatile("mbarrier.init.shared.b64 [%0], %1;" :: "r"(a), "r"(cnt) : "memory")
#define MBAR_EXPECT_TX(a, b) asm volatile("mbarrier.arrive.expect_tx.shared.b64 _, [%0], %1;" :: "r"(a), "r"(b) : "memory")
#define MBAR_WAIT(a, par) do {                                             \
    uint32_t _m = (a); uint32_t _p = (par); uint32_t _d;                   \
    asm volatile("{\n .reg .pred p;\n"                                     \
        " mbarrier.try_wait.parity.acquire.cta.shared::cta.b64 p, [%1], %2;\n" \
        " selp.b32 %0,1,0,p;\n}" : "=r"(_d) : "r"(_m), "r"(_p) : "memory");\
    if (!_d) {                                                             \
        asm volatile("{\n .reg .pred P1;\n"                                \
        "W_%=:\n mbarrier.try_wait.parity.acquire.cta.shared::cta.b64 P1, [%0], %1, 0x989680;\n" \
        " @P1 bra.uni D_%=;\n bra.uni W_%=;\nD_%=:\n}"                     \
        :: "r"(_m), "r"(_p) : "memory");                                   \
    } } while (0)

__device__ __forceinline__ void tma3d(uint32_t dst, const void* tmap, int x, int y, int z, uint32_t mbar) {
    asm volatile(
        "cp.async.bulk.tensor.3d.shared::cta.global.tile.mbarrier::complete_tx::bytes "
        "[%0], [%1, {%2, %3, %4}], [%5];"
        :: "r"(dst), "l"(tmap), "r"(x), "r"(y), "r"(z), "r"(mbar) : "memory");
}
__device__ __forceinline__ void ldsm4(uint32_t* r, uint32_t addr) {
    asm volatile("ldmatrix.sync.aligned.m8n8.x4.shared.b16 {%0,%1,%2,%3}, [%4];"
        : "=r"(r[0]), "=r"(r[1]), "=r"(r[2]), "=r"(r[3]) : "r"(addr));
}
__device__ __forceinline__ void mma16816(float* d, const uint32_t* a, const uint32_t* b) {
    asm volatile("mma.sync.aligned.m16n8k16.row.col.f32.bf16.bf16.f32 "
        "{%0,%1,%2,%3}, {%4,%5,%6,%7}, {%8,%9}, {%0,%1,%2,%3};"
        : "+f"(d[0]), "+f"(d[1]), "+f"(d[2]), "+f"(d[3])
        : "r"(a[0]), "r"(a[1]), "r"(a[2]), "r"(a[3]), "r"(b[0]), "r"(b[1]));
}
__device__ __forceinline__ uint32_t swz(uint32_t base, int row, int byteCol) {
    return base + row * 128 + (byteCol ^ ((row & 7) << 4));
}

// ---------------- misc helpers ----------------
__device__ __forceinline__ unsigned int enc_f(float f) {
    unsigned int u = __float_as_uint(f);
    return (u & 0x80000000u) ? ~u : (u | 0x80000000u);
}
__device__ __forceinline__ float dec_f(unsigned int u) {
    u = (u & 0x80000000u) ? (u ^ 0x80000000u) : ~u;
    return __uint_as_float(u);
}
__device__ __forceinline__ void addh8(float* a, uint4 v) {
    const __half2* h = (const __half2*)&v;
    #pragma unroll
    for (int i = 0; i < 4; i++) {
        float2 f = __half22float2(h[i]);
        a[2 * i] += f.x;
        a[2 * i + 1] += f.y;
    }
}
// pack 4 floats (feature group v = feats 4v..4v+3) of edge-row e, bf16 hi-only,
// chunk = 64 k-values (16 groups) per 128B row
__device__ __forceinline__ void pack_write_hi(__nv_bfloat16* __restrict__ apk, int v, int e,
                                              float r0, float r1, float r2, float r3) {
    int chunk = v >> 4;
    int pos = (v & 15) * 4;
    size_t base = ((size_t)chunk * N_EDGES + e) * 64 + pos;
    *(__nv_bfloat162*)(apk + base)     = __halves2bfloat162(__float2bfloat16(r0), __float2bfloat16(r1));
    *(__nv_bfloat162*)(apk + base + 2) = __halves2bfloat162(__float2bfloat16(r2), __float2bfloat16(r3));
}

// ---------------- setup kernels ----------------
__global__ void k_zero_meta(int* deg_e, int* deg_n, int* cur_e, int* cur_n,
                            unsigned int* maxbits, float* sumexp, float* out) {
    int i = blockIdx.x * blockDim.x + threadIdx.x;
    int stride = gridDim.x * blockDim.x;
    for (int j = i; j < N_NODES; j += stride) {
        deg_n[j] = 0; cur_n[j] = 0;
        if (j < N_EDGES) { deg_e[j] = 0; cur_e[j] = 0; }
        if (j < 128) out[j] = 0.0f;
        if (j == 0) { *maxbits = 0u; *sumexp = 0.0f; }
    }
}

__global__ void k_count(const int* __restrict__ nidx, const int* __restrict__ eidx,
                        int* deg_n, int* deg_e) {
    int i = blockIdx.x * blockDim.x + threadIdx.x;
    if (i < NNZ) {
        atomicAdd(&deg_e[eidx[i]], 1);
        atomicAdd(&deg_n[nidx[i]], 1);
    }
}

__global__ void k_scan_local(const int* __restrict__ deg, int* __restrict__ off,
                             int* __restrict__ bsum, int n) {
    __shared__ int sh[1024];
    int i = blockIdx.x * 1024 + threadIdx.x;
    int v = (i < n) ? deg[i] : 0;
    sh[threadIdx.x] = v;
    __syncthreads();
    #pragma unroll
    for (int s = 1; s < 1024; s <<= 1) {
        int t = (threadIdx.x >= (unsigned)s) ? sh[threadIdx.x - s] : 0;
        __syncthreads();
        sh[threadIdx.x] += t;
        __syncthreads();
    }
    if (i < n) off[i] = sh[threadIdx.x] - v;
    if (threadIdx.x == 1023) bsum[blockIdx.x] = sh[1023];
}

__global__ void k_scan_carry(int* bsum_e, int nbe, int* tot_e,
                             int* bsum_n, int nbn, int* tot_n) {
    if (threadIdx.x == 0) {
        int s = 0;
        for (int i = 0; i < nbe; i++) { int v = bsum_e[i]; bsum_e[i] = s; s += v; }
        *tot_e = s;
    }
    if (threadIdx.x == 1) {
        int s = 0;
        for (int i = 0; i < nbn; i++) { int v = bsum_n[i]; bsum_n[i] = s; s += v; }
        *tot_n = s;
    }
}

__global__ void k_scan_add(int* __restrict__ off, const int* __restrict__ bsum,
                           const int* __restrict__ deg, float* __restrict__ inv, int n) {
    int i = blockIdx.x * blockDim.x + threadIdx.x;
    if (i < n) {
        off[i] += bsum[i >> 10];
        int d = deg[i];
        inv[i] = (d > 0) ? (1.0f / (float)d) : 0.0f;
    }
}

__global__ void k_fill(const int* __restrict__ nidx, const int* __restrict__ eidx,
                       const int* __restrict__ off_e, const int* __restrict__ off_n,
                       int* cur_e, int* cur_n, int* csr_e, int* csr_n) {
    int i = blockIdx.x * blockDim.x + threadIdx.x;
    if (i < NNZ) {
        int e = eidx[i], n = nidx[i];
        int p = atomicAdd(&cur_e[e], 1);
        csr_e[off_e[e] + p] = n;
        int q = atomicAdd(&cur_n[n], 1);
        csr_n[off_n[n] + q] = e;
    }
}

// x [N_NODES,300] fp32 -> g_xh [N_NODES,320] fp16 (zero padded)
__global__ void k_cvtX(const float* __restrict__ x, __half* __restrict__ xh) {
    int m = blockIdx.x;
    int k = threadIdx.x;   // 320
    float v = (k < 300) ? x[(size_t)m * 300 + k] : 0.0f;
    xh[(size_t)m * 320 + k] = __float2half_rn(v);
}

// W [K][N] fp32 -> slice: hi at [chunk][n][k&63], lo at [chunk][256+n][k&63]
__global__ void k_packW(const float* __restrict__ W, int K, int N, __nv_bfloat16* __restrict__ wpk) {
    int n = blockIdx.x;
    int k = threadIdx.x;   // 320 threads
    float a = (k < K) ? W[(size_t)k * N + n] : 0.0f;
    __nv_bfloat16 h = __float2bfloat16(a);
    float r = a - __bfloat162float(h);
    int chunk = k >> 6;
    int kk = k & 63;
    wpk[((size_t)chunk * 512 + n) * 64 + kk] = h;
    wpk[((size_t)chunk * 512 + 256 + n) * 64 + kk] = __float2bfloat16(r);
}

// ---------------- edge gather (fp16 source) + fused bf16 hi pack ----------------
__global__ void k_edge_pack320(const __half* __restrict__ xh,
                               const int* __restrict__ off_e, const int* __restrict__ csr_e,
                               const float* __restrict__ binv, __nv_bfloat16* __restrict__ apk) {
    int w = (blockIdx.x * blockDim.x + threadIdx.x) >> 5;
    if (w >= N_EDGES) return;
    int lane = threadIdx.x & 31;
    float a[8] = {0, 0, 0, 0, 0, 0, 0, 0};
    float b[8] = {0, 0, 0, 0, 0, 0, 0, 0};
    bool hasB = lane < 8;
    int beg = off_e[w], end = off_e[w + 1];
    int m = beg;
    for (; m + 3 < end; m += 4) {
        int n0 = csr_e[m], n1 = csr_e[m + 1], n2 = csr_e[m + 2], n3 = csr_e[m + 3];
        const uint4* r0 = (const uint4*)(xh + (size_t)n0 * 320);
        const uint4* r1 = (const uint4*)(xh + (size_t)n1 * 320);
        const uint4* r2 = (const uint4*)(xh + (size_t)n2 * 320);
        const uint4* r3 = (const uint4*)(xh + (size_t)n3 * 320);
        addh8(a, r0[lane]); addh8(a, r1[lane]); addh8(a, r2[lane]); addh8(a, r3[lane]);
        if (hasB) {
            addh8(b, r0[lane + 32]); addh8(b, r1[lane + 32]);
            addh8(b, r2[lane + 32]); addh8(b, r3[lane + 32]);
        }
    }
    for (; m < end; m++) {
        const uint4* r0 = (const uint4*)(xh + (size_t)csr_e[m] * 320);
        addh8(a, r0[lane]);
        if (hasB) addh8(b, r0[lane + 32]);
    }
    float bi = binv[w];
    #pragma unroll
    for (int i = 0; i < 8; i++) { a[i] *= bi; b[i] *= bi; }
    pack_write_hi(apk, 2 * lane, w, a[0], a[1], a[2], a[3]);
    pack_write_hi(apk, 2 * lane + 1, w, a[4], a[5], a[6], a[7]);
    if (hasB) {
        pack_write_hi(apk, 64 + 2 * lane, w, b[0], b[1], b[2], b[3]);
        pack_write_hi(apk, 64 + 2 * lane + 1, w, b[4], b[5], b[6], b[7]);
    }
}

__global__ void k_edge_pack256(const __half* __restrict__ h,
                               const int* __restrict__ off_e, const int* __restrict__ csr_e,
                               const float* __restrict__ binv, __nv_bfloat16* __restrict__ apk) {
    int w = (blockIdx.x * blockDim.x + threadIdx.x) >> 5;
    if (w >= N_EDGES) return;
    int lane = threadIdx.x & 31;
    float a[8] = {0, 0, 0, 0, 0, 0, 0, 0};
    int beg = off_e[w], end = off_e[w + 1];
    int m = beg;
    for (; m + 3 < end; m += 4) {
        int n0 = csr_e[m], n1 = csr_e[m + 1], n2 = csr_e[m + 2], n3 = csr_e[m + 3];
        addh8(a, ((const uint4*)(h + (size_t)n0 * 256))[lane]);
        addh8(a, ((const uint4*)(h + (size_t)n1 * 256))[lane]);
        addh8(a, ((const uint4*)(h + (size_t)n2 * 256))[lane]);
        addh8(a, ((const uint4*)(h + (size_t)n3 * 256))[lane]);
    }
    for (; m < end; m++)
        addh8(a, ((const uint4*)(h + (size_t)csr_e[m] * 256))[lane]);
    float bi = binv[w];
    #pragma unroll
    for (int i = 0; i < 8; i++) a[i] *= bi;
    pack_write_hi(apk, 2 * lane, w, a[0], a[1], a[2], a[3]);
    pack_write_hi(apk, 2 * lane + 1, w, a[4], a[5], a[6], a[7]);
}

// ---------------- TMA + mma.sync GEMM: A bf16, W = Whi + Wlo; fp16 out ----------------
// 64-k chunks. Stage = A(16K) + Bhi(16K) + Blo(16K) = 48K.
#define STAGE_B 49152
#define N_STAGE 4
#define MB_OFF  (N_STAGE * STAGE_B)
#define SMEM_GEMM (MB_OFF + 64)

__global__ __launch_bounds__(256, 1) void k_mma_gemm(
    const __grid_constant__ CUtensorMap tmA,
    const __grid_constant__ CUtensorMap tmB,
    __half* __restrict__ C, int M, int Ncols, int chunks) {
    extern __shared__ char smem[];
    uint32_t sb = smem_u32(smem);
    int tid = threadIdx.x;
    int lane = tid & 31;
    int wid = tid >> 5;
    int wm = wid >> 2;
    int wn = wid & 3;
    int mBase = blockIdx.y * 128;
    int nBase = blockIdx.x * 128;

    if (tid == 0) {
        #pragma unroll
        for (int s = 0; s < N_STAGE; s++) MBAR_INIT(sb + MB_OFF + s * 8, 1);
    }
    __syncthreads();
    if (tid == 0) {
        #pragma unroll
        for (int s = 0; s < N_STAGE; s++) {
            if (s < chunks) {
                MBAR_EXPECT_TX(sb + MB_OFF + s * 8, STAGE_B);
                tma3d(sb + s * STAGE_B, &tmA, 0, mBase, s, sb + MB_OFF + s * 8);
                tma3d(sb + s * STAGE_B + 16384, &tmB, 0, nBase, s, sb + MB_OFF + s * 8);
                tma3d(sb + s * STAGE_B + 32768, &tmB, 0, nBase + 256, s, sb + MB_OFF + s * 8);
            }
        }
    }

    int a_row = lane & 15;
    int a_byte = (lane >> 4) << 4;
    int b_row = ((lane & 16) >> 1) + (lane & 7);
    int b_byte = (lane & 8) * 2;

    float acc[4][4][4];
    #pragma unroll
    for (int i = 0; i < 4; i++)
        #pragma unroll
        for (int j = 0; j < 4; j++)
            #pragma unroll
            for (int q = 0; q < 4; q++) acc[i][j][q] = 0.0f;

    for (int c = 0; c < chunks; c++) {
        int st = c & (N_STAGE - 1);
        MBAR_WAIT(sb + MB_OFF + st * 8, (c >> 2) & 1);
        uint32_t sA = sb + st * STAGE_B;
        uint32_t sBh = sA + 16384;
        uint32_t sBl = sA + 32768;
        #pragma unroll
        for (int ks = 0; ks < 4; ks++) {
            int kb = ks * 32;
            uint32_t ah[4][4], bh[2][4], bl[2][4];
            #pragma unroll
            for (int i = 0; i < 4; i++) {
                int r = wm * 64 + i * 16 + a_row;
                ldsm4(ah[i], swz(sA, r, kb + a_byte));
            }
            #pragma unroll
            for (int jj = 0; jj < 2; jj++) {
                int r = wn * 32 + jj * 16 + b_row;
                ldsm4(bh[jj], swz(sBh, r, kb + b_byte));
                ldsm4(bl[jj], swz(sBl, r, kb + b_byte));
            }
            #pragma unroll
            for (int i = 0; i < 4; i++)
                #pragma unroll
                for (int j = 0; j < 4; j++) {
                    const uint32_t* bH = &bh[j >> 1][(j & 1) * 2];
                    const uint32_t* bL = &bl[j >> 1][(j & 1) * 2];
                    mma16816(acc[i][j], ah[i], bH);
                    mma16816(acc[i][j], ah[i], bL);
                }
        }
        __syncthreads();
        if (tid == 0 && c + N_STAGE < chunks) {
            MBAR_EXPECT_TX(sb + MB_OFF + st * 8, STAGE_B);
            tma3d(sb + st * STAGE_B, &tmA, 0, mBase, c + N_STAGE, sb + MB_OFF + st * 8);
            tma3d(sb + st * STAGE_B + 16384, &tmB, 0, nBase, c + N_STAGE, sb + MB_OFF + st * 8);
            tma3d(sb + st * STAGE_B + 32768, &tmB, 0, nBase + 256, c + N_STAGE, sb + MB_OFF + st * 8);
        }
    }

    #pragma unroll
    for (int i = 0; i < 4; i++) {
        int r0 = mBase + wm * 64 + i * 16 + (lane >> 2);
        #pragma unroll
        for (int j = 0; j < 4; j++) {
            int cc = nBase + wn * 32 + j * 8 + (lane & 3) * 2;
            if (r0 < M)
                *(__half2*)&C[(size_t)r0 * Ncols + cc] =
                    __floats2half2_rn(acc[i][j][0], acc[i][j][1]);
            if (r0 + 8 < M)
                *(__half2*)&C[(size_t)(r0 + 8) * Ncols + cc] =
                    __floats2half2_rn(acc[i][j][2], acc[i][j][3]);
        }
    }
}

// ---------------- node gather (fp16 edge GEMM output) -> fp16 h ----------------
__global__ void k_node_agg256(const __half* __restrict__ xwE,
                              const int* __restrict__ off_n, const int* __restrict__ csr_n,
                              const float* __restrict__ dinv, const float* __restrict__ bias,
                              __half* __restrict__ dst) {
    int w = (blockIdx.x * blockDim.x + threadIdx.x) >> 5;
    if (w >= N_NODES) return;
    int lane = threadIdx.x & 31;
    float a[8] = {0, 0, 0, 0, 0, 0, 0, 0};
    int beg = off_n[w], end = off_n[w + 1];
    int m = beg;
    for (; m + 3 < end; m += 4) {
        int e0 = csr_n[m], e1 = csr_n[m + 1], e2 = csr_n[m + 2], e3 = csr_n[m + 3];
        addh8(a, ((const uint4*)(xwE + (size_t)e0 * 256))[lane]);
        addh8(a, ((const uint4*)(xwE + (size_t)e1 * 256))[lane]);
        addh8(a, ((const uint4*)(xwE + (size_t)e2 * 256))[lane]);
        addh8(a, ((const uint4*)(xwE + (size_t)e3 * 256))[lane]);
    }
    for (; m < end; m++)
        addh8(a, ((const uint4*)(xwE + (size_t)csr_n[m] * 256))[lane]);
    float di = dinv[w];
    float4 b0 = ((const float4*)bias)[2 * lane];
    float4 b1 = ((const float4*)bias)[2 * lane + 1];
    float r[8];
    r[0] = a[0] * di + b0.x; r[1] = a[1] * di + b0.y;
    r[2] = a[2] * di + b0.z; r[3] = a[3] * di + b0.w;
    r[4] = a[4] * di + b1.x; r[5] = a[5] * di + b1.y;
    r[6] = a[6] * di + b1.z; r[7] = a[7] * di + b1.w;
    #pragma unroll
    for (int i = 0; i < 8; i++) r[i] = r[i] > 0.f ? r[i] : 0.01f * r[i];
    __half2 o[4];
    #pragma unroll
    for (int i = 0; i < 4; i++) o[i] = __floats2half2_rn(r[2 * i], r[2 * i + 1]);
    ((uint4*)(dst + (size_t)w * 256))[lane] = *(const uint4*)o;
}

// ---------------- final-layer algebraic tail ----------------
__global__ void k_cdot(const float* __restrict__ b3, const float* __restrict__ aw,
                       const float* __restrict__ ab, float* __restrict__ cdot) {
    int f = threadIdx.x;   // 128
    float v = b3[f] * aw[f];
    #pragma unroll
    for (int o = 16; o; o >>= 1) v += __shfl_xor_sync(0xffffffffu, v, o);
    __shared__ float sm[4];
    if ((f & 31) == 0) sm[f >> 5] = v;
    __syncthreads();
    if (f == 0) *cdot = sm[0] + sm[1] + sm[2] + sm[3] + ab[0];
}

__global__ void k_edge_dot(const __half* __restrict__ xwE, const float* __restrict__ aw,
                           float* __restrict__ t) {
    int e = (blockIdx.x * blockDim.x + threadIdx.x) >> 5;
    if (e >= N_EDGES) return;
    int lane = threadIdx.x & 31;
    uint2 v = ((const uint2*)(xwE + (size_t)e * 128))[lane];
    const __half2* h = (const __half2*)&v;
    float2 f0 = __half22float2(h[0]);
    float2 f1 = __half22float2(h[1]);
    float4 wv = ((const float4*)aw)[lane];
    float d = f0.x * wv.x + f0.y * wv.y + f1.x * wv.z + f1.y * wv.w;
    #pragma unroll
    for (int o = 16; o; o >>= 1) d += __shfl_xor_sync(0xffffffffu, d, o);
    if (lane == 0) t[e] = d;
}

__global__ void k_logits_node(const float* __restrict__ t,
                              const int* __restrict__ off_n, const int* __restrict__ csr_n,
                              const float* __restrict__ dinv, const float* __restrict__ cdot,
                              float* __restrict__ logits, unsigned int* maxbits) {
    int n = blockIdx.x * blockDim.x + threadIdx.x;
    float lg = -3.4e38f;
    if (n < N_NODES) {
        float s = 0.f;
        int beg = off_n[n], end = off_n[n + 1];
        for (int m = beg; m < end; m++) s += t[csr_n[m]];
        lg = dinv[n] * s + *cdot;
        logits[n] = lg;
    }
    #pragma unroll
    for (int o = 16; o; o >>= 1) lg = fmaxf(lg, __shfl_xor_sync(0xffffffffu, lg, o));
    __shared__ float sm[8];
    if ((threadIdx.x & 31) == 0) sm[threadIdx.x >> 5] = lg;
    __syncthreads();
    if (threadIdx.x < 8) {
        float mv = sm[threadIdx.x];
        #pragma unroll
        for (int o = 4; o; o >>= 1) mv = fmaxf(mv, __shfl_xor_sync(0xffu, mv, o));
        if (threadIdx.x == 0) atomicMax(maxbits, enc_f(mv));
    }
}

__global__ void k_sumexp(const float* __restrict__ logits, const unsigned int* __restrict__ maxbits,
                         float* sumexp) {
    float mx = dec_f(*maxbits);
    int i = blockIdx.x * blockDim.x + threadIdx.x;
    int stride = gridDim.x * blockDim.x;
    float s = 0.f;
    for (int j = i; j < N_NODES; j += stride) s += expf(logits[j] - mx);
    #pragma unroll
    for (int o = 16; o; o >>= 1) s += __shfl_xor_sync(0xffffffffu, s, o);
    __shared__ float sm[8];
    if ((threadIdx.x & 31) == 0) sm[threadIdx.x >> 5] = s;
    __syncthreads();
    if (threadIdx.x < 8) {
        float tt = sm[threadIdx.x];
        #pragma unroll
        for (int o = 4; o; o >>= 1) tt += __shfl_xor_sync(0xffu, tt, o);
        if (threadIdx.x == 0) atomicAdd(sumexp, tt);
    }
}

__global__ void k_coef(const float* __restrict__ logits, const unsigned int* __restrict__ maxbits,
                       const float* __restrict__ dinv, float* __restrict__ c) {
    int n = blockIdx.x * blockDim.x + threadIdx.x;
    if (n < N_NODES) {
        float mx = dec_f(*maxbits);
        c[n] = expf(logits[n] - mx) * dinv[n];
    }
}

__global__ void k_edge_coef(const float* __restrict__ c,
                            const int* __restrict__ off_e, const int* __restrict__ csr_e,
                            float* __restrict__ s) {
    int e = (blockIdx.x * blockDim.x + threadIdx.x) >> 5;
    if (e >= N_EDGES) return;
    int lane = threadIdx.x & 31;
    float acc = 0.f;
    int beg = off_e[e], end = off_e[e + 1];
    for (int m = beg + lane; m < end; m += 32) acc += c[csr_e[m]];
    #pragma unroll
    for (int o = 16; o; o >>= 1) acc += __shfl_xor_sync(0xffffffffu, acc, o);
    if (lane == 0) s[e] = acc;
}

__global__ void k_final_sum(const __half* __restrict__ xwE, const float* __restrict__ s,
                            float* __restrict__ out) {
    int f = threadIdx.x;   // 128
    int e0 = blockIdx.x * 128;
    int e1 = min(e0 + 128, N_EDGES);
    float acc = 0.f;
    for (int e = e0; e < e1; e++)
        acc += s[e] * __half2float(xwE[(size_t)e * 128 + f]);
    atomicAdd(&out[f], acc);
}

__global__ void k_finalize(float* __restrict__ out, const float* __restrict__ sumexp,
                           const float* __restrict__ b3) {
    int f = threadIdx.x;
    out[f] = out[f] / (*sumexp) + b3[f];
}

// ---------------- host-side tensormap plumbing ----------------
typedef CUresult (*PFN_encodeTmap)(
    CUtensorMap*, CUtensorMapDataType, unsigned int, void*,
    const unsigned long long*, const unsigned long long*,
    const unsigned int*, const unsigned int*,
    CUtensorMapInterleave, CUtensorMapSwizzle, CUtensorMapL2promotion, CUtensorMapFloatOOBfill);

// ---------------- launch ----------------
extern "C" void kernel_launch(void* const* d_in, const int* in_sizes, int n_in,
                              void* d_out, int out_size) {
    const float* x   = (const float*)d_in[0];
    const int*   hei = (const int*)d_in[1];
    const int*   nidx = hei;
    const int*   eidx = hei + NNZ;
    const float* W1 = (const float*)d_in[2];
    const float* b1 = (const float*)d_in[3];
    const float* W2 = (const float*)d_in[4];
    const float* b2 = (const float*)d_in[5];
    const float* W3 = (const float*)d_in[6];
    const float* b3 = (const float*)d_in[7];
    const float* aw = (const float*)d_in[8];
    const float* ab = (const float*)d_in[9];
    float* out = (float*)d_out;

    static __half *p_xh = nullptr, *p_xwE, *p_h16, *p_h16b;
    static float *p_t, *p_s, *p_c, *p_cdot;
    static float *p_binv, *p_dinv, *p_logits, *p_sumexp;
    static int *p_deg_e, *p_deg_n, *p_off_e, *p_off_n, *p_cur_e, *p_cur_n, *p_csr_e, *p_csr_n;
    static int *p_bsum_e, *p_bsum_n;
    static unsigned int* p_maxbits;
    static __nv_bfloat16 *p_Apk, *p_Wpk;
    static CUtensorMap tmA, tmB1, tmB2, tmB3;
    static cudaStream_t s1;
    static cudaEvent_t evFork, evJoin;
    if (!p_xh) {
        cudaGetSymbolAddress((void**)&p_xh, g_xh);
        cudaGetSymbolAddress((void**)&p_xwE, g_xwE);
        cudaGetSymbolAddress((void**)&p_h16, g_h16);
        cudaGetSymbolAddress((void**)&p_h16b, g_h16b);
        cudaGetSymbolAddress((void**)&p_t, g_t);
        cudaGetSymbolAddress((void**)&p_s, g_s);
        cudaGetSymbolAddress((void**)&p_c, g_c);
        cudaGetSymbolAddress((void**)&p_cdot, g_cdot);
        cudaGetSymbolAddress((void**)&p_binv, g_binv);
        cudaGetSymbolAddress((void**)&p_dinv, g_dinv);
        cudaGetSymbolAddress((void**)&p_logits, g_logits);
        cudaGetSymbolAddress((void**)&p_sumexp, g_sumexp);
        cudaGetSymbolAddress((void**)&p_deg_e, g_deg_e);
        cudaGetSymbolAddress((void**)&p_deg_n, g_deg_n);
        cudaGetSymbolAddress((void**)&p_off_e, g_off_e);
        cudaGetSymbolAddress((void**)&p_off_n, g_off_n);
        cudaGetSymbolAddress((void**)&p_cur_e, g_cur_e);
        cudaGetSymbolAddress((void**)&p_cur_n, g_cur_n);
        cudaGetSymbolAddress((void**)&p_csr_e, g_csr_e);
        cudaGetSymbolAddress((void**)&p_csr_n, g_csr_n);
        cudaGetSymbolAddress((void**)&p_bsum_e, g_bsum_e);
        cudaGetSymbolAddress((void**)&p_bsum_n, g_bsum_n);
        cudaGetSymbolAddress((void**)&p_maxbits, g_maxbits);
        cudaGetSymbolAddress((void**)&p_Apk, g_Apk);
        cudaGetSymbolAddress((void**)&p_Wpk, g_Wpk);
        cudaFuncSetAttribute(k_mma_gemm, cudaFuncAttributeMaxDynamicSharedMemorySize, SMEM_GEMM);
        cudaStreamCreateWithFlags(&s1, cudaStreamNonBlocking);
        cudaEventCreateWithFlags(&evFork, cudaEventDisableTiming);
        cudaEventCreateWithFlags(&evJoin, cudaEventDisableTiming);

        void* fp = nullptr;
        cudaDriverEntryPointQueryResult qr;
        cudaGetDriverEntryPoint("cuTensorMapEncodeTiled", &fp, cudaEnableDefault, &qr);
        PFN_encodeTmap enc = (PFN_encodeTmap)fp;
        unsigned long long dimsA[3] = {128ull, (unsigned long long)N_EDGES, (unsigned long long)NCHUNK};
        unsigned long long strA[2]  = {128ull, 128ull * N_EDGES};
        unsigned long long dimsB[3] = {128ull, 512ull, (unsigned long long)NCHUNK};
        unsigned long long strB[2]  = {128ull, 128ull * 512ull};
        unsigned int box[3] = {128u, 128u, 1u};
        unsigned int est[3] = {1u, 1u, 1u};
        enc(&tmA, CU_TENSOR_MAP_DATA_TYPE_UINT8, 3, (void*)p_Apk, dimsA, strA, box, est,
            CU_TENSOR_MAP_INTERLEAVE_NONE, CU_TENSOR_MAP_SWIZZLE_128B,
            CU_TENSOR_MAP_L2_PROMOTION_L2_128B, CU_TENSOR_MAP_FLOAT_OOB_FILL_NONE);
        enc(&tmB1, CU_TENSOR_MAP_DATA_TYPE_UINT8, 3, (void*)(p_Wpk), dimsB, strB, box, est,
            CU_TENSOR_MAP_INTERLEAVE_NONE, CU_TENSOR_MAP_SWIZZLE_128B,
            CU_TENSOR_MAP_L2_PROMOTION_L2_128B, CU_TENSOR_MAP_FLOAT_OOB_FILL_NONE);
        enc(&tmB2, CU_TENSOR_MAP_DATA_TYPE_UINT8, 3, (void*)(p_Wpk + WPK_SLICE), dimsB, strB, box, est,
            CU_TENSOR_MAP_INTERLEAVE_NONE, CU_TENSOR_MAP_SWIZZLE_128B,
            CU_TENSOR_MAP_L2_PROMOTION_L2_128B, CU_TENSOR_MAP_FLOAT_OOB_FILL_NONE);
        enc(&tmB3, CU_TENSOR_MAP_DATA_TYPE_UINT8, 3, (void*)(p_Wpk + 2 * WPK_SLICE), dimsB, strB, box, est,
            CU_TENSOR_MAP_INTERLEAVE_NONE, CU_TENSOR_MAP_SWIZZLE_128B,
            CU_TENSOR_MAP_L2_PROMOTION_L2_128B, CU_TENSOR_MAP_FLOAT_OOB_FILL_NONE);
    }

    // ---- fork: independent conversions on s1, CSR chain on stream 0 ----
    cudaEventRecord(evFork, 0);
    cudaStreamWaitEvent(s1, evFork, 0);
    k_cvtX<<<N_NODES, 320, 0, s1>>>(x, p_xh);
    k_packW<<<256, 320, 0, s1>>>(W1, 300, 256, p_Wpk);
    k_packW<<<256, 320, 0, s1>>>(W2, 256, 256, p_Wpk + WPK_SLICE);
    k_packW<<<128, 320, 0, s1>>>(W3, 256, 128, p_Wpk + 2 * WPK_SLICE);
    k_cdot<<<1, 128, 0, s1>>>(b3, aw, ab, p_cdot);

    k_zero_meta<<<400, 256>>>(p_deg_e, p_deg_n, p_cur_e, p_cur_n, p_maxbits, p_sumexp, out);
    k_count<<<(NNZ + 255) / 256, 256>>>(nidx, eidx, p_deg_n, p_deg_e);
    const int NBE = (N_EDGES + 1023) / 1024;
    const int NBN = (N_NODES + 1023) / 1024;
    k_scan_local<<<NBE, 1024>>>(p_deg_e, p_off_e, p_bsum_e, N_EDGES);
    k_scan_local<<<NBN, 1024>>>(p_deg_n, p_off_n, p_bsum_n, N_NODES);
    k_scan_carry<<<1, 32>>>(p_bsum_e, NBE, p_off_e + N_EDGES, p_bsum_n, NBN, p_off_n + N_NODES);
    k_scan_add<<<(N_EDGES + 255) / 256, 256>>>(p_off_e, p_bsum_e, p_deg_e, p_binv, N_EDGES);
    k_scan_add<<<(N_NODES + 255) / 256, 256>>>(p_off_n, p_bsum_n, p_deg_n, p_dinv, N_NODES);
    k_fill<<<(NNZ + 255) / 256, 256>>>(nidx, eidx, p_off_e, p_off_n, p_cur_e, p_cur_n, p_csr_e, p_csr_n);

    // ---- join ----
    cudaEventRecord(evJoin, s1);
    cudaStreamWaitEvent(0, evJoin, 0);

    const int EB = (N_EDGES * 32) / 256;    // 2500
    const int NB = (N_NODES * 32) / 256;    // 12500
    const int GM = (N_EDGES + 127) / 128;   // 157

    // ---- layer 1 ----
    k_edge_pack320<<<EB, 256>>>(p_xh, p_off_e, p_csr_e, p_binv, p_Apk);
    k_mma_gemm<<<dim3(2, GM), 256, SMEM_GEMM>>>(tmA, tmB1, p_xwE, N_EDGES, 256, 5);
    k_node_agg256<<<NB, 256>>>(p_xwE, p_off_n, p_csr_n, p_dinv, b1, p_h16);

    // ---- layer 2 ----
    k_edge_pack256<<<EB, 256>>>(p_h16, p_off_e, p_csr_e, p_binv, p_Apk);
    k_mma_gemm<<<dim3(2, GM), 256, SMEM_GEMM>>>(tmA, tmB2, p_xwE, N_EDGES, 256, 4);
    k_node_agg256<<<NB, 256>>>(p_xwE, p_off_n, p_csr_n, p_dinv, b2, p_h16b);

    // ---- layer 3: edge GEMM then algebraic pooling tail ----
    k_edge_pack256<<<EB, 256>>>(p_h16b, p_off_e, p_csr_e, p_binv, p_Apk);
    k_mma_gemm<<<dim3(1, GM), 256, SMEM_GEMM>>>(tmA, tmB3, p_xwE, N_EDGES, 128, 4);
    k_edge_dot<<<EB, 256>>>(p_xwE, aw, p_t);
    k_logits_node<<<(N_NODES + 255) / 256, 256>>>(p_t, p_off_n, p_csr_n, p_dinv, p_cdot,
                                                  p_logits, p_maxbits);
    k_sumexp<<<512, 256>>>(p_logits, p_maxbits, p_sumexp);
    k_coef<<<(N_NODES + 255) / 256, 256>>>(p_logits, p_maxbits, p_dinv, p_c);
    k_edge_coef<<<EB, 256>>>(p_c, p_off_e, p_csr_e, p_s);
    k_final_sum<<<GM, 128>>>(p_xwE, p_s, out);
    k_finalize<<<1, 128>>>(out, p_sumexp, b3);
}

// round 11
// speedup vs baseline: 2.8483x; 1.0131x over previous
#include <cuda_runtime.h>
#include <cuda.h>
#include <cuda_bf16.h>
#include <cuda_fp16.h>
#include <math.h>
#include <stdint.h>

#define N_NODES 100000
#define N_EDGES 20000
#define NNZ     1600000
#define NCHUNK  5           // 5 chunks of 64 k => KPAD 320

// ---------------- scratch (static device globals; no allocation) ----------------
__device__ __align__(128) __half g_xh[(size_t)N_NODES * 320];    // x in fp16, padded
__device__ __align__(128) __half g_xwE[(size_t)N_EDGES * 256];   // edge GEMM output (fp16)
__device__ __align__(128) __half g_h16[(size_t)N_NODES * 256];   // layer output fp16 (ping)
__device__ __align__(128) __half g_h16b[(size_t)N_NODES * 256];  // layer output fp16 (pong)
__device__ float g_t[N_EDGES];
__device__ float g_s[N_EDGES];
__device__ float g_c[N_NODES];
__device__ float g_cdot;
// A packed bf16 (hi only), chunk-major: [chunk][row][64 bf16] = 128B rows
__device__ __align__(1024) __nv_bfloat16 g_Apk[(size_t)NCHUNK * N_EDGES * 64];
// W packed: per layer slice [chunk][512][64]: rows 0-255 = hi(n), rows 256-511 = lo(n)
#define WPK_SLICE ((size_t)NCHUNK * 512 * 64)
__device__ __align__(1024) __nv_bfloat16 g_Wpk[3 * WPK_SLICE];

__device__ int   g_deg_e[N_EDGES];
__device__ int   g_deg_n[N_NODES];
__device__ float g_binv[N_EDGES];
__device__ float g_dinv[N_NODES];
__device__ int   g_off_e[N_EDGES + 1];
__device__ int   g_off_n[N_NODES + 1];
__device__ int   g_cur_e[N_EDGES];
__device__ int   g_cur_n[N_NODES];
__device__ int   g_csr_e[NNZ];
__device__ int   g_csr_n[NNZ];
__device__ int   g_bsum_e[64];
__device__ int   g_bsum_n[128];

__device__ float        g_logits[N_NODES];
__device__ unsigned int g_maxbits;
__device__ float        g_sumexp;

// ---------------- PTX helpers ----------------
__device__ __forceinline__ uint32_t smem_u32(const void* p) {
    uint32_t a;
    asm("{ .reg .u64 t; cvta.to.shared.u64 t, %1; cvt.u32.u64 %0, t; }" : "=r"(a) : "l"(p));
    return a;
}
#define MBAR_INIT(a, cnt) asm volatile("mbarrier.init.shared.b64 [%0], %1;" :: "r"(a), "r"(cnt) : "memory")
#define MBAR_EXPECT_TX(a, b) asm volatile("mbarrier.arrive.expect_tx.shared.b64 _, [%0], %1;" :: "r"(a), "r"(b) : "memory")
#define MBAR_WAIT(a, par) do {                                             \
    uint32_t _m = (a); uint32_t _p = (par); uint32_t _d;                   \
    asm volatile("{\n .reg .pred p;\n"                                     \
        " mbarrier.try_wait.parity.acquire.cta.shared::cta.b64 p, [%1], %2;\n" \
        " selp.b32 %0,1,0,p;\n}" : "=r"(_d) : "r"(_m), "r"(_p) : "memory");\
    if (!_d) {                                                             \
        asm volatile("{\n .reg .pred P1;\n"                                \
        "W_%=:\n mbarrier.try_wait.parity.acquire.cta.shared::cta.b64 P1, [%0], %1, 0x989680;\n" \
        " @P1 bra.uni D_%=;\n bra.uni W_%=;\nD_%=:\n}"                     \
        :: "r"(_m), "r"(_p) : "memory");                                   \
    } } while (0)

__device__ __forceinline__ void tma3d(uint32_t dst, const void* tmap, int x, int y, int z, uint32_t mbar) {
    asm volatile(
        "cp.async.bulk.tensor.3d.shared::cta.global.tile.mbarrier::complete_tx::bytes "
        "[%0], [%1, {%2, %3, %4}], [%5];"
        :: "r"(dst), "l"(tmap), "r"(x), "r"(y), "r"(z), "r"(mbar) : "memory");
}
__device__ __forceinline__ void ldsm4(uint32_t* r, uint32_t addr) {
    asm volatile("ldmatrix.sync.aligned.m8n8.x4.shared.b16 {%0,%1,%2,%3}, [%4];"
        : "=r"(r[0]), "=r"(r[1]), "=r"(r[2]), "=r"(r[3]) : "r"(addr));
}
__device__ __forceinline__ void mma16816(float* d, const uint32_t* a, const uint32_t* b) {
    asm volatile("mma.sync.aligned.m16n8k16.row.col.f32.bf16.bf16.f32 "
        "{%0,%1,%2,%3}, {%4,%5,%6,%7}, {%8,%9}, {%0,%1,%2,%3};"
        : "+f"(d[0]), "+f"(d[1]), "+f"(d[2]), "+f"(d[3])
        : "r"(a[0]), "r"(a[1]), "r"(a[2]), "r"(a[3]), "r"(b[0]), "r"(b[1]));
}
__device__ __forceinline__ uint32_t swz(uint32_t base, int row, int byteCol) {
    return base + row * 128 + (byteCol ^ ((row & 7) << 4));
}

// ---------------- misc helpers ----------------
__device__ __forceinline__ unsigned int enc_f(float f) {
    unsigned int u = __float_as_uint(f);
    return (u & 0x80000000u) ? ~u : (u | 0x80000000u);
}
__device__ __forceinline__ float dec_f(unsigned int u) {
    u = (u & 0x80000000u) ? (u ^ 0x80000000u) : ~u;
    return __uint_as_float(u);
}
__device__ __forceinline__ void addh8(float* a, uint4 v) {
    const __half2* h = (const __half2*)&v;
    #pragma unroll
    for (int i = 0; i < 4; i++) {
        float2 f = __half22float2(h[i]);
        a[2 * i] += f.x;
        a[2 * i + 1] += f.y;
    }
}
// pack 4 floats (feature group v = feats 4v..4v+3) of edge-row e, bf16 hi-only,
// chunk = 64 k-values (16 groups) per 128B row
__device__ __forceinline__ void pack_write_hi(__nv_bfloat16* __restrict__ apk, int v, int e,
                                              float r0, float r1, float r2, float r3) {
    int chunk = v >> 4;
    int pos = (v & 15) * 4;
    size_t base = ((size_t)chunk * N_EDGES + e) * 64 + pos;
    *(__nv_bfloat162*)(apk + base)     = __halves2bfloat162(__float2bfloat16(r0), __float2bfloat16(r1));
    *(__nv_bfloat162*)(apk + base + 2) = __halves2bfloat162(__float2bfloat16(r2), __float2bfloat16(r3));
}

// ---------------- setup kernels ----------------
__global__ void k_zero_meta(int* deg_e, int* deg_n, int* cur_e, int* cur_n,
                            unsigned int* maxbits, float* sumexp, float* out) {
    int i = blockIdx.x * blockDim.x + threadIdx.x;
    int stride = gridDim.x * blockDim.x;
    for (int j = i; j < N_NODES; j += stride) {
        deg_n[j] = 0; cur_n[j] = 0;
        if (j < N_EDGES) { deg_e[j] = 0; cur_e[j] = 0; }
        if (j < 128) out[j] = 0.0f;
        if (j == 0) { *maxbits = 0u; *sumexp = 0.0f; }
    }
}

__global__ void k_count(const int* __restrict__ nidx, const int* __restrict__ eidx,
                        int* deg_n, int* deg_e) {
    int i = blockIdx.x * blockDim.x + threadIdx.x;
    if (i < NNZ) {
        atomicAdd(&deg_e[eidx[i]], 1);
        atomicAdd(&deg_n[nidx[i]], 1);
    }
}

__global__ void k_scan_local(const int* __restrict__ deg, int* __restrict__ off,
                             int* __restrict__ bsum, int n) {
    __shared__ int sh[1024];
    int i = blockIdx.x * 1024 + threadIdx.x;
    int v = (i < n) ? deg[i] : 0;
    sh[threadIdx.x] = v;
    __syncthreads();
    #pragma unroll
    for (int s = 1; s < 1024; s <<= 1) {
        int t = (threadIdx.x >= (unsigned)s) ? sh[threadIdx.x - s] : 0;
        __syncthreads();
        sh[threadIdx.x] += t;
        __syncthreads();
    }
    if (i < n) off[i] = sh[threadIdx.x] - v;
    if (threadIdx.x == 1023) bsum[blockIdx.x] = sh[1023];
}

__global__ void k_carry(int* bsum, int nb, int* tot) {
    if (threadIdx.x == 0) {
        int s = 0;
        for (int i = 0; i < nb; i++) { int v = bsum[i]; bsum[i] = s; s += v; }
        *tot = s;
    }
}

__global__ void k_scan_add(int* __restrict__ off, const int* __restrict__ bsum,
                           const int* __restrict__ deg, float* __restrict__ inv, int n) {
    int i = blockIdx.x * blockDim.x + threadIdx.x;
    if (i < n) {
        off[i] += bsum[i >> 10];
        int d = deg[i];
        inv[i] = (d > 0) ? (1.0f / (float)d) : 0.0f;
    }
}

__global__ void k_fill_e(const int* __restrict__ nidx, const int* __restrict__ eidx,
                         const int* __restrict__ off_e, int* cur_e, int* csr_e) {
    int i = blockIdx.x * blockDim.x + threadIdx.x;
    if (i < NNZ) {
        int e = eidx[i];
        int p = atomicAdd(&cur_e[e], 1);
        csr_e[off_e[e] + p] = nidx[i];
    }
}

__global__ void k_fill_n(const int* __restrict__ nidx, const int* __restrict__ eidx,
                         const int* __restrict__ off_n, int* cur_n, int* csr_n) {
    int i = blockIdx.x * blockDim.x + threadIdx.x;
    if (i < NNZ) {
        int n = nidx[i];
        int q = atomicAdd(&cur_n[n], 1);
        csr_n[off_n[n] + q] = eidx[i];
    }
}

// x [N_NODES,300] fp32 -> g_xh [N_NODES,320] fp16 (zero padded)
__global__ void k_cvtX(const float* __restrict__ x, __half* __restrict__ xh) {
    int m = blockIdx.x;
    int k = threadIdx.x;   // 320
    float v = (k < 300) ? x[(size_t)m * 300 + k] : 0.0f;
    xh[(size_t)m * 320 + k] = __float2half_rn(v);
}

// W [K][N] fp32 -> slice: hi at [chunk][n][k&63], lo at [chunk][256+n][k&63]
__global__ void k_packW(const float* __restrict__ W, int K, int N, __nv_bfloat16* __restrict__ wpk) {
    int n = blockIdx.x;
    int k = threadIdx.x;   // 320 threads
    float a = (k < K) ? W[(size_t)k * N + n] : 0.0f;
    __nv_bfloat16 h = __float2bfloat16(a);
    float r = a - __bfloat162float(h);
    int chunk = k >> 6;
    int kk = k & 63;
    wpk[((size_t)chunk * 512 + n) * 64 + kk] = h;
    wpk[((size_t)chunk * 512 + 256 + n) * 64 + kk] = __float2bfloat16(r);
}

// ---------------- edge gather (fp16 source) + fused bf16 hi pack ----------------
__global__ void k_edge_pack320(const __half* __restrict__ xh,
                               const int* __restrict__ off_e, const int* __restrict__ csr_e,
                               const float* __restrict__ binv, __nv_bfloat16* __restrict__ apk) {
    int w = (blockIdx.x * blockDim.x + threadIdx.x) >> 5;
    if (w >= N_EDGES) return;
    int lane = threadIdx.x & 31;
    float a[8] = {0, 0, 0, 0, 0, 0, 0, 0};
    float b[8] = {0, 0, 0, 0, 0, 0, 0, 0};
    bool hasB = lane < 8;
    int beg = off_e[w], end = off_e[w + 1];
    int m = beg;
    for (; m + 3 < end; m += 4) {
        int n0 = csr_e[m], n1 = csr_e[m + 1], n2 = csr_e[m + 2], n3 = csr_e[m + 3];
        const uint4* r0 = (const uint4*)(xh + (size_t)n0 * 320);
        const uint4* r1 = (const uint4*)(xh + (size_t)n1 * 320);
        const uint4* r2 = (const uint4*)(xh + (size_t)n2 * 320);
        const uint4* r3 = (const uint4*)(xh + (size_t)n3 * 320);
        addh8(a, r0[lane]); addh8(a, r1[lane]); addh8(a, r2[lane]); addh8(a, r3[lane]);
        if (hasB) {
            addh8(b, r0[lane + 32]); addh8(b, r1[lane + 32]);
            addh8(b, r2[lane + 32]); addh8(b, r3[lane + 32]);
        }
    }
    for (; m < end; m++) {
        const uint4* r0 = (const uint4*)(xh + (size_t)csr_e[m] * 320);
        addh8(a, r0[lane]);
        if (hasB) addh8(b, r0[lane + 32]);
    }
    float bi = binv[w];
    #pragma unroll
    for (int i = 0; i < 8; i++) { a[i] *= bi; b[i] *= bi; }
    pack_write_hi(apk, 2 * lane, w, a[0], a[1], a[2], a[3]);
    pack_write_hi(apk, 2 * lane + 1, w, a[4], a[5], a[6], a[7]);
    if (hasB) {
        pack_write_hi(apk, 64 + 2 * lane, w, b[0], b[1], b[2], b[3]);
        pack_write_hi(apk, 64 + 2 * lane + 1, w, b[4], b[5], b[6], b[7]);
    }
}

__global__ void k_edge_pack256(const __half* __restrict__ h,
                               const int* __restrict__ off_e, const int* __restrict__ csr_e,
                               const float* __restrict__ binv, __nv_bfloat16* __restrict__ apk) {
    int w = (blockIdx.x * blockDim.x + threadIdx.x) >> 5;
    if (w >= N_EDGES) return;
    int lane = threadIdx.x & 31;
    float a[8] = {0, 0, 0, 0, 0, 0, 0, 0};
    int beg = off_e[w], end = off_e[w + 1];
    int m = beg;
    for (; m + 3 < end; m += 4) {
        int n0 = csr_e[m], n1 = csr_e[m + 1], n2 = csr_e[m + 2], n3 = csr_e[m + 3];
        addh8(a, ((const uint4*)(h + (size_t)n0 * 256))[lane]);
        addh8(a, ((const uint4*)(h + (size_t)n1 * 256))[lane]);
        addh8(a, ((const uint4*)(h + (size_t)n2 * 256))[lane]);
        addh8(a, ((const uint4*)(h + (size_t)n3 * 256))[lane]);
    }
    for (; m < end; m++)
        addh8(a, ((const uint4*)(h + (size_t)csr_e[m] * 256))[lane]);
    float bi = binv[w];
    #pragma unroll
    for (int i = 0; i < 8; i++) a[i] *= bi;
    pack_write_hi(apk, 2 * lane, w, a[0], a[1], a[2], a[3]);
    pack_write_hi(apk, 2 * lane + 1, w, a[4], a[5], a[6], a[7]);
}

// ---------------- TMA + mma.sync GEMM: A bf16, W = Whi + Wlo; fp16 out ----------------
#define STAGE_B 49152
#define N_STAGE 4
#define MB_OFF  (N_STAGE * STAGE_B)
#define SMEM_GEMM (MB_OFF + 64)

__global__ __launch_bounds__(256, 1) void k_mma_gemm(
    const __grid_constant__ CUtensorMap tmA,
    const __grid_constant__ CUtensorMap tmB,
    __half* __restrict__ C, int M, int Ncols, int chunks) {
    extern __shared__ char smem[];
    uint32_t sb = smem_u32(smem);
    int tid = threadIdx.x;
    int lane = tid & 31;
    int wid = tid >> 5;
    int wm = wid >> 2;
    int wn = wid & 3;
    int mBase = blockIdx.y * 128;
    int nBase = blockIdx.x * 128;

    if (tid == 0) {
        #pragma unroll
        for (int s = 0; s < N_STAGE; s++) MBAR_INIT(sb + MB_OFF + s * 8, 1);
    }
    __syncthreads();
    if (tid == 0) {
        #pragma unroll
        for (int s = 0; s < N_STAGE; s++) {
            if (s < chunks) {
                MBAR_EXPECT_TX(sb + MB_OFF + s * 8, STAGE_B);
                tma3d(sb + s * STAGE_B, &tmA, 0, mBase, s, sb + MB_OFF + s * 8);
                tma3d(sb + s * STAGE_B + 16384, &tmB, 0, nBase, s, sb + MB_OFF + s * 8);
                tma3d(sb + s * STAGE_B + 32768, &tmB, 0, nBase + 256, s, sb + MB_OFF + s * 8);
            }
        }
    }

    int a_row = lane & 15;
    int a_byte = (lane >> 4) << 4;
    int b_row = ((lane & 16) >> 1) + (lane & 7);
    int b_byte = (lane & 8) * 2;

    float acc[4][4][4];
    #pragma unroll
    for (int i = 0; i < 4; i++)
        #pragma unroll
        for (int j = 0; j < 4; j++)
            #pragma unroll
            for (int q = 0; q < 4; q++) acc[i][j][q] = 0.0f;

    for (int c = 0; c < chunks; c++) {
        int st = c & (N_STAGE - 1);
        MBAR_WAIT(sb + MB_OFF + st * 8, (c >> 2) & 1);
        uint32_t sA = sb + st * STAGE_B;
        uint32_t sBh = sA + 16384;
        uint32_t sBl = sA + 32768;
        #pragma unroll
        for (int ks = 0; ks < 4; ks++) {
            int kb = ks * 32;
            uint32_t ah[4][4], bh[2][4], bl[2][4];
            #pragma unroll
            for (int i = 0; i < 4; i++) {
                int r = wm * 64 + i * 16 + a_row;
                ldsm4(ah[i], swz(sA, r, kb + a_byte));
            }
            #pragma unroll
            for (int jj = 0; jj < 2; jj++) {
                int r = wn * 32 + jj * 16 + b_row;
                ldsm4(bh[jj], swz(sBh, r, kb + b_byte));
                ldsm4(bl[jj], swz(sBl, r, kb + b_byte));
            }
            #pragma unroll
            for (int i = 0; i < 4; i++)
                #pragma unroll
                for (int j = 0; j < 4; j++) {
                    const uint32_t* bH = &bh[j >> 1][(j & 1) * 2];
                    const uint32_t* bL = &bl[j >> 1][(j & 1) * 2];
                    mma16816(acc[i][j], ah[i], bH);
                    mma16816(acc[i][j], ah[i], bL);
                }
        }
        __syncthreads();
        if (tid == 0 && c + N_STAGE < chunks) {
            MBAR_EXPECT_TX(sb + MB_OFF + st * 8, STAGE_B);
            tma3d(sb + st * STAGE_B, &tmA, 0, mBase, c + N_STAGE, sb + MB_OFF + st * 8);
            tma3d(sb + st * STAGE_B + 16384, &tmB, 0, nBase, c + N_STAGE, sb + MB_OFF + st * 8);
            tma3d(sb + st * STAGE_B + 32768, &tmB, 0, nBase + 256, c + N_STAGE, sb + MB_OFF + st * 8);
        }
    }

    #pragma unroll
    for (int i = 0; i < 4; i++) {
        int r0 = mBase + wm * 64 + i * 16 + (lane >> 2);
        #pragma unroll
        for (int j = 0; j < 4; j++) {
            int cc = nBase + wn * 32 + j * 8 + (lane & 3) * 2;
            if (r0 < M)
                *(__half2*)&C[(size_t)r0 * Ncols + cc] =
                    __floats2half2_rn(acc[i][j][0], acc[i][j][1]);
            if (r0 + 8 < M)
                *(__half2*)&C[(size_t)(r0 + 8) * Ncols + cc] =
                    __floats2half2_rn(acc[i][j][2], acc[i][j][3]);
        }
    }
}

// ---------------- node gather (fp16 edge GEMM output) -> fp16 h ----------------
__global__ void k_node_agg256(const __half* __restrict__ xwE,
                              const int* __restrict__ off_n, const int* __restrict__ csr_n,
                              const float* __restrict__ dinv, const float* __restrict__ bias,
                              __half* __restrict__ dst) {
    int w = (blockIdx.x * blockDim.x + threadIdx.x) >> 5;
    if (w >= N_NODES) return;
    int lane = threadIdx.x & 31;
    float a[8] = {0, 0, 0, 0, 0, 0, 0, 0};
    int beg = off_n[w], end = off_n[w + 1];
    int m = beg;
    for (; m + 3 < end; m += 4) {
        int e0 = csr_n[m], e1 = csr_n[m + 1], e2 = csr_n[m + 2], e3 = csr_n[m + 3];
        addh8(a, ((const uint4*)(xwE + (size_t)e0 * 256))[lane]);
        addh8(a, ((const uint4*)(xwE + (size_t)e1 * 256))[lane]);
        addh8(a, ((const uint4*)(xwE + (size_t)e2 * 256))[lane]);
        addh8(a, ((const uint4*)(xwE + (size_t)e3 * 256))[lane]);
    }
    for (; m < end; m++)
        addh8(a, ((const uint4*)(xwE + (size_t)csr_n[m] * 256))[lane]);
    float di = dinv[w];
    float4 b0 = ((const float4*)bias)[2 * lane];
    float4 b1 = ((const float4*)bias)[2 * lane + 1];
    float r[8];
    r[0] = a[0] * di + b0.x; r[1] = a[1] * di + b0.y;
    r[2] = a[2] * di + b0.z; r[3] = a[3] * di + b0.w;
    r[4] = a[4] * di + b1.x; r[5] = a[5] * di + b1.y;
    r[6] = a[6] * di + b1.z; r[7] = a[7] * di + b1.w;
    #pragma unroll
    for (int i = 0; i < 8; i++) r[i] = r[i] > 0.f ? r[i] : 0.01f * r[i];
    __half2 o[4];
    #pragma unroll
    for (int i = 0; i < 4; i++) o[i] = __floats2half2_rn(r[2 * i], r[2 * i + 1]);
    ((uint4*)(dst + (size_t)w * 256))[lane] = *(const uint4*)o;
}

// ---------------- final-layer algebraic tail ----------------
__global__ void k_cdot(const float* __restrict__ b3, const float* __restrict__ aw,
                       const float* __restrict__ ab, float* __restrict__ cdot) {
    int f = threadIdx.x;   // 128
    float v = b3[f] * aw[f];
    #pragma unroll
    for (int o = 16; o; o >>= 1) v += __shfl_xor_sync(0xffffffffu, v, o);
    __shared__ float sm[4];
    if ((f & 31) == 0) sm[f >> 5] = v;
    __syncthreads();
    if (f == 0) *cdot = sm[0] + sm[1] + sm[2] + sm[3] + ab[0];
}

__global__ void k_edge_dot(const __half* __restrict__ xwE, const float* __restrict__ aw,
                           float* __restrict__ t) {
    int e = (blockIdx.x * blockDim.x + threadIdx.x) >> 5;
    if (e >= N_EDGES) return;
    int lane = threadIdx.x & 31;
    uint2 v = ((const uint2*)(xwE + (size_t)e * 128))[lane];
    const __half2* h = (const __half2*)&v;
    float2 f0 = __half22float2(h[0]);
    float2 f1 = __half22float2(h[1]);
    float4 wv = ((const float4*)aw)[lane];
    float d = f0.x * wv.x + f0.y * wv.y + f1.x * wv.z + f1.y * wv.w;
    #pragma unroll
    for (int o = 16; o; o >>= 1) d += __shfl_xor_sync(0xffffffffu, d, o);
    if (lane == 0) t[e] = d;
}

__global__ void k_logits_node(const float* __restrict__ t,
                              const int* __restrict__ off_n, const int* __restrict__ csr_n,
                              const float* __restrict__ dinv, const float* __restrict__ cdot,
                              float* __restrict__ logits, unsigned int* maxbits) {
    int n = blockIdx.x * blockDim.x + threadIdx.x;
    float lg = -3.4e38f;
    if (n < N_NODES) {
        float s = 0.f;
        int beg = off_n[n], end = off_n[n + 1];
        for (int m = beg; m < end; m++) s += t[csr_n[m]];
        lg = dinv[n] * s + *cdot;
        logits[n] = lg;
    }
    #pragma unroll
    for (int o = 16; o; o >>= 1) lg = fmaxf(lg, __shfl_xor_sync(0xffffffffu, lg, o));
    __shared__ float sm[8];
    if ((threadIdx.x & 31) == 0) sm[threadIdx.x >> 5] = lg;
    __syncthreads();
    if (threadIdx.x < 8) {
        float mv = sm[threadIdx.x];
        #pragma unroll
        for (int o = 4; o; o >>= 1) mv = fmaxf(mv, __shfl_xor_sync(0xffu, mv, o));
        if (threadIdx.x == 0) atomicMax(maxbits, enc_f(mv));
    }
}

// fused: sumexp accumulation + c_n = exp(logit-mx)*dinv_n
__global__ void k_sumexp_coef(const float* __restrict__ logits,
                              const unsigned int* __restrict__ maxbits,
                              const float* __restrict__ dinv,
                              float* __restrict__ c, float* sumexp) {
    float mx = dec_f(*maxbits);
    int i = blockIdx.x * blockDim.x + threadIdx.x;
    int stride = gridDim.x * blockDim.x;
    float s = 0.f;
    for (int j = i; j < N_NODES; j += stride) {
        float ev = expf(logits[j] - mx);
        c[j] = ev * dinv[j];
        s += ev;
    }
    #pragma unroll
    for (int o = 16; o; o >>= 1) s += __shfl_xor_sync(0xffffffffu, s, o);
    __shared__ float sm[8];
    if ((threadIdx.x & 31) == 0) sm[threadIdx.x >> 5] = s;
    __syncthreads();
    if (threadIdx.x < 8) {
        float tt = sm[threadIdx.x];
        #pragma unroll
        for (int o = 4; o; o >>= 1) tt += __shfl_xor_sync(0xffu, tt, o);
        if (threadIdx.x == 0) atomicAdd(sumexp, tt);
    }
}

__global__ void k_edge_coef(const float* __restrict__ c,
                            const int* __restrict__ off_e, const int* __restrict__ csr_e,
                            float* __restrict__ s) {
    int e = (blockIdx.x * blockDim.x + threadIdx.x) >> 5;
    if (e >= N_EDGES) return;
    int lane = threadIdx.x & 31;
    float acc = 0.f;
    int beg = off_e[e], end = off_e[e + 1];
    for (int m = beg + lane; m < end; m += 32) acc += c[csr_e[m]];
    #pragma unroll
    for (int o = 16; o; o >>= 1) acc += __shfl_xor_sync(0xffffffffu, acc, o);
    if (lane == 0) s[e] = acc;
}

__global__ void k_final_sum(const __half* __restrict__ xwE, const float* __restrict__ s,
                            float* __restrict__ out) {
    int f = threadIdx.x;   // 128
    int e0 = blockIdx.x * 128;
    int e1 = min(e0 + 128, N_EDGES);
    float acc = 0.f;
    for (int e = e0; e < e1; e++)
        acc += s[e] * __half2float(xwE[(size_t)e * 128 + f]);
    atomicAdd(&out[f], acc);
}

__global__ void k_finalize(float* __restrict__ out, const float* __restrict__ sumexp,
                           const float* __restrict__ b3) {
    int f = threadIdx.x;
    out[f] = out[f] / (*sumexp) + b3[f];
}

// ---------------- host-side tensormap plumbing ----------------
typedef CUresult (*PFN_encodeTmap)(
    CUtensorMap*, CUtensorMapDataType, unsigned int, void*,
    const unsigned long long*, const unsigned long long*,
    const unsigned int*, const unsigned int*,
    CUtensorMapInterleave, CUtensorMapSwizzle, CUtensorMapL2promotion, CUtensorMapFloatOOBfill);

// ---------------- launch ----------------
extern "C" void kernel_launch(void* const* d_in, const int* in_sizes, int n_in,
                              void* d_out, int out_size) {
    const float* x   = (const float*)d_in[0];
    const int*   hei = (const int*)d_in[1];
    const int*   nidx = hei;
    const int*   eidx = hei + NNZ;
    const float* W1 = (const float*)d_in[2];
    const float* b1 = (const float*)d_in[3];
    const float* W2 = (const float*)d_in[4];
    const float* b2 = (const float*)d_in[5];
    const float* W3 = (const float*)d_in[6];
    const float* b3 = (const float*)d_in[7];
    const float* aw = (const float*)d_in[8];
    const float* ab = (const float*)d_in[9];
    float* out = (float*)d_out;

    static __half *p_xh = nullptr, *p_xwE, *p_h16, *p_h16b;
    static float *p_t, *p_s, *p_c, *p_cdot;
    static float *p_binv, *p_dinv, *p_logits, *p_sumexp;
    static int *p_deg_e, *p_deg_n, *p_off_e, *p_off_n, *p_cur_e, *p_cur_n, *p_csr_e, *p_csr_n;
    static int *p_bsum_e, *p_bsum_n;
    static unsigned int* p_maxbits;
    static __nv_bfloat16 *p_Apk, *p_Wpk;
    static CUtensorMap tmA, tmB1, tmB2, tmB3;
    static cudaStream_t s1;
    static cudaEvent_t evFork, evCnt, evPrep, evN;
    if (!p_xh) {
        cudaGetSymbolAddress((void**)&p_xh, g_xh);
        cudaGetSymbolAddress((void**)&p_xwE, g_xwE);
        cudaGetSymbolAddress((void**)&p_h16, g_h16);
        cudaGetSymbolAddress((void**)&p_h16b, g_h16b);
        cudaGetSymbolAddress((void**)&p_t, g_t);
        cudaGetSymbolAddress((void**)&p_s, g_s);
        cudaGetSymbolAddress((void**)&p_c, g_c);
        cudaGetSymbolAddress((void**)&p_cdot, g_cdot);
        cudaGetSymbolAddress((void**)&p_binv, g_binv);
        cudaGetSymbolAddress((void**)&p_dinv, g_dinv);
        cudaGetSymbolAddress((void**)&p_logits, g_logits);
        cudaGetSymbolAddress((void**)&p_sumexp, g_sumexp);
        cudaGetSymbolAddress((void**)&p_deg_e, g_deg_e);
        cudaGetSymbolAddress((void**)&p_deg_n, g_deg_n);
        cudaGetSymbolAddress((void**)&p_off_e, g_off_e);
        cudaGetSymbolAddress((void**)&p_off_n, g_off_n);
        cudaGetSymbolAddress((void**)&p_cur_e, g_cur_e);
        cudaGetSymbolAddress((void**)&p_cur_n, g_cur_n);
        cudaGetSymbolAddress((void**)&p_csr_e, g_csr_e);
        cudaGetSymbolAddress((void**)&p_csr_n, g_csr_n);
        cudaGetSymbolAddress((void**)&p_bsum_e, g_bsum_e);
        cudaGetSymbolAddress((void**)&p_bsum_n, g_bsum_n);
        cudaGetSymbolAddress((void**)&p_maxbits, g_maxbits);
        cudaGetSymbolAddress((void**)&p_Apk, g_Apk);
        cudaGetSymbolAddress((void**)&p_Wpk, g_Wpk);
        cudaFuncSetAttribute(k_mma_gemm, cudaFuncAttributeMaxDynamicSharedMemorySize, SMEM_GEMM);
        cudaStreamCreateWithFlags(&s1, cudaStreamNonBlocking);
        cudaEventCreateWithFlags(&evFork, cudaEventDisableTiming);
        cudaEventCreateWithFlags(&evCnt, cudaEventDisableTiming);
        cudaEventCreateWithFlags(&evPrep, cudaEventDisableTiming);
        cudaEventCreateWithFlags(&evN, cudaEventDisableTiming);

        void* fp = nullptr;
        cudaDriverEntryPointQueryResult qr;
        cudaGetDriverEntryPoint("cuTensorMapEncodeTiled", &fp, cudaEnableDefault, &qr);
        PFN_encodeTmap enc = (PFN_encodeTmap)fp;
        unsigned long long dimsA[3] = {128ull, (unsigned long long)N_EDGES, (unsigned long long)NCHUNK};
        unsigned long long strA[2]  = {128ull, 128ull * N_EDGES};
        unsigned long long dimsB[3] = {128ull, 512ull, (unsigned long long)NCHUNK};
        unsigned long long strB[2]  = {128ull, 128ull * 512ull};
        unsigned int box[3] = {128u, 128u, 1u};
        unsigned int est[3] = {1u, 1u, 1u};
        enc(&tmA, CU_TENSOR_MAP_DATA_TYPE_UINT8, 3, (void*)p_Apk, dimsA, strA, box, est,
            CU_TENSOR_MAP_INTERLEAVE_NONE, CU_TENSOR_MAP_SWIZZLE_128B,
            CU_TENSOR_MAP_L2_PROMOTION_L2_128B, CU_TENSOR_MAP_FLOAT_OOB_FILL_NONE);
        enc(&tmB1, CU_TENSOR_MAP_DATA_TYPE_UINT8, 3, (void*)(p_Wpk), dimsB, strB, box, est,
            CU_TENSOR_MAP_INTERLEAVE_NONE, CU_TENSOR_MAP_SWIZZLE_128B,
            CU_TENSOR_MAP_L2_PROMOTION_L2_128B, CU_TENSOR_MAP_FLOAT_OOB_FILL_NONE);
        enc(&tmB2, CU_TENSOR_MAP_DATA_TYPE_UINT8, 3, (void*)(p_Wpk + WPK_SLICE), dimsB, strB, box, est,
            CU_TENSOR_MAP_INTERLEAVE_NONE, CU_TENSOR_MAP_SWIZZLE_128B,
            CU_TENSOR_MAP_L2_PROMOTION_L2_128B, CU_TENSOR_MAP_FLOAT_OOB_FILL_NONE);
        enc(&tmB3, CU_TENSOR_MAP_DATA_TYPE_UINT8, 3, (void*)(p_Wpk + 2 * WPK_SLICE), dimsB, strB, box, est,
            CU_TENSOR_MAP_INTERLEAVE_NONE, CU_TENSOR_MAP_SWIZZLE_128B,
            CU_TENSOR_MAP_L2_PROMOTION_L2_128B, CU_TENSOR_MAP_FLOAT_OOB_FILL_NONE);
    }

    // ---- fork: conversions on s1; CSR edge-side on stream 0 ----
    cudaEventRecord(evFork, 0);
    cudaStreamWaitEvent(s1, evFork, 0);
    k_cvtX<<<N_NODES, 320, 0, s1>>>(x, p_xh);
    k_packW<<<256, 320, 0, s1>>>(W1, 300, 256, p_Wpk);
    k_packW<<<256, 320, 0, s1>>>(W2, 256, 256, p_Wpk + WPK_SLICE);
    k_packW<<<128, 320, 0, s1>>>(W3, 256, 128, p_Wpk + 2 * WPK_SLICE);
    k_cdot<<<1, 128, 0, s1>>>(b3, aw, ab, p_cdot);
    cudaEventRecord(evPrep, s1);

    k_zero_meta<<<400, 256>>>(p_deg_e, p_deg_n, p_cur_e, p_cur_n, p_maxbits, p_sumexp, out);
    k_count<<<(NNZ + 255) / 256, 256>>>(nidx, eidx, p_deg_n, p_deg_e);
    cudaEventRecord(evCnt, 0);

    const int NBE = (N_EDGES + 1023) / 1024;
    const int NBN = (N_NODES + 1023) / 1024;
    // edge-side CSR on stream 0 (needed first)
    k_scan_local<<<NBE, 1024>>>(p_deg_e, p_off_e, p_bsum_e, N_EDGES);
    k_carry<<<1, 32>>>(p_bsum_e, NBE, p_off_e + N_EDGES);
    k_scan_add<<<(N_EDGES + 255) / 256, 256>>>(p_off_e, p_bsum_e, p_deg_e, p_binv, N_EDGES);
    k_fill_e<<<(NNZ + 255) / 256, 256>>>(nidx, eidx, p_off_e, p_cur_e, p_csr_e);

    // node-side CSR on s1, overlapping edge gather + GEMM1
    cudaStreamWaitEvent(s1, evCnt, 0);
    k_scan_local<<<NBN, 1024, 0, s1>>>(p_deg_n, p_off_n, p_bsum_n, N_NODES);
    k_carry<<<1, 32, 0, s1>>>(p_bsum_n, NBN, p_off_n + N_NODES);
    k_scan_add<<<(N_NODES + 255) / 256, 256, 0, s1>>>(p_off_n, p_bsum_n, p_deg_n, p_dinv, N_NODES);
    k_fill_n<<<(NNZ + 255) / 256, 256, 0, s1>>>(nidx, eidx, p_off_n, p_cur_n, p_csr_n);
    cudaEventRecord(evN, s1);

    cudaStreamWaitEvent(0, evPrep, 0);

    const int EB = (N_EDGES * 32) / 256;    // 2500
    const int NB = (N_NODES * 32) / 256;    // 12500
    const int GM = (N_EDGES + 127) / 128;   // 157

    // ---- layer 1 ----
    k_edge_pack320<<<EB, 256>>>(p_xh, p_off_e, p_csr_e, p_binv, p_Apk);
    k_mma_gemm<<<dim3(2, GM), 256, SMEM_GEMM>>>(tmA, tmB1, p_xwE, N_EDGES, 256, 5);
    cudaStreamWaitEvent(0, evN, 0);
    k_node_agg256<<<NB, 256>>>(p_xwE, p_off_n, p_csr_n, p_dinv, b1, p_h16);

    // ---- layer 2 ----
    k_edge_pack256<<<EB, 256>>>(p_h16, p_off_e, p_csr_e, p_binv, p_Apk);
    k_mma_gemm<<<dim3(2, GM), 256, SMEM_GEMM>>>(tmA, tmB2, p_xwE, N_EDGES, 256, 4);
    k_node_agg256<<<NB, 256>>>(p_xwE, p_off_n, p_csr_n, p_dinv, b2, p_h16b);

    // ---- layer 3: edge GEMM then algebraic pooling tail ----
    k_edge_pack256<<<EB, 256>>>(p_h16b, p_off_e, p_csr_e, p_binv, p_Apk);
    k_mma_gemm<<<dim3(1, GM), 256, SMEM_GEMM>>>(tmA, tmB3, p_xwE, N_EDGES, 128, 4);
    k_edge_dot<<<EB, 256>>>(p_xwE, aw, p_t);
    k_logits_node<<<(N_NODES + 255) / 256, 256>>>(p_t, p_off_n, p_csr_n, p_dinv, p_cdot,
                                                  p_logits, p_maxbits);
    k_sumexp_coef<<<512, 256>>>(p_logits, p_maxbits, p_dinv, p_c, p_sumexp);
    k_edge_coef<<<EB, 256>>>(p_c, p_off_e, p_csr_e, p_s);
    k_final_sum<<<GM, 128>>>(p_xwE, p_s, out);
    k_finalize<<<1, 128>>>(out, p_sumexp, b3);
}